// round 1
// baseline (speedup 1.0000x reference)
#include <cuda_runtime.h>
#include <math.h>
#include <float.h>

// ---------------- problem constants ----------------
constexpr int NB  = 4;
constexpr int NS  = 1024;
constexpr int ND  = 1024;
constexpr int NH  = 16;
constexpr int NHD = 64;
constexpr int NE  = 8;
constexpr int NF  = 4096;
constexpr int NT  = NB * NS;            // 4096 tokens
constexpr float EPS = 1e-5f;

// ---------------- scratch (device globals; no runtime alloc) ----------------
__device__ float g_qkv[(size_t)NT * 3 * ND];        // 50 MB
__device__ float g_attno[(size_t)NT * ND];          // 16 MB
__device__ float g_tmp[(size_t)NT * ND];            // 16 MB
__device__ float g_x1[(size_t)NT * ND];             // 16 MB
__device__ float g_h[(size_t)(NT + 128) * NF];      // 68 MB (oversized for tile-tail reads)
__device__ int   g_idx[NT];
__device__ int   g_order[NT];
__device__ int   g_cnt[NE];
__device__ int   g_off[NE + 1];
__device__ int   g_pos[NE];

// ---------------- SGEMM: C[M,N] = A[M,K] * B[N,K]^T + bias[N] ----------------
// BM=BN=128, BK=16, 256 threads, 8x8 register tile. M,N,K multiples of tile dims.
__global__ __launch_bounds__(256) void sgemm_abt(
    const float* __restrict__ A, const float* __restrict__ Bm,
    const float* __restrict__ bias, float* __restrict__ C,
    int M, int N, int K)
{
    __shared__ float As[16][128];
    __shared__ float Bs[16][128];
    const int tid = threadIdx.x;
    const int m0 = blockIdx.y * 128;
    const int n0 = blockIdx.x * 128;
    const int tx = tid & 15;
    const int ty = tid >> 4;

    float acc[8][8];
#pragma unroll
    for (int i = 0; i < 8; ++i)
#pragma unroll
        for (int j = 0; j < 8; ++j) acc[i][j] = 0.f;

    for (int k0 = 0; k0 < K; k0 += 16) {
#pragma unroll
        for (int it = 0; it < 2; ++it) {
            int v = tid + it * 256;          // 0..511
            int row = v >> 2;                // 0..127
            int kq  = (v & 3) * 4;           // 0,4,8,12
            float4 t4 = *reinterpret_cast<const float4*>(A + (size_t)(m0 + row) * K + k0 + kq);
            As[kq + 0][row] = t4.x; As[kq + 1][row] = t4.y;
            As[kq + 2][row] = t4.z; As[kq + 3][row] = t4.w;
        }
#pragma unroll
        for (int it = 0; it < 2; ++it) {
            int v = tid + it * 256;
            int row = v >> 2;
            int kq  = (v & 3) * 4;
            float4 t4 = *reinterpret_cast<const float4*>(Bm + (size_t)(n0 + row) * K + k0 + kq);
            Bs[kq + 0][row] = t4.x; Bs[kq + 1][row] = t4.y;
            Bs[kq + 2][row] = t4.z; Bs[kq + 3][row] = t4.w;
        }
        __syncthreads();
#pragma unroll
        for (int kk = 0; kk < 16; ++kk) {
            float4 a0 = *reinterpret_cast<const float4*>(&As[kk][ty * 8]);
            float4 a1 = *reinterpret_cast<const float4*>(&As[kk][ty * 8 + 4]);
            float4 b0 = *reinterpret_cast<const float4*>(&Bs[kk][tx * 8]);
            float4 b1 = *reinterpret_cast<const float4*>(&Bs[kk][tx * 8 + 4]);
            float a[8] = {a0.x, a0.y, a0.z, a0.w, a1.x, a1.y, a1.z, a1.w};
            float b[8] = {b0.x, b0.y, b0.z, b0.w, b1.x, b1.y, b1.z, b1.w};
#pragma unroll
            for (int i = 0; i < 8; ++i)
#pragma unroll
                for (int j = 0; j < 8; ++j) acc[i][j] = fmaf(a[i], b[j], acc[i][j]);
        }
        __syncthreads();
    }

#pragma unroll
    for (int i = 0; i < 8; ++i) {
        float* cp = C + (size_t)(m0 + ty * 8 + i) * N + n0 + tx * 8;
#pragma unroll
        for (int j = 0; j < 8; ++j) cp[j] = acc[i][j] + bias[n0 + tx * 8 + j];
    }
}

// ---------------- flash attention (fp32, Br=Bc=64, HD=64) ----------------
// grid: (NS/64, NB*NH), block: 64 threads; thread = one query row.
__global__ __launch_bounds__(64) void flash_attn(
    const float* __restrict__ qkv, float* __restrict__ O)
{
    const int bh = blockIdx.y;
    const int b  = bh >> 4;
    const int h  = bh & 15;
    const int q  = blockIdx.x * 64 + threadIdx.x;
    const int tx = threadIdx.x;

    __shared__ float Ks[64][68];
    __shared__ float Vs[64][68];

    const size_t str = 3 * ND;
    const float* qp = qkv + ((size_t)(b * NS) + q) * str + h * NHD;

    float qr[64];
#pragma unroll
    for (int d = 0; d < 64; d += 4) {
        float4 t = *reinterpret_cast<const float4*>(qp + d);
        qr[d] = t.x; qr[d + 1] = t.y; qr[d + 2] = t.z; qr[d + 3] = t.w;
    }
    float o[64];
#pragma unroll
    for (int d = 0; d < 64; ++d) o[d] = 0.f;
    float m = -1e30f, l = 0.f;
    const float scale = 0.125f;   // 1/sqrt(64)

    for (int kt = 0; kt < NS; kt += 64) {
        const float* kp = qkv + ((size_t)(b * NS) + kt + tx) * str + ND + h * NHD;
        const float* vp = kp + ND;
#pragma unroll
        for (int d = 0; d < 64; d += 4) {
            float4 kk = *reinterpret_cast<const float4*>(kp + d);
            float4 vv = *reinterpret_cast<const float4*>(vp + d);
            *reinterpret_cast<float4*>(&Ks[tx][d]) = kk;
            *reinterpret_cast<float4*>(&Vs[tx][d]) = vv;
        }
        __syncthreads();

        float s[64];
        float mn = m;
#pragma unroll 2
        for (int j = 0; j < 64; ++j) {
            float sum = 0.f;
#pragma unroll
            for (int d = 0; d < 64; d += 4) {
                float4 kv = *reinterpret_cast<const float4*>(&Ks[j][d]);
                sum = fmaf(qr[d], kv.x, sum);
                sum = fmaf(qr[d + 1], kv.y, sum);
                sum = fmaf(qr[d + 2], kv.z, sum);
                sum = fmaf(qr[d + 3], kv.w, sum);
            }
            sum *= scale;
            s[j] = sum;
            mn = fmaxf(mn, sum);
        }
        float corr = __expf(m - mn);
        m = mn;
        l *= corr;
#pragma unroll
        for (int d = 0; d < 64; ++d) o[d] *= corr;
#pragma unroll 2
        for (int j = 0; j < 64; ++j) {
            float p = __expf(s[j] - m);
            l += p;
#pragma unroll
            for (int d = 0; d < 64; d += 4) {
                float4 vv = *reinterpret_cast<const float4*>(&Vs[j][d]);
                o[d]     = fmaf(p, vv.x, o[d]);
                o[d + 1] = fmaf(p, vv.y, o[d + 1]);
                o[d + 2] = fmaf(p, vv.z, o[d + 2]);
                o[d + 3] = fmaf(p, vv.w, o[d + 3]);
            }
        }
        __syncthreads();
    }

    const float inv = 1.f / l;
    float* op = O + ((size_t)(b * NS) + q) * ND + h * NHD;
#pragma unroll
    for (int d = 0; d < 64; d += 4) {
        float4 t;
        t.x = o[d] * inv; t.y = o[d + 1] * inv; t.z = o[d + 2] * inv; t.w = o[d + 3] * inv;
        *reinterpret_cast<float4*>(op + d) = t;
    }
}

// ---------------- residual add + LayerNorm ----------------
// out[t,:] = LN(A[t,:] + R[t,:]) ; one block (256 thr) per token, D=1024.
__global__ __launch_bounds__(256) void add_ln(
    const float* __restrict__ A, const float* __restrict__ R,
    const float* __restrict__ g, const float* __restrict__ bt,
    float* __restrict__ out)
{
    const int t = blockIdx.x;
    const int tid = threadIdx.x;
    __shared__ float red[8];

    const float4 a4 = *reinterpret_cast<const float4*>(A + (size_t)t * ND + tid * 4);
    const float4 r4 = *reinterpret_cast<const float4*>(R + (size_t)t * ND + tid * 4);
    float v[4] = {a4.x + r4.x, a4.y + r4.y, a4.z + r4.z, a4.w + r4.w};

    float sum = v[0] + v[1] + v[2] + v[3];
#pragma unroll
    for (int off = 16; off; off >>= 1) sum += __shfl_down_sync(0xffffffffu, sum, off);
    if ((tid & 31) == 0) red[tid >> 5] = sum;
    __syncthreads();
    if (tid < 8) {
        float s = red[tid];
#pragma unroll
        for (int off = 4; off; off >>= 1) s += __shfl_down_sync(0xffu, s, off);
        if (tid == 0) red[0] = s;
    }
    __syncthreads();
    const float mu = red[0] * (1.f / ND);
    __syncthreads();

    float vs = 0.f;
#pragma unroll
    for (int i = 0; i < 4; ++i) { float d = v[i] - mu; vs += d * d; }
#pragma unroll
    for (int off = 16; off; off >>= 1) vs += __shfl_down_sync(0xffffffffu, vs, off);
    if ((tid & 31) == 0) red[tid >> 5] = vs;
    __syncthreads();
    if (tid < 8) {
        float s = red[tid];
#pragma unroll
        for (int off = 4; off; off >>= 1) s += __shfl_down_sync(0xffu, s, off);
        if (tid == 0) red[0] = s;
    }
    __syncthreads();
    const float rstd = rsqrtf(red[0] * (1.f / ND) + EPS);

    float4 o4;
    const int d0 = tid * 4;
    o4.x = (v[0] - mu) * rstd * g[d0]     + bt[d0];
    o4.y = (v[1] - mu) * rstd * g[d0 + 1] + bt[d0 + 1];
    o4.z = (v[2] - mu) * rstd * g[d0 + 2] + bt[d0 + 2];
    o4.w = (v[3] - mu) * rstd * g[d0 + 3] + bt[d0 + 3];
    *reinterpret_cast<float4*>(out + (size_t)t * ND + d0) = o4;
}

// ---------------- routing ----------------
__global__ void route_init() {
    if (threadIdx.x < NE) g_cnt[threadIdx.x] = 0;
}

// one warp per token; E=8 dot products over D=1024
__global__ __launch_bounds__(256) void gate_kernel(
    const float* __restrict__ X, const float* __restrict__ gw,
    const float* __restrict__ gb)
{
    const int warp = threadIdx.x >> 5;
    const int lane = threadIdx.x & 31;
    const int t = blockIdx.x * 8 + warp;
    const float* xp = X + (size_t)t * ND;
    float acc[NE];
#pragma unroll
    for (int e = 0; e < NE; ++e) acc[e] = 0.f;
    for (int d = lane; d < ND; d += 32) {
        const float xv = xp[d];
#pragma unroll
        for (int e = 0; e < NE; ++e) acc[e] = fmaf(xv, gw[e * ND + d], acc[e]);
    }
#pragma unroll
    for (int e = 0; e < NE; ++e)
#pragma unroll
        for (int off = 16; off; off >>= 1)
            acc[e] += __shfl_down_sync(0xffffffffu, acc[e], off);
    if (lane == 0) {
        int best = 0; float bv = acc[0] + gb[0];
#pragma unroll
        for (int e = 1; e < NE; ++e) {
            float v = acc[e] + gb[e];
            if (v > bv) { bv = v; best = e; }
        }
        g_idx[t] = best;
        atomicAdd(&g_cnt[best], 1);
    }
}

__global__ void route_scan() {
    g_off[0] = 0;
    for (int e = 0; e < NE; ++e) {
        g_off[e + 1] = g_off[e] + g_cnt[e];
        g_pos[e] = g_off[e];
    }
}

__global__ __launch_bounds__(256) void route_scatter() {
    const int t = blockIdx.x * 256 + threadIdx.x;
    if (t < NT) {
        const int e = g_idx[t];
        const int p = atomicAdd(&g_pos[e], 1);
        g_order[p] = t;
    }
}

// ---------------- MoE grouped GEMM 1: h[p,f] = relu(x1[tok(p),:] @ W1[e] + b1[e]) ----
// grid: (NF/128, NT/128, NE), block 256
__global__ __launch_bounds__(256) void moe_gemm1(
    const float* __restrict__ X, const float* __restrict__ W1,
    const float* __restrict__ b1)
{
    const int e = blockIdx.z;
    const int seg0 = g_off[e], seg1 = g_off[e + 1];
    const int m0 = blockIdx.y * 128;
    if (seg0 + m0 >= seg1) return;
    const int n0 = blockIdx.x * 128;

    __shared__ float As[16][128];
    __shared__ float Bs[16][128];
    __shared__ int tok[128];

    const int tid = threadIdx.x;
    if (tid < 128) {
        const int p = seg0 + m0 + tid;
        tok[tid] = (p < seg1) ? g_order[p] : -1;
    }
    __syncthreads();

    const float* Bm = W1 + (size_t)e * ND * NF;
    const int tx = tid & 15, ty = tid >> 4;
    float acc[8][8];
#pragma unroll
    for (int i = 0; i < 8; ++i)
#pragma unroll
        for (int j = 0; j < 8; ++j) acc[i][j] = 0.f;

    for (int k0 = 0; k0 < ND; k0 += 16) {
#pragma unroll
        for (int it = 0; it < 2; ++it) {
            int v = tid + it * 256;
            int row = v >> 2;
            int kq = (v & 3) * 4;
            int tk = tok[row];
            float4 t4 = make_float4(0.f, 0.f, 0.f, 0.f);
            if (tk >= 0) t4 = *reinterpret_cast<const float4*>(X + (size_t)tk * ND + k0 + kq);
            As[kq + 0][row] = t4.x; As[kq + 1][row] = t4.y;
            As[kq + 2][row] = t4.z; As[kq + 3][row] = t4.w;
        }
#pragma unroll
        for (int it = 0; it < 2; ++it) {
            int v = tid + it * 256;
            int krow = v >> 5;            // 0..15
            int nq = (v & 31) * 4;        // 0..124
            float4 t4 = *reinterpret_cast<const float4*>(Bm + (size_t)(k0 + krow) * NF + n0 + nq);
            *reinterpret_cast<float4*>(&Bs[krow][nq]) = t4;
        }
        __syncthreads();
#pragma unroll
        for (int kk = 0; kk < 16; ++kk) {
            float4 a0 = *reinterpret_cast<const float4*>(&As[kk][ty * 8]);
            float4 a1 = *reinterpret_cast<const float4*>(&As[kk][ty * 8 + 4]);
            float4 b0 = *reinterpret_cast<const float4*>(&Bs[kk][tx * 8]);
            float4 b1r = *reinterpret_cast<const float4*>(&Bs[kk][tx * 8 + 4]);
            float a[8] = {a0.x, a0.y, a0.z, a0.w, a1.x, a1.y, a1.z, a1.w};
            float b[8] = {b0.x, b0.y, b0.z, b0.w, b1r.x, b1r.y, b1r.z, b1r.w};
#pragma unroll
            for (int i = 0; i < 8; ++i)
#pragma unroll
                for (int j = 0; j < 8; ++j) acc[i][j] = fmaf(a[i], b[j], acc[i][j]);
        }
        __syncthreads();
    }

#pragma unroll
    for (int i = 0; i < 8; ++i) {
        const int p = seg0 + m0 + ty * 8 + i;
        if (p < seg1) {
            float* hp = g_h + (size_t)p * NF + n0 + tx * 8;
#pragma unroll
            for (int j = 0; j < 8; ++j) {
                float v = acc[i][j] + b1[(size_t)e * NF + n0 + tx * 8 + j];
                hp[j] = fmaxf(v, 0.f);
            }
        }
    }
}

// ---------------- MoE grouped GEMM 2: y[tok(p),d] = h[p,:] @ W2[e] + b2[e] ----------
// grid: (ND/128, NT/128, NE), block 256
__global__ __launch_bounds__(256) void moe_gemm2(
    const float* __restrict__ W2, const float* __restrict__ b2,
    float* __restrict__ Y)
{
    const int e = blockIdx.z;
    const int seg0 = g_off[e], seg1 = g_off[e + 1];
    const int m0 = blockIdx.y * 128;
    if (seg0 + m0 >= seg1) return;
    const int n0 = blockIdx.x * 128;

    __shared__ float As[16][128];
    __shared__ float Bs[16][128];
    __shared__ int tok[128];

    const int tid = threadIdx.x;
    if (tid < 128) {
        const int p = seg0 + m0 + tid;
        tok[tid] = (p < seg1) ? g_order[p] : -1;
    }
    __syncthreads();

    const float* Bm = W2 + (size_t)e * NF * ND;
    const int tx = tid & 15, ty = tid >> 4;
    float acc[8][8];
#pragma unroll
    for (int i = 0; i < 8; ++i)
#pragma unroll
        for (int j = 0; j < 8; ++j) acc[i][j] = 0.f;

    for (int k0 = 0; k0 < NF; k0 += 16) {
#pragma unroll
        for (int it = 0; it < 2; ++it) {
            int v = tid + it * 256;
            int row = v >> 2;
            int kq = (v & 3) * 4;
            const int p = seg0 + m0 + row;   // g_h oversized: reads past 4096 stay in-bounds
            float4 t4 = *reinterpret_cast<const float4*>(g_h + (size_t)p * NF + k0 + kq);
            As[kq + 0][row] = t4.x; As[kq + 1][row] = t4.y;
            As[kq + 2][row] = t4.z; As[kq + 3][row] = t4.w;
        }
#pragma unroll
        for (int it = 0; it < 2; ++it) {
            int v = tid + it * 256;
            int krow = v >> 5;
            int nq = (v & 31) * 4;
            float4 t4 = *reinterpret_cast<const float4*>(Bm + (size_t)(k0 + krow) * ND + n0 + nq);
            *reinterpret_cast<float4*>(&Bs[krow][nq]) = t4;
        }
        __syncthreads();
#pragma unroll
        for (int kk = 0; kk < 16; ++kk) {
            float4 a0 = *reinterpret_cast<const float4*>(&As[kk][ty * 8]);
            float4 a1 = *reinterpret_cast<const float4*>(&As[kk][ty * 8 + 4]);
            float4 b0 = *reinterpret_cast<const float4*>(&Bs[kk][tx * 8]);
            float4 b1r = *reinterpret_cast<const float4*>(&Bs[kk][tx * 8 + 4]);
            float a[8] = {a0.x, a0.y, a0.z, a0.w, a1.x, a1.y, a1.z, a1.w};
            float b[8] = {b0.x, b0.y, b0.z, b0.w, b1r.x, b1r.y, b1r.z, b1r.w};
#pragma unroll
            for (int i = 0; i < 8; ++i)
#pragma unroll
                for (int j = 0; j < 8; ++j) acc[i][j] = fmaf(a[i], b[j], acc[i][j]);
        }
        __syncthreads();
    }

#pragma unroll
    for (int i = 0; i < 8; ++i) {
        const int tk = tok[ty * 8 + i];
        if (tk >= 0) {
            float* yp = Y + (size_t)tk * ND + n0 + tx * 8;
#pragma unroll
            for (int j = 0; j < 8; ++j)
                yp[j] = acc[i][j] + b2[(size_t)e * ND + n0 + tx * 8 + j];
        }
    }
}

// ---------------- launcher ----------------
extern "C" void kernel_launch(void* const* d_in, const int* in_sizes, int n_in,
                              void* d_out, int out_size)
{
    const float* x         = (const float*)d_in[0];
    const float* in_proj_w = (const float*)d_in[1];
    const float* in_proj_b = (const float*)d_in[2];
    const float* out_w     = (const float*)d_in[3];
    const float* out_b     = (const float*)d_in[4];
    const float* gate_w    = (const float*)d_in[5];
    const float* gate_b    = (const float*)d_in[6];
    const float* W1        = (const float*)d_in[7];
    const float* b1        = (const float*)d_in[8];
    const float* W2        = (const float*)d_in[9];
    const float* b2        = (const float*)d_in[10];
    const float* ln1_g     = (const float*)d_in[11];
    const float* ln1_b     = (const float*)d_in[12];
    const float* ln2_g     = (const float*)d_in[13];
    const float* ln2_b     = (const float*)d_in[14];
    float* out = (float*)d_out;

    float* qkv;   cudaGetSymbolAddress((void**)&qkv,   g_qkv);
    float* attno; cudaGetSymbolAddress((void**)&attno, g_attno);
    float* tmp;   cudaGetSymbolAddress((void**)&tmp,   g_tmp);
    float* x1;    cudaGetSymbolAddress((void**)&x1,    g_x1);

    // 1) QKV projection
    sgemm_abt<<<dim3(3 * ND / 128, NT / 128), 256>>>(x, in_proj_w, in_proj_b, qkv, NT, 3 * ND, ND);
    // 2) attention
    flash_attn<<<dim3(NS / 64, NB * NH), 64>>>(qkv, attno);
    // 3) output projection
    sgemm_abt<<<dim3(ND / 128, NT / 128), 256>>>(attno, out_w, out_b, tmp, NT, ND, ND);
    // 4) residual + LN1
    add_ln<<<NT, 256>>>(tmp, x, ln1_g, ln1_b, x1);
    // 5) routing
    route_init<<<1, 32>>>();
    gate_kernel<<<NT / 8, 256>>>(x1, gate_w, gate_b);
    route_scan<<<1, 1>>>();
    route_scatter<<<NT / 256, 256>>>();
    // 6) MoE expert FFN (grouped)
    moe_gemm1<<<dim3(NF / 128, NT / 128, NE), 256>>>(x1, W1, b1);
    moe_gemm2<<<dim3(ND / 128, NT / 128, NE), 256>>>(W2, b2, tmp);
    // 7) residual + LN2 -> output
    add_ln<<<NT, 256>>>(tmp, x1, ln2_g, ln2_b, out);

    (void)in_sizes; (void)n_in; (void)out_size;
}

// round 4
// speedup vs baseline: 1.9747x; 1.9747x over previous
#include <cuda_runtime.h>
#include <math.h>
#include <float.h>
#include <stdint.h>

// ---------------- problem constants ----------------
constexpr int NB  = 4;
constexpr int NS  = 1024;
constexpr int ND  = 1024;
constexpr int NH  = 16;
constexpr int NHD = 64;
constexpr int NE  = 8;
constexpr int NF  = 4096;
constexpr int NT  = NB * NS;            // 4096 tokens
constexpr float EPS = 1e-5f;

// ---------------- scratch (device globals; no runtime alloc) ----------------
__device__ float g_qkv[(size_t)NT * 3 * ND];
__device__ float g_attno[(size_t)NT * ND];
__device__ float g_tmp[(size_t)NT * ND];
__device__ float g_x1[(size_t)NT * ND];
__device__ float g_h[(size_t)(NT + 128) * NF];
__device__ int   g_idx[NT];
__device__ int   g_order[NT];
__device__ int   g_cnt[NE];
__device__ int   g_off[NE + 1];
__device__ int   g_pos[NE];

// ---------------- tf32 helpers ----------------
__device__ __forceinline__ uint32_t tf32r(float x) {
    uint32_t u; asm("cvt.rna.tf32.f32 %0, %1;" : "=r"(u) : "f"(x)); return u;
}
__device__ __forceinline__ void mma_tf32(float c[4], const uint32_t a[4],
                                         uint32_t b0, uint32_t b1) {
    asm volatile(
        "mma.sync.aligned.m16n8k8.row.col.f32.tf32.tf32.f32 "
        "{%0,%1,%2,%3}, {%4,%5,%6,%7}, {%8,%9}, {%0,%1,%2,%3};"
        : "+f"(c[0]), "+f"(c[1]), "+f"(c[2]), "+f"(c[3])
        : "r"(a[0]), "r"(a[1]), "r"(a[2]), "r"(a[3]), "r"(b0), "r"(b1));
}

// ---------------- SMEM layout constants (floats) ----------------
constexpr int A_STG = 4608;                          // [128][36]
constexpr int B_OFF = 9216;
constexpr int B_STG = 4608;                          // [128][36] or [32][136]
constexpr int SMEM_FLOATS = B_OFF + 2 * B_STG;       // 18432 floats = 73728 B

// ================= tf32 tensor-core GEMM =================
// C[M,N] = A[M,K] * B^T + bias.
// MODE 0: B is [N,K] row-major (k-contiguous). Plain rows.
// MODE 1: MoE FFN1 — A gathered via g_order, B is [K,N] (n-contig), ReLU, store rows p.
// MODE 2: MoE FFN2 — A direct rows of g_h, B is [K,N], scatter store via tok.
template<int MODE>
__global__ void __launch_bounds__(256) gemm_mma(
    const float* __restrict__ A, int lda,
    const float* __restrict__ B, int ldb,
    const float* __restrict__ bias,
    float* __restrict__ C, int ldc,
    int K, int Nglob)
{
    extern __shared__ float smf[];
    __shared__ int tok[128];

    const int tid = threadIdx.x;
    const int wid = tid >> 5;
    const int ln  = tid & 31;
    const int wm  = wid >> 1;           // 0..3 -> 32-row slice
    const int wn  = wid & 1;            // 0..1 -> 64-col slice
    const int m0 = blockIdx.x * 128;
    const int n0 = blockIdx.y * 128;

    int seg0 = 0, seg1 = 1 << 30;
    const float* Bp = B;
    const float* biasp = bias;
    if (MODE != 0) {
        const int e = blockIdx.z;
        seg0 = g_off[e]; seg1 = g_off[e + 1];
        if (seg0 + m0 >= seg1) return;
        Bp    = B + (size_t)e * K * Nglob;
        biasp = bias + (size_t)e * Nglob;
        if (tid < 128) {
            const int p = seg0 + m0 + tid;
            tok[tid] = (p < seg1) ? g_order[p] : -1;
        }
        __syncthreads();   // tok[] visible to ALL warps before any gather
    }

    float acc[2][8][4];
#pragma unroll
    for (int mt = 0; mt < 2; ++mt)
#pragma unroll
        for (int nt = 0; nt < 8; ++nt)
#pragma unroll
            for (int r = 0; r < 4; ++r) acc[mt][nt][r] = 0.f;

    float4 pa[4];
    float4 pb4[4];
    float  pbs[16];

    const int nK = K >> 5;

    auto loadA = [&](int kt) {
        const int k0 = kt << 5;
#pragma unroll
        for (int it = 0; it < 4; ++it) {
            const int idx = tid + it * 256;
            const int row = idx >> 3;
            const int kq  = (idx & 7) * 4;
            if (MODE == 1) {
                const int tk = tok[row];
                pa[it] = (tk >= 0)
                    ? *reinterpret_cast<const float4*>(A + (size_t)tk * lda + k0 + kq)
                    : make_float4(0.f, 0.f, 0.f, 0.f);
            } else if (MODE == 2) {
                pa[it] = *reinterpret_cast<const float4*>(A + (size_t)(seg0 + m0 + row) * lda + k0 + kq);
            } else {
                pa[it] = *reinterpret_cast<const float4*>(A + (size_t)(m0 + row) * lda + k0 + kq);
            }
        }
    };
    auto loadB = [&](int kt) {
        const int k0 = kt << 5;
        if (MODE == 0) {
#pragma unroll
            for (int it = 0; it < 4; ++it) {
                const int idx = tid + it * 256;
                const int row = idx >> 3;
                const int kq  = (idx & 7) * 4;
                pb4[it] = *reinterpret_cast<const float4*>(Bp + (size_t)(n0 + row) * ldb + k0 + kq);
            }
        } else {
#pragma unroll
            for (int it = 0; it < 16; ++it) {
                const int flat = tid + it * 256;
                const int k = flat >> 7;
                const int n = flat & 127;
                pbs[it] = Bp[(size_t)(k0 + k) * ldb + n0 + n];
            }
        }
    };
    auto stsAB = [&](int s) {
        float* sA = smf + s * A_STG;
        float* sB = smf + B_OFF + s * B_STG;
#pragma unroll
        for (int it = 0; it < 4; ++it) {
            const int idx = tid + it * 256;
            const int row = idx >> 3;
            const int kq  = (idx & 7) * 4;
            uint4 u;
            u.x = tf32r(pa[it].x); u.y = tf32r(pa[it].y);
            u.z = tf32r(pa[it].z); u.w = tf32r(pa[it].w);
            *reinterpret_cast<uint4*>(sA + row * 36 + kq) = u;
        }
        if (MODE == 0) {
#pragma unroll
            for (int it = 0; it < 4; ++it) {
                const int idx = tid + it * 256;
                const int row = idx >> 3;
                const int kq  = (idx & 7) * 4;
                uint4 u;
                u.x = tf32r(pb4[it].x); u.y = tf32r(pb4[it].y);
                u.z = tf32r(pb4[it].z); u.w = tf32r(pb4[it].w);
                *reinterpret_cast<uint4*>(sB + row * 36 + kq) = u;
            }
        } else {
#pragma unroll
            for (int it = 0; it < 16; ++it) {
                const int flat = tid + it * 256;
                const int k = flat >> 7;
                const int n = flat & 127;
                reinterpret_cast<uint32_t*>(sB)[k * 136 + n] = tf32r(pbs[it]);
            }
        }
    };
    auto compute = [&](int s) {
        const uint32_t* sA = reinterpret_cast<const uint32_t*>(smf + s * A_STG);
        const uint32_t* sB = reinterpret_cast<const uint32_t*>(smf + B_OFF + s * B_STG);
        const int lr = ln >> 2;
        const int lc = ln & 3;
#pragma unroll
        for (int ks = 0; ks < 4; ++ks) {
            const int kk = ks * 8;
            uint32_t af[2][4];
#pragma unroll
            for (int mt = 0; mt < 2; ++mt) {
                const int r = wm * 32 + mt * 16 + lr;
                af[mt][0] = sA[r * 36 + kk + lc];
                af[mt][1] = sA[(r + 8) * 36 + kk + lc];
                af[mt][2] = sA[r * 36 + kk + 4 + lc];
                af[mt][3] = sA[(r + 8) * 36 + kk + 4 + lc];
            }
#pragma unroll
            for (int nt = 0; nt < 8; ++nt) {
                const int n = wn * 64 + nt * 8 + lr;
                uint32_t b0, b1;
                if (MODE == 0) {
                    b0 = sB[n * 36 + kk + lc];
                    b1 = sB[n * 36 + kk + 4 + lc];
                } else {
                    b0 = sB[(kk + lc) * 136 + n];
                    b1 = sB[(kk + 4 + lc) * 136 + n];
                }
                mma_tf32(acc[0][nt], af[0], b0, b1);
                mma_tf32(acc[1][nt], af[1], b0, b1);
            }
        }
    };

    // ---- pipelined mainloop ----
    loadA(0); loadB(0);
    stsAB(0);
    __syncthreads();
    for (int kt = 0; kt < nK; ++kt) {
        const int s = kt & 1;
        if (kt + 1 < nK) { loadA(kt + 1); loadB(kt + 1); }
        compute(s);
        if (kt + 1 < nK) {
            stsAB(s ^ 1);
            __syncthreads();
        }
    }

    // ---- epilogue ----
    const int lr = ln >> 2;
    const int lc = ln & 3;
#pragma unroll
    for (int mt = 0; mt < 2; ++mt) {
        const int lrow0 = wm * 32 + mt * 16 + lr;
#pragma unroll
        for (int half = 0; half < 2; ++half) {
            const int lrow = lrow0 + half * 8;
            float* dst = nullptr;
            bool valid = true;
            if (MODE == 0) {
                dst = C + (size_t)(m0 + lrow) * ldc;
            } else if (MODE == 1) {
                const int p = seg0 + m0 + lrow;
                valid = (p < seg1);
                dst = C + (size_t)p * ldc;
            } else {
                const int tk = tok[lrow];
                valid = (tk >= 0);
                dst = C + (size_t)(valid ? tk : 0) * ldc;
            }
            if (!valid) continue;
#pragma unroll
            for (int nt = 0; nt < 8; ++nt) {
                const int cc = n0 + wn * 64 + nt * 8 + lc * 2;
                float2 v;
                v.x = acc[mt][nt][half * 2 + 0] + biasp[cc];
                v.y = acc[mt][nt][half * 2 + 1] + biasp[cc + 1];
                if (MODE == 1) { v.x = fmaxf(v.x, 0.f); v.y = fmaxf(v.y, 0.f); }
                *reinterpret_cast<float2*>(dst + cc) = v;
            }
        }
    }
}

// ---------------- flash attention (fp32, Br=Bc=64, HD=64) ----------------
__global__ __launch_bounds__(64) void flash_attn(
    const float* __restrict__ qkv, float* __restrict__ O)
{
    const int bh = blockIdx.y;
    const int b  = bh >> 4;
    const int h  = bh & 15;
    const int q  = blockIdx.x * 64 + threadIdx.x;
    const int tx = threadIdx.x;

    __shared__ float Ks[64][68];
    __shared__ float Vs[64][68];

    const size_t str = 3 * ND;
    const float* qp = qkv + ((size_t)(b * NS) + q) * str + h * NHD;

    float qr[64];
#pragma unroll
    for (int d = 0; d < 64; d += 4) {
        float4 t = *reinterpret_cast<const float4*>(qp + d);
        qr[d] = t.x; qr[d + 1] = t.y; qr[d + 2] = t.z; qr[d + 3] = t.w;
    }
    float o[64];
#pragma unroll
    for (int d = 0; d < 64; ++d) o[d] = 0.f;
    float m = -1e30f, l = 0.f;
    const float scale = 0.125f;

    for (int kt = 0; kt < NS; kt += 64) {
        const float* kp = qkv + ((size_t)(b * NS) + kt + tx) * str + ND + h * NHD;
        const float* vp = kp + ND;
#pragma unroll
        for (int d = 0; d < 64; d += 4) {
            float4 kk = *reinterpret_cast<const float4*>(kp + d);
            float4 vv = *reinterpret_cast<const float4*>(vp + d);
            *reinterpret_cast<float4*>(&Ks[tx][d]) = kk;
            *reinterpret_cast<float4*>(&Vs[tx][d]) = vv;
        }
        __syncthreads();

        float s[64];
        float mn = m;
#pragma unroll 2
        for (int j = 0; j < 64; ++j) {
            float sum = 0.f;
#pragma unroll
            for (int d = 0; d < 64; d += 4) {
                float4 kv = *reinterpret_cast<const float4*>(&Ks[j][d]);
                sum = fmaf(qr[d], kv.x, sum);
                sum = fmaf(qr[d + 1], kv.y, sum);
                sum = fmaf(qr[d + 2], kv.z, sum);
                sum = fmaf(qr[d + 3], kv.w, sum);
            }
            sum *= scale;
            s[j] = sum;
            mn = fmaxf(mn, sum);
        }
        float corr = __expf(m - mn);
        m = mn;
        l *= corr;
#pragma unroll
        for (int d = 0; d < 64; ++d) o[d] *= corr;
#pragma unroll 2
        for (int j = 0; j < 64; ++j) {
            float p = __expf(s[j] - m);
            l += p;
#pragma unroll
            for (int d = 0; d < 64; d += 4) {
                float4 vv = *reinterpret_cast<const float4*>(&Vs[j][d]);
                o[d]     = fmaf(p, vv.x, o[d]);
                o[d + 1] = fmaf(p, vv.y, o[d + 1]);
                o[d + 2] = fmaf(p, vv.z, o[d + 2]);
                o[d + 3] = fmaf(p, vv.w, o[d + 3]);
            }
        }
        __syncthreads();
    }

    const float inv = 1.f / l;
    float* op = O + ((size_t)(b * NS) + q) * ND + h * NHD;
#pragma unroll
    for (int d = 0; d < 64; d += 4) {
        float4 t;
        t.x = o[d] * inv; t.y = o[d + 1] * inv; t.z = o[d + 2] * inv; t.w = o[d + 3] * inv;
        *reinterpret_cast<float4*>(op + d) = t;
    }
}

// ---------------- residual add + LayerNorm ----------------
__global__ __launch_bounds__(256) void add_ln(
    const float* __restrict__ A, const float* __restrict__ R,
    const float* __restrict__ g, const float* __restrict__ bt,
    float* __restrict__ out)
{
    const int t = blockIdx.x;
    const int tid = threadIdx.x;
    __shared__ float red[8];

    const float4 a4 = *reinterpret_cast<const float4*>(A + (size_t)t * ND + tid * 4);
    const float4 r4 = *reinterpret_cast<const float4*>(R + (size_t)t * ND + tid * 4);
    float v[4] = {a4.x + r4.x, a4.y + r4.y, a4.z + r4.z, a4.w + r4.w};

    float sum = v[0] + v[1] + v[2] + v[3];
#pragma unroll
    for (int off = 16; off; off >>= 1) sum += __shfl_down_sync(0xffffffffu, sum, off);
    if ((tid & 31) == 0) red[tid >> 5] = sum;
    __syncthreads();
    if (tid < 8) {
        float s = red[tid];
#pragma unroll
        for (int off = 4; off; off >>= 1) s += __shfl_down_sync(0xffu, s, off);
        if (tid == 0) red[0] = s;
    }
    __syncthreads();
    const float mu = red[0] * (1.f / ND);
    __syncthreads();

    float vs = 0.f;
#pragma unroll
    for (int i = 0; i < 4; ++i) { float d = v[i] - mu; vs += d * d; }
#pragma unroll
    for (int off = 16; off; off >>= 1) vs += __shfl_down_sync(0xffffffffu, vs, off);
    if ((tid & 31) == 0) red[tid >> 5] = vs;
    __syncthreads();
    if (tid < 8) {
        float s = red[tid];
#pragma unroll
        for (int off = 4; off; off >>= 1) s += __shfl_down_sync(0xffu, s, off);
        if (tid == 0) red[0] = s;
    }
    __syncthreads();
    const float rstd = rsqrtf(red[0] * (1.f / ND) + EPS);

    float4 o4;
    const int d0 = tid * 4;
    o4.x = (v[0] - mu) * rstd * g[d0]     + bt[d0];
    o4.y = (v[1] - mu) * rstd * g[d0 + 1] + bt[d0 + 1];
    o4.z = (v[2] - mu) * rstd * g[d0 + 2] + bt[d0 + 2];
    o4.w = (v[3] - mu) * rstd * g[d0 + 3] + bt[d0 + 3];
    *reinterpret_cast<float4*>(out + (size_t)t * ND + d0) = o4;
}

// ---------------- routing ----------------
__global__ void route_init() {
    if (threadIdx.x < NE) g_cnt[threadIdx.x] = 0;
}

__global__ __launch_bounds__(256) void gate_kernel(
    const float* __restrict__ X, const float* __restrict__ gw,
    const float* __restrict__ gb)
{
    const int warp = threadIdx.x >> 5;
    const int lane = threadIdx.x & 31;
    const int t = blockIdx.x * 8 + warp;
    const float* xp = X + (size_t)t * ND;
    float acc[NE];
#pragma unroll
    for (int e = 0; e < NE; ++e) acc[e] = 0.f;
    for (int d = lane; d < ND; d += 32) {
        const float xv = xp[d];
#pragma unroll
        for (int e = 0; e < NE; ++e) acc[e] = fmaf(xv, gw[e * ND + d], acc[e]);
    }
#pragma unroll
    for (int e = 0; e < NE; ++e)
#pragma unroll
        for (int off = 16; off; off >>= 1)
            acc[e] += __shfl_down_sync(0xffffffffu, acc[e], off);
    if (lane == 0) {
        int best = 0; float bv = acc[0] + gb[0];
#pragma unroll
        for (int e = 1; e < NE; ++e) {
            float v = acc[e] + gb[e];
            if (v > bv) { bv = v; best = e; }
        }
        g_idx[t] = best;
        atomicAdd(&g_cnt[best], 1);
    }
}

__global__ void route_scan() {
    g_off[0] = 0;
    for (int e = 0; e < NE; ++e) {
        g_off[e + 1] = g_off[e] + g_cnt[e];
        g_pos[e] = g_off[e];
    }
}

__global__ __launch_bounds__(256) void route_scatter() {
    const int t = blockIdx.x * 256 + threadIdx.x;
    if (t < NT) {
        const int e = g_idx[t];
        const int p = atomicAdd(&g_pos[e], 1);
        g_order[p] = t;
    }
}

// ---------------- launcher ----------------
extern "C" void kernel_launch(void* const* d_in, const int* in_sizes, int n_in,
                              void* d_out, int out_size)
{
    const float* x         = (const float*)d_in[0];
    const float* in_proj_w = (const float*)d_in[1];
    const float* in_proj_b = (const float*)d_in[2];
    const float* out_w     = (const float*)d_in[3];
    const float* out_b     = (const float*)d_in[4];
    const float* gate_w    = (const float*)d_in[5];
    const float* gate_b    = (const float*)d_in[6];
    const float* W1        = (const float*)d_in[7];
    const float* b1        = (const float*)d_in[8];
    const float* W2        = (const float*)d_in[9];
    const float* b2        = (const float*)d_in[10];
    const float* ln1_g     = (const float*)d_in[11];
    const float* ln1_b     = (const float*)d_in[12];
    const float* ln2_g     = (const float*)d_in[13];
    const float* ln2_b     = (const float*)d_in[14];
    float* out = (float*)d_out;

    float* qkv;   cudaGetSymbolAddress((void**)&qkv,   g_qkv);
    float* attno; cudaGetSymbolAddress((void**)&attno, g_attno);
    float* tmp;   cudaGetSymbolAddress((void**)&tmp,   g_tmp);
    float* x1;    cudaGetSymbolAddress((void**)&x1,    g_x1);
    float* hbuf;  cudaGetSymbolAddress((void**)&hbuf,  g_h);

    const int smem = SMEM_FLOATS * 4;   // 73728 B
    cudaFuncSetAttribute(gemm_mma<0>, cudaFuncAttributeMaxDynamicSharedMemorySize, smem);
    cudaFuncSetAttribute(gemm_mma<1>, cudaFuncAttributeMaxDynamicSharedMemorySize, smem);
    cudaFuncSetAttribute(gemm_mma<2>, cudaFuncAttributeMaxDynamicSharedMemorySize, smem);

    // 1) QKV projection: [4096,1024] @ [3072,1024]^T
    gemm_mma<0><<<dim3(NT / 128, 3 * ND / 128, 1), 256, smem>>>(
        x, ND, in_proj_w, ND, in_proj_b, qkv, 3 * ND, ND, 3 * ND);
    // 2) attention
    flash_attn<<<dim3(NS / 64, NB * NH), 64>>>(qkv, attno);
    // 3) output projection
    gemm_mma<0><<<dim3(NT / 128, ND / 128, 1), 256, smem>>>(
        attno, ND, out_w, ND, out_b, tmp, ND, ND, ND);
    // 4) residual + LN1
    add_ln<<<NT, 256>>>(tmp, x, ln1_g, ln1_b, x1);
    // 5) routing
    route_init<<<1, 32>>>();
    gate_kernel<<<NT / 8, 256>>>(x1, gate_w, gate_b);
    route_scan<<<1, 1>>>();
    route_scatter<<<NT / 256, 256>>>();
    // 6) MoE expert FFN
    gemm_mma<1><<<dim3(NT / 128, NF / 128, NE), 256, smem>>>(
        x1, ND, W1, NF, b1, hbuf, NF, ND, NF);
    gemm_mma<2><<<dim3(NT / 128, ND / 128, NE), 256, smem>>>(
        hbuf, NF, W2, ND, b2, tmp, ND, NF, ND);
    // 7) residual + LN2 -> output
    add_ln<<<NT, 256>>>(tmp, x1, ln2_g, ln2_b, out);

    (void)in_sizes; (void)n_in; (void)out_size;
}

// round 5
// speedup vs baseline: 3.0882x; 1.5639x over previous
#include <cuda_runtime.h>
#include <math.h>
#include <float.h>
#include <stdint.h>

// ---------------- problem constants ----------------
constexpr int NB  = 4;
constexpr int NS  = 1024;
constexpr int ND  = 1024;
constexpr int NH  = 16;
constexpr int NHD = 64;
constexpr int NE  = 8;
constexpr int NF  = 4096;
constexpr int NT  = NB * NS;            // 4096 tokens
constexpr float EPS = 1e-5f;

// ---------------- scratch (device globals; no runtime alloc) ----------------
__device__ float g_qkv[(size_t)NT * 3 * ND];
__device__ float g_attno[(size_t)NT * ND];
__device__ float g_tmp[(size_t)NT * ND];
__device__ float g_x1[(size_t)NT * ND];
__device__ float g_h[(size_t)(NT + 128) * NF];
__device__ int   g_idx[NT];
__device__ int   g_order[NT];
__device__ int   g_cnt[NE];
__device__ int   g_off[NE + 1];
__device__ int   g_pos[NE];

// ---------------- tf32 helpers ----------------
__device__ __forceinline__ uint32_t tf32r(float x) {
    uint32_t u; asm("cvt.rna.tf32.f32 %0, %1;" : "=r"(u) : "f"(x)); return u;
}
__device__ __forceinline__ void mma_tf32(float c[4], const uint32_t a[4],
                                         uint32_t b0, uint32_t b1) {
    asm volatile(
        "mma.sync.aligned.m16n8k8.row.col.f32.tf32.tf32.f32 "
        "{%0,%1,%2,%3}, {%4,%5,%6,%7}, {%8,%9}, {%0,%1,%2,%3};"
        : "+f"(c[0]), "+f"(c[1]), "+f"(c[2]), "+f"(c[3])
        : "r"(a[0]), "r"(a[1]), "r"(a[2]), "r"(a[3]), "r"(b0), "r"(b1));
}

// fast 2^y for y <= 0, on the FMA pipe (no MUFU). |rel err| ~3e-6.
__device__ __forceinline__ float exp2p(float y) {
    y = fmaxf(y, -80.f);
    const int ni = __float2int_rn(y);
    const float f = y - (float)ni;
    float p = 0.0013333558146428443f;
    p = fmaf(p, f, 0.009618129107628477f);
    p = fmaf(p, f, 0.05550410866482158f);
    p = fmaf(p, f, 0.2402265069591007f);
    p = fmaf(p, f, 0.6931471805599453f);
    p = fmaf(p, f, 1.0f);
    return __uint_as_float(__float_as_uint(p) + ((uint32_t)ni << 23));
}

// ---------------- SMEM layout constants (floats) ----------------
constexpr int A_STG = 4608;                          // [128][36]
constexpr int B_OFF = 9216;
constexpr int B_STG = 4608;                          // [128][36] or [32][136]
constexpr int SMEM_FLOATS = B_OFF + 2 * B_STG;       // 18432 floats = 73728 B

// ================= tf32 tensor-core GEMM =================
// C[M,N] = A[M,K] * B^T + bias.
// MODE 0: B is [N,K] row-major (k-contiguous). Plain rows.
// MODE 1: MoE FFN1 — A gathered via g_order, B is [K,N] (n-contig), ReLU, store rows p.
// MODE 2: MoE FFN2 — A direct rows of g_h, B is [K,N], scatter store via tok.
template<int MODE>
__global__ void __launch_bounds__(256) gemm_mma(
    const float* __restrict__ A, int lda,
    const float* __restrict__ B, int ldb,
    const float* __restrict__ bias,
    float* __restrict__ C, int ldc,
    int K, int Nglob)
{
    extern __shared__ float smf[];
    __shared__ int tok[128];

    const int tid = threadIdx.x;
    const int wid = tid >> 5;
    const int ln  = tid & 31;
    const int wm  = wid >> 1;
    const int wn  = wid & 1;
    const int m0 = blockIdx.x * 128;
    const int n0 = blockIdx.y * 128;

    int seg0 = 0, seg1 = 1 << 30;
    const float* Bp = B;
    const float* biasp = bias;
    if (MODE != 0) {
        const int e = blockIdx.z;
        seg0 = g_off[e]; seg1 = g_off[e + 1];
        if (seg0 + m0 >= seg1) return;
        Bp    = B + (size_t)e * K * Nglob;
        biasp = bias + (size_t)e * Nglob;
        if (tid < 128) {
            const int p = seg0 + m0 + tid;
            tok[tid] = (p < seg1) ? g_order[p] : -1;
        }
        __syncthreads();
    }

    float acc[2][8][4];
#pragma unroll
    for (int mt = 0; mt < 2; ++mt)
#pragma unroll
        for (int nt = 0; nt < 8; ++nt)
#pragma unroll
            for (int r = 0; r < 4; ++r) acc[mt][nt][r] = 0.f;

    float4 pa[4];
    float4 pb4[4];
    float  pbs[16];

    const int nK = K >> 5;

    auto loadA = [&](int kt) {
        const int k0 = kt << 5;
#pragma unroll
        for (int it = 0; it < 4; ++it) {
            const int idx = tid + it * 256;
            const int row = idx >> 3;
            const int kq  = (idx & 7) * 4;
            if (MODE == 1) {
                const int tk = tok[row];
                pa[it] = (tk >= 0)
                    ? *reinterpret_cast<const float4*>(A + (size_t)tk * lda + k0 + kq)
                    : make_float4(0.f, 0.f, 0.f, 0.f);
            } else if (MODE == 2) {
                pa[it] = *reinterpret_cast<const float4*>(A + (size_t)(seg0 + m0 + row) * lda + k0 + kq);
            } else {
                pa[it] = *reinterpret_cast<const float4*>(A + (size_t)(m0 + row) * lda + k0 + kq);
            }
        }
    };
    auto loadB = [&](int kt) {
        const int k0 = kt << 5;
        if (MODE == 0) {
#pragma unroll
            for (int it = 0; it < 4; ++it) {
                const int idx = tid + it * 256;
                const int row = idx >> 3;
                const int kq  = (idx & 7) * 4;
                pb4[it] = *reinterpret_cast<const float4*>(Bp + (size_t)(n0 + row) * ldb + k0 + kq);
            }
        } else {
#pragma unroll
            for (int it = 0; it < 16; ++it) {
                const int flat = tid + it * 256;
                const int k = flat >> 7;
                const int n = flat & 127;
                pbs[it] = Bp[(size_t)(k0 + k) * ldb + n0 + n];
            }
        }
    };
    auto stsAB = [&](int s) {
        float* sA = smf + s * A_STG;
        float* sB = smf + B_OFF + s * B_STG;
#pragma unroll
        for (int it = 0; it < 4; ++it) {
            const int idx = tid + it * 256;
            const int row = idx >> 3;
            const int kq  = (idx & 7) * 4;
            uint4 u;
            u.x = tf32r(pa[it].x); u.y = tf32r(pa[it].y);
            u.z = tf32r(pa[it].z); u.w = tf32r(pa[it].w);
            *reinterpret_cast<uint4*>(sA + row * 36 + kq) = u;
        }
        if (MODE == 0) {
#pragma unroll
            for (int it = 0; it < 4; ++it) {
                const int idx = tid + it * 256;
                const int row = idx >> 3;
                const int kq  = (idx & 7) * 4;
                uint4 u;
                u.x = tf32r(pb4[it].x); u.y = tf32r(pb4[it].y);
                u.z = tf32r(pb4[it].z); u.w = tf32r(pb4[it].w);
                *reinterpret_cast<uint4*>(sB + row * 36 + kq) = u;
            }
        } else {
#pragma unroll
            for (int it = 0; it < 16; ++it) {
                const int flat = tid + it * 256;
                const int k = flat >> 7;
                const int n = flat & 127;
                reinterpret_cast<uint32_t*>(sB)[k * 136 + n] = tf32r(pbs[it]);
            }
        }
    };
    auto compute = [&](int s) {
        const uint32_t* sA = reinterpret_cast<const uint32_t*>(smf + s * A_STG);
        const uint32_t* sB = reinterpret_cast<const uint32_t*>(smf + B_OFF + s * B_STG);
        const int lr = ln >> 2;
        const int lc = ln & 3;
#pragma unroll
        for (int ks = 0; ks < 4; ++ks) {
            const int kk = ks * 8;
            uint32_t af[2][4];
#pragma unroll
            for (int mt = 0; mt < 2; ++mt) {
                const int r = wm * 32 + mt * 16 + lr;
                af[mt][0] = sA[r * 36 + kk + lc];
                af[mt][1] = sA[(r + 8) * 36 + kk + lc];
                af[mt][2] = sA[r * 36 + kk + 4 + lc];
                af[mt][3] = sA[(r + 8) * 36 + kk + 4 + lc];
            }
#pragma unroll
            for (int nt = 0; nt < 8; ++nt) {
                const int n = wn * 64 + nt * 8 + lr;
                uint32_t b0, b1;
                if (MODE == 0) {
                    b0 = sB[n * 36 + kk + lc];
                    b1 = sB[n * 36 + kk + 4 + lc];
                } else {
                    b0 = sB[(kk + lc) * 136 + n];
                    b1 = sB[(kk + 4 + lc) * 136 + n];
                }
                mma_tf32(acc[0][nt], af[0], b0, b1);
                mma_tf32(acc[1][nt], af[1], b0, b1);
            }
        }
    };

    loadA(0); loadB(0);
    stsAB(0);
    __syncthreads();
    for (int kt = 0; kt < nK; ++kt) {
        const int s = kt & 1;
        if (kt + 1 < nK) { loadA(kt + 1); loadB(kt + 1); }
        compute(s);
        if (kt + 1 < nK) {
            stsAB(s ^ 1);
            __syncthreads();
        }
    }

    const int lr = ln >> 2;
    const int lc = ln & 3;
#pragma unroll
    for (int mt = 0; mt < 2; ++mt) {
        const int lrow0 = wm * 32 + mt * 16 + lr;
#pragma unroll
        for (int half = 0; half < 2; ++half) {
            const int lrow = lrow0 + half * 8;
            float* dst = nullptr;
            bool valid = true;
            if (MODE == 0) {
                dst = C + (size_t)(m0 + lrow) * ldc;
            } else if (MODE == 1) {
                const int p = seg0 + m0 + lrow;
                valid = (p < seg1);
                dst = C + (size_t)p * ldc;
            } else {
                const int tk = tok[lrow];
                valid = (tk >= 0);
                dst = C + (size_t)(valid ? tk : 0) * ldc;
            }
            if (!valid) continue;
#pragma unroll
            for (int nt = 0; nt < 8; ++nt) {
                const int cc = n0 + wn * 64 + nt * 8 + lc * 2;
                float2 v;
                v.x = acc[mt][nt][half * 2 + 0] + biasp[cc];
                v.y = acc[mt][nt][half * 2 + 1] + biasp[cc + 1];
                if (MODE == 1) { v.x = fmaxf(v.x, 0.f); v.y = fmaxf(v.y, 0.f); }
                *reinterpret_cast<float2*>(dst + cc) = v;
            }
        }
    }
}

// ================= tensor-core flash attention (tf32 mma + FMA-pipe exp2) =================
// grid: (NS/128, NB*NH) ; 256 threads = 8 warps ; warp w owns q-rows [16w, 16w+16).
// SMEM: sQ[128][68] | sKP[128][68] (K rows 0..63, then P rows 0..127) | sV[64][72]
constexpr int FA_SQ  = 0;
constexpr int FA_SKP = 8704;
constexpr int FA_SV  = 17408;
constexpr int FA_SMEM_FLOATS = 22016;     // 88064 bytes

__global__ void __launch_bounds__(256, 2) flash_attn_tc(
    const float* __restrict__ qkv, float* __restrict__ O)
{
    extern __shared__ float sm[];
    float* sQ  = sm + FA_SQ;
    float* sKP = sm + FA_SKP;
    float* sV  = sm + FA_SV;

    const int tid = threadIdx.x;
    const int wid = tid >> 5;
    const int ln  = tid & 31;
    const int lr  = ln >> 2;
    const int lc  = ln & 3;
    const int b   = blockIdx.y >> 4;
    const int h   = blockIdx.y & 15;
    const int q0  = blockIdx.x * 128;
    const int wq  = wid * 16;
    const float qscale = 0.18033688011112042f;   // log2(e) / sqrt(64)

    // ---- stage Q (scaled into log2 domain, tf32 RN) ----
    {
        const float* qbase = qkv + ((size_t)(b * NS) + q0) * 3072 + h * 64;
#pragma unroll
        for (int it = 0; it < 8; ++it) {
            const int idx = tid + it * 256;
            const int row = idx >> 4;
            const int c4  = (idx & 15) * 4;
            float4 v = *reinterpret_cast<const float4*>(qbase + (size_t)row * 3072 + c4);
            uint4 u;
            u.x = tf32r(v.x * qscale); u.y = tf32r(v.y * qscale);
            u.z = tf32r(v.z * qscale); u.w = tf32r(v.w * qscale);
            *reinterpret_cast<uint4*>(sQ + row * 68 + c4) = u;
        }
    }

    float mr0 = -1e30f, mr1 = -1e30f;
    float l0 = 0.f, l1 = 0.f;
    float o[8][4];
#pragma unroll
    for (int jd = 0; jd < 8; ++jd)
#pragma unroll
        for (int r = 0; r < 4; ++r) o[jd][r] = 0.f;

    const uint32_t* uQ = reinterpret_cast<const uint32_t*>(sQ);
    uint32_t* uP = reinterpret_cast<uint32_t*>(sKP);
    const uint32_t* uV = reinterpret_cast<const uint32_t*>(sV);

    for (int kb = 0; kb < 16; ++kb) {
        // ---- stage K (rows 0..63 of sKP) and V, tf32 RN ----
        {
            const float* kbase = qkv + ((size_t)(b * NS) + kb * 64) * 3072 + 1024 + h * 64;
#pragma unroll
            for (int it = 0; it < 4; ++it) {
                const int idx = tid + it * 256;
                const int row = idx >> 4;
                const int c4  = (idx & 15) * 4;
                float4 kv = *reinterpret_cast<const float4*>(kbase + (size_t)row * 3072 + c4);
                float4 vv = *reinterpret_cast<const float4*>(kbase + (size_t)row * 3072 + 1024 + c4);
                uint4 uk, uvv;
                uk.x = tf32r(kv.x); uk.y = tf32r(kv.y); uk.z = tf32r(kv.z); uk.w = tf32r(kv.w);
                uvv.x = tf32r(vv.x); uvv.y = tf32r(vv.y); uvv.z = tf32r(vv.z); uvv.w = tf32r(vv.w);
                *reinterpret_cast<uint4*>(sKP + row * 68 + c4) = uk;
                *reinterpret_cast<uint4*>(sV + row * 72 + c4) = uvv;
            }
        }
        __syncthreads();

        // ---- S = Q @ K^T (log2 domain) ----
        float s[8][4];
#pragma unroll
        for (int jn = 0; jn < 8; ++jn)
#pragma unroll
            for (int r = 0; r < 4; ++r) s[jn][r] = 0.f;
#pragma unroll
        for (int kk = 0; kk < 8; ++kk) {
            uint32_t a[4];
            a[0] = uQ[(wq + lr) * 68 + kk * 8 + lc];
            a[1] = uQ[(wq + lr + 8) * 68 + kk * 8 + lc];
            a[2] = uQ[(wq + lr) * 68 + kk * 8 + lc + 4];
            a[3] = uQ[(wq + lr + 8) * 68 + kk * 8 + lc + 4];
#pragma unroll
            for (int jn = 0; jn < 8; ++jn) {
                const uint32_t b0 = uP[(jn * 8 + lr) * 68 + kk * 8 + lc];
                const uint32_t b1 = uP[(jn * 8 + lr) * 68 + kk * 8 + lc + 4];
                mma_tf32(s[jn], a, b0, b1);
            }
        }

        // ---- online softmax (all on FMA pipe) ----
        float mx0 = s[0][0], mx1 = s[0][2];
#pragma unroll
        for (int jn = 0; jn < 8; ++jn) {
            mx0 = fmaxf(mx0, fmaxf(s[jn][0], s[jn][1]));
            mx1 = fmaxf(mx1, fmaxf(s[jn][2], s[jn][3]));
        }
        mx0 = fmaxf(mx0, __shfl_xor_sync(0xffffffffu, mx0, 1));
        mx0 = fmaxf(mx0, __shfl_xor_sync(0xffffffffu, mx0, 2));
        mx1 = fmaxf(mx1, __shfl_xor_sync(0xffffffffu, mx1, 1));
        mx1 = fmaxf(mx1, __shfl_xor_sync(0xffffffffu, mx1, 2));
        const float mn0 = fmaxf(mr0, mx0);
        const float mn1 = fmaxf(mr1, mx1);
        const float c0 = exp2p(mr0 - mn0);
        const float c1 = exp2p(mr1 - mn1);
        mr0 = mn0; mr1 = mn1;
        l0 *= c0; l1 *= c1;
#pragma unroll
        for (int jn = 0; jn < 8; ++jn) {
            s[jn][0] = exp2p(s[jn][0] - mr0);
            s[jn][1] = exp2p(s[jn][1] - mr0);
            s[jn][2] = exp2p(s[jn][2] - mr1);
            s[jn][3] = exp2p(s[jn][3] - mr1);
            l0 += s[jn][0] + s[jn][1];
            l1 += s[jn][2] + s[jn][3];
        }
#pragma unroll
        for (int jd = 0; jd < 8; ++jd) {
            o[jd][0] *= c0; o[jd][1] *= c0;
            o[jd][2] *= c1; o[jd][3] *= c1;
        }

        __syncthreads();   // all warps done reading K before P overwrites it

        // ---- write P (tf32 RN) into sKP; each warp writes only its own rows ----
#pragma unroll
        for (int jn = 0; jn < 8; ++jn) {
            uint2 w0, w1;
            w0.x = tf32r(s[jn][0]); w0.y = tf32r(s[jn][1]);
            w1.x = tf32r(s[jn][2]); w1.y = tf32r(s[jn][3]);
            *reinterpret_cast<uint2*>(&uP[(wq + lr) * 68 + jn * 8 + 2 * lc]) = w0;
            *reinterpret_cast<uint2*>(&uP[(wq + lr + 8) * 68 + jn * 8 + 2 * lc]) = w1;
        }
        __syncwarp();

        // ---- O += P @ V ----
#pragma unroll
        for (int kk = 0; kk < 8; ++kk) {
            uint32_t a[4];
            a[0] = uP[(wq + lr) * 68 + kk * 8 + lc];
            a[1] = uP[(wq + lr + 8) * 68 + kk * 8 + lc];
            a[2] = uP[(wq + lr) * 68 + kk * 8 + lc + 4];
            a[3] = uP[(wq + lr + 8) * 68 + kk * 8 + lc + 4];
#pragma unroll
            for (int jd = 0; jd < 8; ++jd) {
                const uint32_t b0 = uV[(kk * 8 + lc) * 72 + jd * 8 + lr];
                const uint32_t b1 = uV[(kk * 8 + lc + 4) * 72 + jd * 8 + lr];
                mma_tf32(o[jd], a, b0, b1);
            }
        }
        __syncthreads();   // done reading P & V before next staging
    }

    // ---- finalize ----
    l0 += __shfl_xor_sync(0xffffffffu, l0, 1);
    l0 += __shfl_xor_sync(0xffffffffu, l0, 2);
    l1 += __shfl_xor_sync(0xffffffffu, l1, 1);
    l1 += __shfl_xor_sync(0xffffffffu, l1, 2);
    const float i0 = 1.f / l0;
    const float i1 = 1.f / l1;
    float* orow0 = O + ((size_t)(b * NS) + q0 + wq + lr) * ND + h * 64;
    float* orow1 = orow0 + (size_t)8 * ND;
#pragma unroll
    for (int jd = 0; jd < 8; ++jd) {
        float2 v0, v1;
        v0.x = o[jd][0] * i0; v0.y = o[jd][1] * i0;
        v1.x = o[jd][2] * i1; v1.y = o[jd][3] * i1;
        *reinterpret_cast<float2*>(orow0 + jd * 8 + 2 * lc) = v0;
        *reinterpret_cast<float2*>(orow1 + jd * 8 + 2 * lc) = v1;
    }
}

// ---------------- residual add + LayerNorm ----------------
__global__ __launch_bounds__(256) void add_ln(
    const float* __restrict__ A, const float* __restrict__ R,
    const float* __restrict__ g, const float* __restrict__ bt,
    float* __restrict__ out)
{
    const int t = blockIdx.x;
    const int tid = threadIdx.x;
    __shared__ float red[8];

    const float4 a4 = *reinterpret_cast<const float4*>(A + (size_t)t * ND + tid * 4);
    const float4 r4 = *reinterpret_cast<const float4*>(R + (size_t)t * ND + tid * 4);
    float v[4] = {a4.x + r4.x, a4.y + r4.y, a4.z + r4.z, a4.w + r4.w};

    float sum = v[0] + v[1] + v[2] + v[3];
#pragma unroll
    for (int off = 16; off; off >>= 1) sum += __shfl_down_sync(0xffffffffu, sum, off);
    if ((tid & 31) == 0) red[tid >> 5] = sum;
    __syncthreads();
    if (tid < 8) {
        float s = red[tid];
#pragma unroll
        for (int off = 4; off; off >>= 1) s += __shfl_down_sync(0xffu, s, off);
        if (tid == 0) red[0] = s;
    }
    __syncthreads();
    const float mu = red[0] * (1.f / ND);
    __syncthreads();

    float vs = 0.f;
#pragma unroll
    for (int i = 0; i < 4; ++i) { float d = v[i] - mu; vs += d * d; }
#pragma unroll
    for (int off = 16; off; off >>= 1) vs += __shfl_down_sync(0xffffffffu, vs, off);
    if ((tid & 31) == 0) red[tid >> 5] = vs;
    __syncthreads();
    if (tid < 8) {
        float s = red[tid];
#pragma unroll
        for (int off = 4; off; off >>= 1) s += __shfl_down_sync(0xffu, s, off);
        if (tid == 0) red[0] = s;
    }
    __syncthreads();
    const float rstd = rsqrtf(red[0] * (1.f / ND) + EPS);

    float4 o4;
    const int d0 = tid * 4;
    o4.x = (v[0] - mu) * rstd * g[d0]     + bt[d0];
    o4.y = (v[1] - mu) * rstd * g[d0 + 1] + bt[d0 + 1];
    o4.z = (v[2] - mu) * rstd * g[d0 + 2] + bt[d0 + 2];
    o4.w = (v[3] - mu) * rstd * g[d0 + 3] + bt[d0 + 3];
    *reinterpret_cast<float4*>(out + (size_t)t * ND + d0) = o4;
}

// ---------------- routing ----------------
__global__ void route_init() {
    if (threadIdx.x < NE) g_cnt[threadIdx.x] = 0;
}

__global__ __launch_bounds__(256) void gate_kernel(
    const float* __restrict__ X, const float* __restrict__ gw,
    const float* __restrict__ gb)
{
    const int warp = threadIdx.x >> 5;
    const int lane = threadIdx.x & 31;
    const int t = blockIdx.x * 8 + warp;
    const float* xp = X + (size_t)t * ND;
    float acc[NE];
#pragma unroll
    for (int e = 0; e < NE; ++e) acc[e] = 0.f;
    for (int d = lane; d < ND; d += 32) {
        const float xv = xp[d];
#pragma unroll
        for (int e = 0; e < NE; ++e) acc[e] = fmaf(xv, gw[e * ND + d], acc[e]);
    }
#pragma unroll
    for (int e = 0; e < NE; ++e)
#pragma unroll
        for (int off = 16; off; off >>= 1)
            acc[e] += __shfl_down_sync(0xffffffffu, acc[e], off);
    if (lane == 0) {
        int best = 0; float bv = acc[0] + gb[0];
#pragma unroll
        for (int e = 1; e < NE; ++e) {
            float v = acc[e] + gb[e];
            if (v > bv) { bv = v; best = e; }
        }
        g_idx[t] = best;
        atomicAdd(&g_cnt[best], 1);
    }
}

__global__ void route_scan() {
    g_off[0] = 0;
    for (int e = 0; e < NE; ++e) {
        g_off[e + 1] = g_off[e] + g_cnt[e];
        g_pos[e] = g_off[e];
    }
}

__global__ __launch_bounds__(256) void route_scatter() {
    const int t = blockIdx.x * 256 + threadIdx.x;
    if (t < NT) {
        const int e = g_idx[t];
        const int p = atomicAdd(&g_pos[e], 1);
        g_order[p] = t;
    }
}

// ---------------- launcher ----------------
extern "C" void kernel_launch(void* const* d_in, const int* in_sizes, int n_in,
                              void* d_out, int out_size)
{
    const float* x         = (const float*)d_in[0];
    const float* in_proj_w = (const float*)d_in[1];
    const float* in_proj_b = (const float*)d_in[2];
    const float* out_w     = (const float*)d_in[3];
    const float* out_b     = (const float*)d_in[4];
    const float* gate_w    = (const float*)d_in[5];
    const float* gate_b    = (const float*)d_in[6];
    const float* W1        = (const float*)d_in[7];
    const float* b1        = (const float*)d_in[8];
    const float* W2        = (const float*)d_in[9];
    const float* b2        = (const float*)d_in[10];
    const float* ln1_g     = (const float*)d_in[11];
    const float* ln1_b     = (const float*)d_in[12];
    const float* ln2_g     = (const float*)d_in[13];
    const float* ln2_b     = (const float*)d_in[14];
    float* out = (float*)d_out;

    float* qkv;   cudaGetSymbolAddress((void**)&qkv,   g_qkv);
    float* attno; cudaGetSymbolAddress((void**)&attno, g_attno);
    float* tmp;   cudaGetSymbolAddress((void**)&tmp,   g_tmp);
    float* x1;    cudaGetSymbolAddress((void**)&x1,    g_x1);
    float* hbuf;  cudaGetSymbolAddress((void**)&hbuf,  g_h);

    const int smem = SMEM_FLOATS * 4;   // 73728 B
    cudaFuncSetAttribute(gemm_mma<0>, cudaFuncAttributeMaxDynamicSharedMemorySize, smem);
    cudaFuncSetAttribute(gemm_mma<1>, cudaFuncAttributeMaxDynamicSharedMemorySize, smem);
    cudaFuncSetAttribute(gemm_mma<2>, cudaFuncAttributeMaxDynamicSharedMemorySize, smem);
    const int fa_smem = FA_SMEM_FLOATS * 4;   // 88064 B
    cudaFuncSetAttribute(flash_attn_tc, cudaFuncAttributeMaxDynamicSharedMemorySize, fa_smem);

    // 1) QKV projection
    gemm_mma<0><<<dim3(NT / 128, 3 * ND / 128, 1), 256, smem>>>(
        x, ND, in_proj_w, ND, in_proj_b, qkv, 3 * ND, ND, 3 * ND);
    // 2) attention (tensor cores)
    flash_attn_tc<<<dim3(NS / 128, NB * NH), 256, fa_smem>>>(qkv, attno);
    // 3) output projection
    gemm_mma<0><<<dim3(NT / 128, ND / 128, 1), 256, smem>>>(
        attno, ND, out_w, ND, out_b, tmp, ND, ND, ND);
    // 4) residual + LN1
    add_ln<<<NT, 256>>>(tmp, x, ln1_g, ln1_b, x1);
    // 5) routing
    route_init<<<1, 32>>>();
    gate_kernel<<<NT / 8, 256>>>(x1, gate_w, gate_b);
    route_scan<<<1, 1>>>();
    route_scatter<<<NT / 256, 256>>>();
    // 6) MoE expert FFN
    gemm_mma<1><<<dim3(NT / 128, NF / 128, NE), 256, smem>>>(
        x1, ND, W1, NF, b1, hbuf, NF, ND, NF);
    gemm_mma<2><<<dim3(NT / 128, ND / 128, NE), 256, smem>>>(
        hbuf, NF, W2, ND, b2, tmp, ND, NF, ND);
    // 7) residual + LN2 -> output
    add_ln<<<NT, 256>>>(tmp, x1, ln2_g, ln2_b, out);

    (void)in_sizes; (void)n_in; (void)out_size;
}

// round 6
// speedup vs baseline: 3.1974x; 1.0353x over previous
#include <cuda_runtime.h>
#include <math.h>
#include <float.h>
#include <stdint.h>

// ---------------- problem constants ----------------
constexpr int NB  = 4;
constexpr int NS  = 1024;
constexpr int ND  = 1024;
constexpr int NH  = 16;
constexpr int NHD = 64;
constexpr int NE  = 8;
constexpr int NF  = 4096;
constexpr int NT  = NB * NS;            // 4096 tokens
constexpr float EPS = 1e-5f;

// ---------------- scratch (device globals; no runtime alloc) ----------------
__device__ float g_qkv[(size_t)NT * 3 * ND];
__device__ float g_attno[(size_t)NT * ND];
__device__ float g_tmp[(size_t)NT * ND];
__device__ float g_x1[(size_t)NT * ND];
__device__ float g_h[(size_t)(NT + 128) * NF];
__device__ int   g_idx[NT];
__device__ int   g_order[NT];
__device__ int   g_cnt[NE];
__device__ int   g_off[NE + 1];
__device__ int   g_pos[NE];

// ---------------- tf32 helpers ----------------
__device__ __forceinline__ uint32_t tf32r(float x) {
    uint32_t u; asm("cvt.rna.tf32.f32 %0, %1;" : "=r"(u) : "f"(x)); return u;
}
__device__ __forceinline__ void mma_tf32(float c[4], const uint32_t a[4],
                                         uint32_t b0, uint32_t b1) {
    asm volatile(
        "mma.sync.aligned.m16n8k8.row.col.f32.tf32.tf32.f32 "
        "{%0,%1,%2,%3}, {%4,%5,%6,%7}, {%8,%9}, {%0,%1,%2,%3};"
        : "+f"(c[0]), "+f"(c[1]), "+f"(c[2]), "+f"(c[3])
        : "r"(a[0]), "r"(a[1]), "r"(a[2]), "r"(a[3]), "r"(b0), "r"(b1));
}

// fast 2^y for y <= 0, on the FMA pipe (no MUFU). |rel err| ~3e-6.
__device__ __forceinline__ float exp2p(float y) {
    y = fmaxf(y, -80.f);
    const int ni = __float2int_rn(y);
    const float f = y - (float)ni;
    float p = 0.0013333558146428443f;
    p = fmaf(p, f, 0.009618129107628477f);
    p = fmaf(p, f, 0.05550410866482158f);
    p = fmaf(p, f, 0.2402265069591007f);
    p = fmaf(p, f, 0.6931471805599453f);
    p = fmaf(p, f, 1.0f);
    return __uint_as_float(__float_as_uint(p) + ((uint32_t)ni << 23));
}

// ---------------- SMEM layout constants (floats) ----------------
constexpr int A_STG = 4608;                          // [128][36]
constexpr int B_OFF = 9216;
constexpr int B_STG = 4608;                          // [128][36] or [32][136]
constexpr int SMEM_FLOATS = B_OFF + 2 * B_STG;       // 18432 floats = 73728 B

// ================= tf32 tensor-core GEMM =================
// C[M,N] = A[M,K] * B^T + bias.
// MODE 0: B is [N,K] row-major (k-contiguous). Plain rows.
// MODE 1: MoE FFN1 — A gathered via g_order, B is [K,N] (n-contig), ReLU,
//         store rows p PRE-ROUNDED to tf32 (consumed by MODE 2).
// MODE 2: MoE FFN2 — A direct rows of g_h (already tf32-rounded), B is [K,N],
//         scatter store via tok.
template<int MODE>
__global__ void __launch_bounds__(256, 2) gemm_mma(
    const float* __restrict__ A, int lda,
    const float* __restrict__ B, int ldb,
    const float* __restrict__ bias,
    float* __restrict__ C, int ldc,
    int K, int Nglob)
{
    extern __shared__ float smf[];
    __shared__ int tok[128];

    const int tid = threadIdx.x;
    const int wid = tid >> 5;
    const int ln  = tid & 31;
    const int wm  = wid >> 1;
    const int wn  = wid & 1;
    const int m0 = blockIdx.x * 128;
    const int n0 = blockIdx.y * 128;

    int seg0 = 0, seg1 = 1 << 30;
    const float* Bp = B;
    const float* biasp = bias;
    if (MODE != 0) {
        const int e = blockIdx.z;
        seg0 = g_off[e]; seg1 = g_off[e + 1];
        if (seg0 + m0 >= seg1) return;
        Bp    = B + (size_t)e * K * Nglob;
        biasp = bias + (size_t)e * Nglob;
        if (tid < 128) {
            const int p = seg0 + m0 + tid;
            tok[tid] = (p < seg1) ? g_order[p] : -1;
        }
        __syncthreads();
    }

    float acc[2][8][4];
#pragma unroll
    for (int mt = 0; mt < 2; ++mt)
#pragma unroll
        for (int nt = 0; nt < 8; ++nt)
#pragma unroll
            for (int r = 0; r < 4; ++r) acc[mt][nt][r] = 0.f;

    float4 pa[4];
    float4 pb4[4];
    float  pbs[16];

    const int nK = K >> 5;

    auto loadA = [&](int kt) {
        const int k0 = kt << 5;
#pragma unroll
        for (int it = 0; it < 4; ++it) {
            const int idx = tid + it * 256;
            const int row = idx >> 3;
            const int kq  = (idx & 7) * 4;
            if (MODE == 1) {
                const int tk = tok[row];
                pa[it] = (tk >= 0)
                    ? *reinterpret_cast<const float4*>(A + (size_t)tk * lda + k0 + kq)
                    : make_float4(0.f, 0.f, 0.f, 0.f);
            } else if (MODE == 2) {
                pa[it] = *reinterpret_cast<const float4*>(A + (size_t)(seg0 + m0 + row) * lda + k0 + kq);
            } else {
                pa[it] = *reinterpret_cast<const float4*>(A + (size_t)(m0 + row) * lda + k0 + kq);
            }
        }
    };
    auto loadB = [&](int kt) {
        const int k0 = kt << 5;
        if (MODE == 0) {
#pragma unroll
            for (int it = 0; it < 4; ++it) {
                const int idx = tid + it * 256;
                const int row = idx >> 3;
                const int kq  = (idx & 7) * 4;
                pb4[it] = *reinterpret_cast<const float4*>(Bp + (size_t)(n0 + row) * ldb + k0 + kq);
            }
        } else {
#pragma unroll
            for (int it = 0; it < 16; ++it) {
                const int flat = tid + it * 256;
                const int k = flat >> 7;
                const int n = flat & 127;
                pbs[it] = Bp[(size_t)(k0 + k) * ldb + n0 + n];
            }
        }
    };
    auto stsAB = [&](int s) {
        float* sA = smf + s * A_STG;
        float* sB = smf + B_OFF + s * B_STG;
#pragma unroll
        for (int it = 0; it < 4; ++it) {
            const int idx = tid + it * 256;
            const int row = idx >> 3;
            const int kq  = (idx & 7) * 4;
            uint4 u;
            if (MODE == 2) {
                // g_h already tf32-RN rounded by MODE 1 epilogue
                u = *reinterpret_cast<const uint4*>(&pa[it]);
            } else {
                u.x = tf32r(pa[it].x); u.y = tf32r(pa[it].y);
                u.z = tf32r(pa[it].z); u.w = tf32r(pa[it].w);
            }
            *reinterpret_cast<uint4*>(sA + row * 36 + kq) = u;
        }
        if (MODE == 0) {
#pragma unroll
            for (int it = 0; it < 4; ++it) {
                const int idx = tid + it * 256;
                const int row = idx >> 3;
                const int kq  = (idx & 7) * 4;
                uint4 u;
                u.x = tf32r(pb4[it].x); u.y = tf32r(pb4[it].y);
                u.z = tf32r(pb4[it].z); u.w = tf32r(pb4[it].w);
                *reinterpret_cast<uint4*>(sB + row * 36 + kq) = u;
            }
        } else {
#pragma unroll
            for (int it = 0; it < 16; ++it) {
                const int flat = tid + it * 256;
                const int k = flat >> 7;
                const int n = flat & 127;
                reinterpret_cast<uint32_t*>(sB)[k * 136 + n] = tf32r(pbs[it]);
            }
        }
    };
    auto compute = [&](int s) {
        const uint32_t* sA = reinterpret_cast<const uint32_t*>(smf + s * A_STG);
        const uint32_t* sB = reinterpret_cast<const uint32_t*>(smf + B_OFF + s * B_STG);
        const int lr = ln >> 2;
        const int lc = ln & 3;
#pragma unroll
        for (int ks = 0; ks < 4; ++ks) {
            const int kk = ks * 8;
            uint32_t af[2][4];
#pragma unroll
            for (int mt = 0; mt < 2; ++mt) {
                const int r = wm * 32 + mt * 16 + lr;
                af[mt][0] = sA[r * 36 + kk + lc];
                af[mt][1] = sA[(r + 8) * 36 + kk + lc];
                af[mt][2] = sA[r * 36 + kk + 4 + lc];
                af[mt][3] = sA[(r + 8) * 36 + kk + 4 + lc];
            }
#pragma unroll
            for (int nt = 0; nt < 8; ++nt) {
                const int n = wn * 64 + nt * 8 + lr;
                uint32_t b0, b1;
                if (MODE == 0) {
                    b0 = sB[n * 36 + kk + lc];
                    b1 = sB[n * 36 + kk + 4 + lc];
                } else {
                    b0 = sB[(kk + lc) * 136 + n];
                    b1 = sB[(kk + 4 + lc) * 136 + n];
                }
                mma_tf32(acc[0][nt], af[0], b0, b1);
                mma_tf32(acc[1][nt], af[1], b0, b1);
            }
        }
    };

    loadA(0); loadB(0);
    stsAB(0);
    __syncthreads();
    for (int kt = 0; kt < nK; ++kt) {
        const int s = kt & 1;
        if (kt + 1 < nK) { loadA(kt + 1); loadB(kt + 1); }
        compute(s);
        if (kt + 1 < nK) {
            stsAB(s ^ 1);
            __syncthreads();
        }
    }

    const int lr = ln >> 2;
    const int lc = ln & 3;
#pragma unroll
    for (int mt = 0; mt < 2; ++mt) {
        const int lrow0 = wm * 32 + mt * 16 + lr;
#pragma unroll
        for (int half = 0; half < 2; ++half) {
            const int lrow = lrow0 + half * 8;
            float* dst = nullptr;
            bool valid = true;
            if (MODE == 0) {
                dst = C + (size_t)(m0 + lrow) * ldc;
            } else if (MODE == 1) {
                const int p = seg0 + m0 + lrow;
                valid = (p < seg1);
                dst = C + (size_t)p * ldc;
            } else {
                const int tk = tok[lrow];
                valid = (tk >= 0);
                dst = C + (size_t)(valid ? tk : 0) * ldc;
            }
            if (!valid) continue;
#pragma unroll
            for (int nt = 0; nt < 8; ++nt) {
                const int cc = n0 + wn * 64 + nt * 8 + lc * 2;
                float2 v;
                v.x = acc[mt][nt][half * 2 + 0] + biasp[cc];
                v.y = acc[mt][nt][half * 2 + 1] + biasp[cc + 1];
                if (MODE == 1) {
                    // ReLU then pre-round to tf32-RN (identical numerics downstream;
                    // lets MODE 2 skip per-element cvt in its staging hot loop)
                    v.x = __uint_as_float(tf32r(fmaxf(v.x, 0.f)));
                    v.y = __uint_as_float(tf32r(fmaxf(v.y, 0.f)));
                }
                *reinterpret_cast<float2*>(dst + cc) = v;
            }
        }
    }
}

// ================= tensor-core flash attention (tf32 mma + FMA-pipe exp2) =================
// grid: (NS/128, NB*NH) ; 256 threads = 8 warps ; warp w owns q-rows [16w, 16w+16).
// SMEM: sQ[128][68] | sKP[128][68] (K rows 0..63, then P rows 0..127) | sV[64][72]
constexpr int FA_SQ  = 0;
constexpr int FA_SKP = 8704;
constexpr int FA_SV  = 17408;
constexpr int FA_SMEM_FLOATS = 22016;     // 88064 bytes

__global__ void __launch_bounds__(256, 2) flash_attn_tc(
    const float* __restrict__ qkv, float* __restrict__ O)
{
    extern __shared__ float sm[];
    float* sQ  = sm + FA_SQ;
    float* sKP = sm + FA_SKP;
    float* sV  = sm + FA_SV;

    const int tid = threadIdx.x;
    const int wid = tid >> 5;
    const int ln  = tid & 31;
    const int lr  = ln >> 2;
    const int lc  = ln & 3;
    const int b   = blockIdx.y >> 4;
    const int h   = blockIdx.y & 15;
    const int q0  = blockIdx.x * 128;
    const int wq  = wid * 16;
    const float qscale = 0.18033688011112042f;   // log2(e) / sqrt(64)

    {
        const float* qbase = qkv + ((size_t)(b * NS) + q0) * 3072 + h * 64;
#pragma unroll
        for (int it = 0; it < 8; ++it) {
            const int idx = tid + it * 256;
            const int row = idx >> 4;
            const int c4  = (idx & 15) * 4;
            float4 v = *reinterpret_cast<const float4*>(qbase + (size_t)row * 3072 + c4);
            uint4 u;
            u.x = tf32r(v.x * qscale); u.y = tf32r(v.y * qscale);
            u.z = tf32r(v.z * qscale); u.w = tf32r(v.w * qscale);
            *reinterpret_cast<uint4*>(sQ + row * 68 + c4) = u;
        }
    }

    float mr0 = -1e30f, mr1 = -1e30f;
    float l0 = 0.f, l1 = 0.f;
    float o[8][4];
#pragma unroll
    for (int jd = 0; jd < 8; ++jd)
#pragma unroll
        for (int r = 0; r < 4; ++r) o[jd][r] = 0.f;

    const uint32_t* uQ = reinterpret_cast<const uint32_t*>(sQ);
    uint32_t* uP = reinterpret_cast<uint32_t*>(sKP);
    const uint32_t* uV = reinterpret_cast<const uint32_t*>(sV);

    for (int kb = 0; kb < 16; ++kb) {
        {
            const float* kbase = qkv + ((size_t)(b * NS) + kb * 64) * 3072 + 1024 + h * 64;
#pragma unroll
            for (int it = 0; it < 4; ++it) {
                const int idx = tid + it * 256;
                const int row = idx >> 4;
                const int c4  = (idx & 15) * 4;
                float4 kv = *reinterpret_cast<const float4*>(kbase + (size_t)row * 3072 + c4);
                float4 vv = *reinterpret_cast<const float4*>(kbase + (size_t)row * 3072 + 1024 + c4);
                uint4 uk, uvv;
                uk.x = tf32r(kv.x); uk.y = tf32r(kv.y); uk.z = tf32r(kv.z); uk.w = tf32r(kv.w);
                uvv.x = tf32r(vv.x); uvv.y = tf32r(vv.y); uvv.z = tf32r(vv.z); uvv.w = tf32r(vv.w);
                *reinterpret_cast<uint4*>(sKP + row * 68 + c4) = uk;
                *reinterpret_cast<uint4*>(sV + row * 72 + c4) = uvv;
            }
        }
        __syncthreads();

        float s[8][4];
#pragma unroll
        for (int jn = 0; jn < 8; ++jn)
#pragma unroll
            for (int r = 0; r < 4; ++r) s[jn][r] = 0.f;
#pragma unroll
        for (int kk = 0; kk < 8; ++kk) {
            uint32_t a[4];
            a[0] = uQ[(wq + lr) * 68 + kk * 8 + lc];
            a[1] = uQ[(wq + lr + 8) * 68 + kk * 8 + lc];
            a[2] = uQ[(wq + lr) * 68 + kk * 8 + lc + 4];
            a[3] = uQ[(wq + lr + 8) * 68 + kk * 8 + lc + 4];
#pragma unroll
            for (int jn = 0; jn < 8; ++jn) {
                const uint32_t b0 = uP[(jn * 8 + lr) * 68 + kk * 8 + lc];
                const uint32_t b1 = uP[(jn * 8 + lr) * 68 + kk * 8 + lc + 4];
                mma_tf32(s[jn], a, b0, b1);
            }
        }

        float mx0 = s[0][0], mx1 = s[0][2];
#pragma unroll
        for (int jn = 0; jn < 8; ++jn) {
            mx0 = fmaxf(mx0, fmaxf(s[jn][0], s[jn][1]));
            mx1 = fmaxf(mx1, fmaxf(s[jn][2], s[jn][3]));
        }
        mx0 = fmaxf(mx0, __shfl_xor_sync(0xffffffffu, mx0, 1));
        mx0 = fmaxf(mx0, __shfl_xor_sync(0xffffffffu, mx0, 2));
        mx1 = fmaxf(mx1, __shfl_xor_sync(0xffffffffu, mx1, 1));
        mx1 = fmaxf(mx1, __shfl_xor_sync(0xffffffffu, mx1, 2));
        const float mn0 = fmaxf(mr0, mx0);
        const float mn1 = fmaxf(mr1, mx1);
        const float c0 = exp2p(mr0 - mn0);
        const float c1 = exp2p(mr1 - mn1);
        mr0 = mn0; mr1 = mn1;
        l0 *= c0; l1 *= c1;
#pragma unroll
        for (int jn = 0; jn < 8; ++jn) {
            s[jn][0] = exp2p(s[jn][0] - mr0);
            s[jn][1] = exp2p(s[jn][1] - mr0);
            s[jn][2] = exp2p(s[jn][2] - mr1);
            s[jn][3] = exp2p(s[jn][3] - mr1);
            l0 += s[jn][0] + s[jn][1];
            l1 += s[jn][2] + s[jn][3];
        }
#pragma unroll
        for (int jd = 0; jd < 8; ++jd) {
            o[jd][0] *= c0; o[jd][1] *= c0;
            o[jd][2] *= c1; o[jd][3] *= c1;
        }

        __syncthreads();

#pragma unroll
        for (int jn = 0; jn < 8; ++jn) {
            uint2 w0, w1;
            w0.x = tf32r(s[jn][0]); w0.y = tf32r(s[jn][1]);
            w1.x = tf32r(s[jn][2]); w1.y = tf32r(s[jn][3]);
            *reinterpret_cast<uint2*>(&uP[(wq + lr) * 68 + jn * 8 + 2 * lc]) = w0;
            *reinterpret_cast<uint2*>(&uP[(wq + lr + 8) * 68 + jn * 8 + 2 * lc]) = w1;
        }
        __syncwarp();

#pragma unroll
        for (int kk = 0; kk < 8; ++kk) {
            uint32_t a[4];
            a[0] = uP[(wq + lr) * 68 + kk * 8 + lc];
            a[1] = uP[(wq + lr + 8) * 68 + kk * 8 + lc];
            a[2] = uP[(wq + lr) * 68 + kk * 8 + lc + 4];
            a[3] = uP[(wq + lr + 8) * 68 + kk * 8 + lc + 4];
#pragma unroll
            for (int jd = 0; jd < 8; ++jd) {
                const uint32_t b0 = uV[(kk * 8 + lc) * 72 + jd * 8 + lr];
                const uint32_t b1 = uV[(kk * 8 + lc + 4) * 72 + jd * 8 + lr];
                mma_tf32(o[jd], a, b0, b1);
            }
        }
        __syncthreads();
    }

    l0 += __shfl_xor_sync(0xffffffffu, l0, 1);
    l0 += __shfl_xor_sync(0xffffffffu, l0, 2);
    l1 += __shfl_xor_sync(0xffffffffu, l1, 1);
    l1 += __shfl_xor_sync(0xffffffffu, l1, 2);
    const float i0 = 1.f / l0;
    const float i1 = 1.f / l1;
    float* orow0 = O + ((size_t)(b * NS) + q0 + wq + lr) * ND + h * 64;
    float* orow1 = orow0 + (size_t)8 * ND;
#pragma unroll
    for (int jd = 0; jd < 8; ++jd) {
        float2 v0, v1;
        v0.x = o[jd][0] * i0; v0.y = o[jd][1] * i0;
        v1.x = o[jd][2] * i1; v1.y = o[jd][3] * i1;
        *reinterpret_cast<float2*>(orow0 + jd * 8 + 2 * lc) = v0;
        *reinterpret_cast<float2*>(orow1 + jd * 8 + 2 * lc) = v1;
    }
}

// ---------------- residual add + LayerNorm ----------------
__global__ __launch_bounds__(256) void add_ln(
    const float* __restrict__ A, const float* __restrict__ R,
    const float* __restrict__ g, const float* __restrict__ bt,
    float* __restrict__ out)
{
    const int t = blockIdx.x;
    const int tid = threadIdx.x;
    __shared__ float red[8];

    const float4 a4 = *reinterpret_cast<const float4*>(A + (size_t)t * ND + tid * 4);
    const float4 r4 = *reinterpret_cast<const float4*>(R + (size_t)t * ND + tid * 4);
    float v[4] = {a4.x + r4.x, a4.y + r4.y, a4.z + r4.z, a4.w + r4.w};

    float sum = v[0] + v[1] + v[2] + v[3];
#pragma unroll
    for (int off = 16; off; off >>= 1) sum += __shfl_down_sync(0xffffffffu, sum, off);
    if ((tid & 31) == 0) red[tid >> 5] = sum;
    __syncthreads();
    if (tid < 8) {
        float s = red[tid];
#pragma unroll
        for (int off = 4; off; off >>= 1) s += __shfl_down_sync(0xffu, s, off);
        if (tid == 0) red[0] = s;
    }
    __syncthreads();
    const float mu = red[0] * (1.f / ND);
    __syncthreads();

    float vs = 0.f;
#pragma unroll
    for (int i = 0; i < 4; ++i) { float d = v[i] - mu; vs += d * d; }
#pragma unroll
    for (int off = 16; off; off >>= 1) vs += __shfl_down_sync(0xffffffffu, vs, off);
    if ((tid & 31) == 0) red[tid >> 5] = vs;
    __syncthreads();
    if (tid < 8) {
        float s = red[tid];
#pragma unroll
        for (int off = 4; off; off >>= 1) s += __shfl_down_sync(0xffu, s, off);
        if (tid == 0) red[0] = s;
    }
    __syncthreads();
    const float rstd = rsqrtf(red[0] * (1.f / ND) + EPS);

    float4 o4;
    const int d0 = tid * 4;
    o4.x = (v[0] - mu) * rstd * g[d0]     + bt[d0];
    o4.y = (v[1] - mu) * rstd * g[d0 + 1] + bt[d0 + 1];
    o4.z = (v[2] - mu) * rstd * g[d0 + 2] + bt[d0 + 2];
    o4.w = (v[3] - mu) * rstd * g[d0 + 3] + bt[d0 + 3];
    *reinterpret_cast<float4*>(out + (size_t)t * ND + d0) = o4;
}

// ---------------- routing ----------------
__global__ void route_init() {
    if (threadIdx.x < NE) g_cnt[threadIdx.x] = 0;
}

__global__ __launch_bounds__(256) void gate_kernel(
    const float* __restrict__ X, const float* __restrict__ gw,
    const float* __restrict__ gb)
{
    const int warp = threadIdx.x >> 5;
    const int lane = threadIdx.x & 31;
    const int t = blockIdx.x * 8 + warp;
    const float* xp = X + (size_t)t * ND;
    float acc[NE];
#pragma unroll
    for (int e = 0; e < NE; ++e) acc[e] = 0.f;
    for (int d = lane; d < ND; d += 32) {
        const float xv = xp[d];
#pragma unroll
        for (int e = 0; e < NE; ++e) acc[e] = fmaf(xv, gw[e * ND + d], acc[e]);
    }
#pragma unroll
    for (int e = 0; e < NE; ++e)
#pragma unroll
        for (int off = 16; off; off >>= 1)
            acc[e] += __shfl_down_sync(0xffffffffu, acc[e], off);
    if (lane == 0) {
        int best = 0; float bv = acc[0] + gb[0];
#pragma unroll
        for (int e = 1; e < NE; ++e) {
            float v = acc[e] + gb[e];
            if (v > bv) { bv = v; best = e; }
        }
        g_idx[t] = best;
        atomicAdd(&g_cnt[best], 1);
    }
}

__global__ void route_scan() {
    g_off[0] = 0;
    for (int e = 0; e < NE; ++e) {
        g_off[e + 1] = g_off[e] + g_cnt[e];
        g_pos[e] = g_off[e];
    }
}

__global__ __launch_bounds__(256) void route_scatter() {
    const int t = blockIdx.x * 256 + threadIdx.x;
    if (t < NT) {
        const int e = g_idx[t];
        const int p = atomicAdd(&g_pos[e], 1);
        g_order[p] = t;
    }
}

// ---------------- launcher ----------------
extern "C" void kernel_launch(void* const* d_in, const int* in_sizes, int n_in,
                              void* d_out, int out_size)
{
    const float* x         = (const float*)d_in[0];
    const float* in_proj_w = (const float*)d_in[1];
    const float* in_proj_b = (const float*)d_in[2];
    const float* out_w     = (const float*)d_in[3];
    const float* out_b     = (const float*)d_in[4];
    const float* gate_w    = (const float*)d_in[5];
    const float* gate_b    = (const float*)d_in[6];
    const float* W1        = (const float*)d_in[7];
    const float* b1        = (const float*)d_in[8];
    const float* W2        = (const float*)d_in[9];
    const float* b2        = (const float*)d_in[10];
    const float* ln1_g     = (const float*)d_in[11];
    const float* ln1_b     = (const float*)d_in[12];
    const float* ln2_g     = (const float*)d_in[13];
    const float* ln2_b     = (const float*)d_in[14];
    float* out = (float*)d_out;

    float* qkv;   cudaGetSymbolAddress((void**)&qkv,   g_qkv);
    float* attno; cudaGetSymbolAddress((void**)&attno, g_attno);
    float* tmp;   cudaGetSymbolAddress((void**)&tmp,   g_tmp);
    float* x1;    cudaGetSymbolAddress((void**)&x1,    g_x1);
    float* hbuf;  cudaGetSymbolAddress((void**)&hbuf,  g_h);

    const int smem = SMEM_FLOATS * 4;   // 73728 B
    cudaFuncSetAttribute(gemm_mma<0>, cudaFuncAttributeMaxDynamicSharedMemorySize, smem);
    cudaFuncSetAttribute(gemm_mma<1>, cudaFuncAttributeMaxDynamicSharedMemorySize, smem);
    cudaFuncSetAttribute(gemm_mma<2>, cudaFuncAttributeMaxDynamicSharedMemorySize, smem);
    const int fa_smem = FA_SMEM_FLOATS * 4;   // 88064 B
    cudaFuncSetAttribute(flash_attn_tc, cudaFuncAttributeMaxDynamicSharedMemorySize, fa_smem);

    // 1) QKV projection
    gemm_mma<0><<<dim3(NT / 128, 3 * ND / 128, 1), 256, smem>>>(
        x, ND, in_proj_w, ND, in_proj_b, qkv, 3 * ND, ND, 3 * ND);
    // 2) attention (tensor cores)
    flash_attn_tc<<<dim3(NS / 128, NB * NH), 256, fa_smem>>>(qkv, attno);
    // 3) output projection
    gemm_mma<0><<<dim3(NT / 128, ND / 128, 1), 256, smem>>>(
        attno, ND, out_w, ND, out_b, tmp, ND, ND, ND);
    // 4) residual + LN1
    add_ln<<<NT, 256>>>(tmp, x, ln1_g, ln1_b, x1);
    // 5) routing
    route_init<<<1, 32>>>();
    gate_kernel<<<NT / 8, 256>>>(x1, gate_w, gate_b);
    route_scan<<<1, 1>>>();
    route_scatter<<<NT / 256, 256>>>();
    // 6) MoE expert FFN
    gemm_mma<1><<<dim3(NT / 128, NF / 128, NE), 256, smem>>>(
        x1, ND, W1, NF, b1, hbuf, NF, ND, NF);
    gemm_mma<2><<<dim3(NT / 128, ND / 128, NE), 256, smem>>>(
        hbuf, NF, W2, ND, b2, tmp, ND, NF, ND);
    // 7) residual + LN2 -> output
    add_ln<<<NT, 256>>>(tmp, x1, ln2_g, ln2_b, out);

    (void)in_sizes; (void)n_in; (void)out_size;
}

// round 7
// speedup vs baseline: 4.1348x; 1.2932x over previous
#include <cuda_runtime.h>
#include <cuda_fp16.h>
#include <math.h>
#include <float.h>
#include <stdint.h>

// ---------------- problem constants ----------------
constexpr int NB  = 4;
constexpr int NS  = 1024;
constexpr int ND  = 1024;
constexpr int NH  = 16;
constexpr int NHD = 64;
constexpr int NE  = 8;
constexpr int NF  = 4096;
constexpr int NT  = NB * NS;            // 4096 tokens
constexpr float EPS = 1e-5f;

// ---------------- scratch (device globals; no runtime alloc) ----------------
__device__ float  g_qkv[(size_t)NT * 3 * ND];
__device__ float  g_attno[(size_t)NT * ND];
__device__ float  g_tmp[(size_t)NT * ND];
__device__ float  g_x1[(size_t)NT * ND];
__device__ __half g_h[(size_t)(NT + 128) * NF];     // fp16 hidden (MODE1 out, MODE2 in)
__device__ int    g_idx[NT];
__device__ int    g_order[NT];
__device__ int    g_cnt[NE];
__device__ int    g_off[NE + 1];
__device__ int    g_pos[NE];

// ---------------- helpers ----------------
__device__ __forceinline__ uint32_t f2h2(float lo, float hi) {
    __half2 h = __floats2half2_rn(lo, hi);           // low=lo, high=hi
    return *reinterpret_cast<uint32_t*>(&h);
}
__device__ __forceinline__ uint32_t tf32r(float x) {
    uint32_t u; asm("cvt.rna.tf32.f32 %0, %1;" : "=r"(u) : "f"(x)); return u;
}
__device__ __forceinline__ void mma_tf32(float c[4], const uint32_t a[4],
                                         uint32_t b0, uint32_t b1) {
    asm volatile(
        "mma.sync.aligned.m16n8k8.row.col.f32.tf32.tf32.f32 "
        "{%0,%1,%2,%3}, {%4,%5,%6,%7}, {%8,%9}, {%0,%1,%2,%3};"
        : "+f"(c[0]), "+f"(c[1]), "+f"(c[2]), "+f"(c[3])
        : "r"(a[0]), "r"(a[1]), "r"(a[2]), "r"(a[3]), "r"(b0), "r"(b1));
}
__device__ __forceinline__ void mma_f16(float c[4], const uint32_t a[4],
                                        uint32_t b0, uint32_t b1) {
    asm volatile(
        "mma.sync.aligned.m16n8k16.row.col.f32.f16.f16.f32 "
        "{%0,%1,%2,%3}, {%4,%5,%6,%7}, {%8,%9}, {%0,%1,%2,%3};"
        : "+f"(c[0]), "+f"(c[1]), "+f"(c[2]), "+f"(c[3])
        : "r"(a[0]), "r"(a[1]), "r"(a[2]), "r"(a[3]), "r"(b0), "r"(b1));
}

// fast 2^y for y <= 0, on the FMA pipe (no MUFU). |rel err| ~3e-6.
__device__ __forceinline__ float exp2p(float y) {
    y = fmaxf(y, -80.f);
    const int ni = __float2int_rn(y);
    const float f = y - (float)ni;
    float p = 0.0013333558146428443f;
    p = fmaf(p, f, 0.009618129107628477f);
    p = fmaf(p, f, 0.05550410866482158f);
    p = fmaf(p, f, 0.2402265069591007f);
    p = fmaf(p, f, 0.6931471805599453f);
    p = fmaf(p, f, 1.0f);
    return __uint_as_float(__float_as_uint(p) + ((uint32_t)ni << 23));
}

// ---------------- GEMM SMEM layout (uint32 words) ----------------
// A tile: [128 rows][16 half2 words + pad4] stride 20 -> 2560 words/stage
// B tile: MODE0 [128][20]; MODE1/2 transposed [16 k2][128 n + pad8] stride 136 -> 2176
constexpr int A_STG = 2560;
constexpr int B_OFF = 5120;
constexpr int B_STG = 2560;
constexpr int GEMM_SMEM_BYTES = (B_OFF + 2 * B_STG) * 4;   // 40960 B

// ================= fp16 tensor-core GEMM (fp32 accum) =================
// C[M,N] = A[M,K] * B^T + bias.
// MODE 0: A fp32, B fp32 [N,K] k-contig, C fp32 plain rows.
// MODE 1: A fp32 gathered via g_order, B fp32 [K,N], ReLU, C = g_h (fp16) rows p.
// MODE 2: A = g_h (fp16) direct rows, B fp32 [K,N], C fp32 scatter via tok.
template<int MODE>
__global__ void __launch_bounds__(256, 2) gemm_mma(
    const void* __restrict__ Av, int lda,
    const float* __restrict__ B, int ldb,
    const float* __restrict__ bias,
    void* __restrict__ Cv, int ldc,
    int K, int Nglob)
{
    extern __shared__ uint32_t smw[];
    __shared__ int tok[128];

    const int tid = threadIdx.x;
    const int wid = tid >> 5;
    const int ln  = tid & 31;
    const int wm  = wid >> 1;
    const int wn  = wid & 1;
    const int m0 = blockIdx.x * 128;
    const int n0 = blockIdx.y * 128;

    int seg0 = 0, seg1 = 1 << 30;
    const float* Bp = B;
    const float* biasp = bias;
    if (MODE != 0) {
        const int e = blockIdx.z;
        seg0 = g_off[e]; seg1 = g_off[e + 1];
        if (seg0 + m0 >= seg1) return;
        Bp    = B + (size_t)e * K * Nglob;
        biasp = bias + (size_t)e * Nglob;
        if (tid < 128) {
            const int p = seg0 + m0 + tid;
            tok[tid] = (p < seg1) ? g_order[p] : -1;
        }
        __syncthreads();
    }

    const float* Af = (const float*)Av;
    const __half* Ah = (const __half*)Av;

    float acc[2][8][4];
#pragma unroll
    for (int mt = 0; mt < 2; ++mt)
#pragma unroll
        for (int nt = 0; nt < 8; ++nt)
#pragma unroll
            for (int r = 0; r < 4; ++r) acc[mt][nt][r] = 0.f;

    float4 pa[4];
    uint4  pau[2];
    float4 pb4[4];
    uint32_t pbh[8];

    const int nK = K >> 5;

    auto loadA = [&](int kt) {
        const int k0 = kt << 5;
        if (MODE == 2) {
#pragma unroll
            for (int it = 0; it < 2; ++it) {
                const int idx = tid + it * 256;       // 0..511
                const int row = idx >> 2;             // 0..127
                const int q   = idx & 3;              // 16B chunk
                pau[it] = *reinterpret_cast<const uint4*>(
                    Ah + (size_t)(seg0 + m0 + row) * lda + k0 + q * 8);
            }
        } else {
#pragma unroll
            for (int it = 0; it < 4; ++it) {
                const int idx = tid + it * 256;
                const int row = idx >> 3;
                const int kq  = (idx & 7) * 4;
                if (MODE == 1) {
                    const int tk = tok[row];
                    pa[it] = (tk >= 0)
                        ? *reinterpret_cast<const float4*>(Af + (size_t)tk * lda + k0 + kq)
                        : make_float4(0.f, 0.f, 0.f, 0.f);
                } else {
                    pa[it] = *reinterpret_cast<const float4*>(Af + (size_t)(m0 + row) * lda + k0 + kq);
                }
            }
        }
    };
    auto loadB = [&](int kt) {
        const int k0 = kt << 5;
        if (MODE == 0) {
#pragma unroll
            for (int it = 0; it < 4; ++it) {
                const int idx = tid + it * 256;
                const int row = idx >> 3;
                const int kq  = (idx & 7) * 4;
                pb4[it] = *reinterpret_cast<const float4*>(Bp + (size_t)(n0 + row) * ldb + k0 + kq);
            }
        } else {
#pragma unroll
            for (int it = 0; it < 8; ++it) {
                const int flat = tid + it * 256;      // 0..2047
                const int k2 = flat >> 7;             // 0..15
                const int n  = flat & 127;
                const float f0 = Bp[(size_t)(k0 + 2 * k2) * ldb + n0 + n];
                const float f1 = Bp[(size_t)(k0 + 2 * k2 + 1) * ldb + n0 + n];
                pbh[it] = f2h2(f0, f1);
            }
        }
    };
    auto stsAB = [&](int s) {
        uint32_t* sA = smw + s * A_STG;
        uint32_t* sB = smw + B_OFF + s * B_STG;
        if (MODE == 2) {
#pragma unroll
            for (int it = 0; it < 2; ++it) {
                const int idx = tid + it * 256;
                const int row = idx >> 2;
                const int q   = idx & 3;
                *reinterpret_cast<uint4*>(sA + row * 20 + q * 4) = pau[it];
            }
        } else {
#pragma unroll
            for (int it = 0; it < 4; ++it) {
                const int idx = tid + it * 256;
                const int row = idx >> 3;
                const int kq  = idx & 7;              // float4 slot -> 2 half2 words
                uint2 w;
                w.x = f2h2(pa[it].x, pa[it].y);
                w.y = f2h2(pa[it].z, pa[it].w);
                *reinterpret_cast<uint2*>(sA + row * 20 + kq * 2) = w;
            }
        }
        if (MODE == 0) {
#pragma unroll
            for (int it = 0; it < 4; ++it) {
                const int idx = tid + it * 256;
                const int row = idx >> 3;
                const int kq  = idx & 7;
                uint2 w;
                w.x = f2h2(pb4[it].x, pb4[it].y);
                w.y = f2h2(pb4[it].z, pb4[it].w);
                *reinterpret_cast<uint2*>(sB + row * 20 + kq * 2) = w;
            }
        } else {
#pragma unroll
            for (int it = 0; it < 8; ++it) {
                const int flat = tid + it * 256;
                const int k2 = flat >> 7;
                const int n  = flat & 127;
                sB[k2 * 136 + n] = pbh[it];
            }
        }
    };
    auto compute = [&](int s) {
        const uint32_t* sA = smw + s * A_STG;
        const uint32_t* sB = smw + B_OFF + s * B_STG;
        const int lr = ln >> 2;
        const int lc = ln & 3;
#pragma unroll
        for (int ks = 0; ks < 2; ++ks) {              // two k16 steps per k32 tile
            const int kk2 = ks * 8;                   // half2-word base
            uint32_t af[2][4];
#pragma unroll
            for (int mt = 0; mt < 2; ++mt) {
                const int r = wm * 32 + mt * 16 + lr;
                af[mt][0] = sA[r * 20 + kk2 + lc];
                af[mt][1] = sA[(r + 8) * 20 + kk2 + lc];
                af[mt][2] = sA[r * 20 + kk2 + 4 + lc];
                af[mt][3] = sA[(r + 8) * 20 + kk2 + 4 + lc];
            }
#pragma unroll
            for (int nt = 0; nt < 8; ++nt) {
                const int n = wn * 64 + nt * 8 + lr;
                uint32_t b0, b1;
                if (MODE == 0) {
                    b0 = sB[n * 20 + kk2 + lc];
                    b1 = sB[n * 20 + kk2 + 4 + lc];
                } else {
                    b0 = sB[(kk2 + lc) * 136 + n];
                    b1 = sB[(kk2 + lc + 4) * 136 + n];
                }
                mma_f16(acc[0][nt], af[0], b0, b1);
                mma_f16(acc[1][nt], af[1], b0, b1);
            }
        }
    };

    loadA(0); loadB(0);
    stsAB(0);
    __syncthreads();
    for (int kt = 0; kt < nK; ++kt) {
        const int s = kt & 1;
        if (kt + 1 < nK) { loadA(kt + 1); loadB(kt + 1); }
        compute(s);
        if (kt + 1 < nK) {
            stsAB(s ^ 1);
            __syncthreads();
        }
    }

    // ---- epilogue ----
    const int lr = ln >> 2;
    const int lc = ln & 3;
#pragma unroll
    for (int mt = 0; mt < 2; ++mt) {
        const int lrow0 = wm * 32 + mt * 16 + lr;
#pragma unroll
        for (int half = 0; half < 2; ++half) {
            const int lrow = lrow0 + half * 8;
            bool valid = true;
            size_t rowidx = 0;
            if (MODE == 0) {
                rowidx = (size_t)(m0 + lrow);
            } else if (MODE == 1) {
                const int p = seg0 + m0 + lrow;
                valid = (p < seg1);
                rowidx = (size_t)p;
            } else {
                const int tk = tok[lrow];
                valid = (tk >= 0);
                rowidx = (size_t)(valid ? tk : 0);
            }
            if (!valid) continue;
#pragma unroll
            for (int nt = 0; nt < 8; ++nt) {
                const int cc = n0 + wn * 64 + nt * 8 + lc * 2;
                float vx = acc[mt][nt][half * 2 + 0] + biasp[cc];
                float vy = acc[mt][nt][half * 2 + 1] + biasp[cc + 1];
                if (MODE == 1) {
                    vx = fmaxf(vx, 0.f); vy = fmaxf(vy, 0.f);
                    __half* dst = (__half*)Cv + rowidx * ldc + cc;
                    *reinterpret_cast<uint32_t*>(dst) = f2h2(vx, vy);
                } else {
                    float* dst = (float*)Cv + rowidx * ldc + cc;
                    float2 v; v.x = vx; v.y = vy;
                    *reinterpret_cast<float2*>(dst) = v;
                }
            }
        }
    }
}

// ================= tensor-core flash attention (tf32 mma + FMA-pipe exp2) =================
constexpr int FA_SQ  = 0;
constexpr int FA_SKP = 8704;
constexpr int FA_SV  = 17408;
constexpr int FA_SMEM_FLOATS = 22016;     // 88064 bytes

__global__ void __launch_bounds__(256, 2) flash_attn_tc(
    const float* __restrict__ qkv, float* __restrict__ O)
{
    extern __shared__ float sm[];
    float* sQ  = sm + FA_SQ;
    float* sKP = sm + FA_SKP;
    float* sV  = sm + FA_SV;

    const int tid = threadIdx.x;
    const int wid = tid >> 5;
    const int ln  = tid & 31;
    const int lr  = ln >> 2;
    const int lc  = ln & 3;
    const int b   = blockIdx.y >> 4;
    const int h   = blockIdx.y & 15;
    const int q0  = blockIdx.x * 128;
    const int wq  = wid * 16;
    const float qscale = 0.18033688011112042f;   // log2(e) / sqrt(64)

    {
        const float* qbase = qkv + ((size_t)(b * NS) + q0) * 3072 + h * 64;
#pragma unroll
        for (int it = 0; it < 8; ++it) {
            const int idx = tid + it * 256;
            const int row = idx >> 4;
            const int c4  = (idx & 15) * 4;
            float4 v = *reinterpret_cast<const float4*>(qbase + (size_t)row * 3072 + c4);
            uint4 u;
            u.x = tf32r(v.x * qscale); u.y = tf32r(v.y * qscale);
            u.z = tf32r(v.z * qscale); u.w = tf32r(v.w * qscale);
            *reinterpret_cast<uint4*>(sQ + row * 68 + c4) = u;
        }
    }

    float mr0 = -1e30f, mr1 = -1e30f;
    float l0 = 0.f, l1 = 0.f;
    float o[8][4];
#pragma unroll
    for (int jd = 0; jd < 8; ++jd)
#pragma unroll
        for (int r = 0; r < 4; ++r) o[jd][r] = 0.f;

    const uint32_t* uQ = reinterpret_cast<const uint32_t*>(sQ);
    uint32_t* uP = reinterpret_cast<uint32_t*>(sKP);
    const uint32_t* uV = reinterpret_cast<const uint32_t*>(sV);

    for (int kb = 0; kb < 16; ++kb) {
        {
            const float* kbase = qkv + ((size_t)(b * NS) + kb * 64) * 3072 + 1024 + h * 64;
#pragma unroll
            for (int it = 0; it < 4; ++it) {
                const int idx = tid + it * 256;
                const int row = idx >> 4;
                const int c4  = (idx & 15) * 4;
                float4 kv = *reinterpret_cast<const float4*>(kbase + (size_t)row * 3072 + c4);
                float4 vv = *reinterpret_cast<const float4*>(kbase + (size_t)row * 3072 + 1024 + c4);
                uint4 uk, uvv;
                uk.x = tf32r(kv.x); uk.y = tf32r(kv.y); uk.z = tf32r(kv.z); uk.w = tf32r(kv.w);
                uvv.x = tf32r(vv.x); uvv.y = tf32r(vv.y); uvv.z = tf32r(vv.z); uvv.w = tf32r(vv.w);
                *reinterpret_cast<uint4*>(sKP + row * 68 + c4) = uk;
                *reinterpret_cast<uint4*>(sV + row * 72 + c4) = uvv;
            }
        }
        __syncthreads();

        float s[8][4];
#pragma unroll
        for (int jn = 0; jn < 8; ++jn)
#pragma unroll
            for (int r = 0; r < 4; ++r) s[jn][r] = 0.f;
#pragma unroll
        for (int kk = 0; kk < 8; ++kk) {
            uint32_t a[4];
            a[0] = uQ[(wq + lr) * 68 + kk * 8 + lc];
            a[1] = uQ[(wq + lr + 8) * 68 + kk * 8 + lc];
            a[2] = uQ[(wq + lr) * 68 + kk * 8 + lc + 4];
            a[3] = uQ[(wq + lr + 8) * 68 + kk * 8 + lc + 4];
#pragma unroll
            for (int jn = 0; jn < 8; ++jn) {
                const uint32_t b0 = uP[(jn * 8 + lr) * 68 + kk * 8 + lc];
                const uint32_t b1 = uP[(jn * 8 + lr) * 68 + kk * 8 + lc + 4];
                mma_tf32(s[jn], a, b0, b1);
            }
        }

        float mx0 = s[0][0], mx1 = s[0][2];
#pragma unroll
        for (int jn = 0; jn < 8; ++jn) {
            mx0 = fmaxf(mx0, fmaxf(s[jn][0], s[jn][1]));
            mx1 = fmaxf(mx1, fmaxf(s[jn][2], s[jn][3]));
        }
        mx0 = fmaxf(mx0, __shfl_xor_sync(0xffffffffu, mx0, 1));
        mx0 = fmaxf(mx0, __shfl_xor_sync(0xffffffffu, mx0, 2));
        mx1 = fmaxf(mx1, __shfl_xor_sync(0xffffffffu, mx1, 1));
        mx1 = fmaxf(mx1, __shfl_xor_sync(0xffffffffu, mx1, 2));
        const float mn0 = fmaxf(mr0, mx0);
        const float mn1 = fmaxf(mr1, mx1);
        const float c0 = exp2p(mr0 - mn0);
        const float c1 = exp2p(mr1 - mn1);
        mr0 = mn0; mr1 = mn1;
        l0 *= c0; l1 *= c1;
#pragma unroll
        for (int jn = 0; jn < 8; ++jn) {
            s[jn][0] = exp2p(s[jn][0] - mr0);
            s[jn][1] = exp2p(s[jn][1] - mr0);
            s[jn][2] = exp2p(s[jn][2] - mr1);
            s[jn][3] = exp2p(s[jn][3] - mr1);
            l0 += s[jn][0] + s[jn][1];
            l1 += s[jn][2] + s[jn][3];
        }
#pragma unroll
        for (int jd = 0; jd < 8; ++jd) {
            o[jd][0] *= c0; o[jd][1] *= c0;
            o[jd][2] *= c1; o[jd][3] *= c1;
        }

        __syncthreads();

#pragma unroll
        for (int jn = 0; jn < 8; ++jn) {
            uint2 w0, w1;
            w0.x = tf32r(s[jn][0]); w0.y = tf32r(s[jn][1]);
            w1.x = tf32r(s[jn][2]); w1.y = tf32r(s[jn][3]);
            *reinterpret_cast<uint2*>(&uP[(wq + lr) * 68 + jn * 8 + 2 * lc]) = w0;
            *reinterpret_cast<uint2*>(&uP[(wq + lr + 8) * 68 + jn * 8 + 2 * lc]) = w1;
        }
        __syncwarp();

#pragma unroll
        for (int kk = 0; kk < 8; ++kk) {
            uint32_t a[4];
            a[0] = uP[(wq + lr) * 68 + kk * 8 + lc];
            a[1] = uP[(wq + lr + 8) * 68 + kk * 8 + lc];
            a[2] = uP[(wq + lr) * 68 + kk * 8 + lc + 4];
            a[3] = uP[(wq + lr + 8) * 68 + kk * 8 + lc + 4];
#pragma unroll
            for (int jd = 0; jd < 8; ++jd) {
                const uint32_t b0 = uV[(kk * 8 + lc) * 72 + jd * 8 + lr];
                const uint32_t b1 = uV[(kk * 8 + lc + 4) * 72 + jd * 8 + lr];
                mma_tf32(o[jd], a, b0, b1);
            }
        }
        __syncthreads();
    }

    l0 += __shfl_xor_sync(0xffffffffu, l0, 1);
    l0 += __shfl_xor_sync(0xffffffffu, l0, 2);
    l1 += __shfl_xor_sync(0xffffffffu, l1, 1);
    l1 += __shfl_xor_sync(0xffffffffu, l1, 2);
    const float i0 = 1.f / l0;
    const float i1 = 1.f / l1;
    float* orow0 = O + ((size_t)(b * NS) + q0 + wq + lr) * ND + h * 64;
    float* orow1 = orow0 + (size_t)8 * ND;
#pragma unroll
    for (int jd = 0; jd < 8; ++jd) {
        float2 v0, v1;
        v0.x = o[jd][0] * i0; v0.y = o[jd][1] * i0;
        v1.x = o[jd][2] * i1; v1.y = o[jd][3] * i1;
        *reinterpret_cast<float2*>(orow0 + jd * 8 + 2 * lc) = v0;
        *reinterpret_cast<float2*>(orow1 + jd * 8 + 2 * lc) = v1;
    }
}

// ---------------- residual add + LayerNorm ----------------
__global__ __launch_bounds__(256) void add_ln(
    const float* __restrict__ A, const float* __restrict__ R,
    const float* __restrict__ g, const float* __restrict__ bt,
    float* __restrict__ out)
{
    const int t = blockIdx.x;
    const int tid = threadIdx.x;
    __shared__ float red[8];

    const float4 a4 = *reinterpret_cast<const float4*>(A + (size_t)t * ND + tid * 4);
    const float4 r4 = *reinterpret_cast<const float4*>(R + (size_t)t * ND + tid * 4);
    float v[4] = {a4.x + r4.x, a4.y + r4.y, a4.z + r4.z, a4.w + r4.w};

    float sum = v[0] + v[1] + v[2] + v[3];
#pragma unroll
    for (int off = 16; off; off >>= 1) sum += __shfl_down_sync(0xffffffffu, sum, off);
    if ((tid & 31) == 0) red[tid >> 5] = sum;
    __syncthreads();
    if (tid < 8) {
        float s = red[tid];
#pragma unroll
        for (int off = 4; off; off >>= 1) s += __shfl_down_sync(0xffu, s, off);
        if (tid == 0) red[0] = s;
    }
    __syncthreads();
    const float mu = red[0] * (1.f / ND);
    __syncthreads();

    float vs = 0.f;
#pragma unroll
    for (int i = 0; i < 4; ++i) { float d = v[i] - mu; vs += d * d; }
#pragma unroll
    for (int off = 16; off; off >>= 1) vs += __shfl_down_sync(0xffffffffu, vs, off);
    if ((tid & 31) == 0) red[tid >> 5] = vs;
    __syncthreads();
    if (tid < 8) {
        float s = red[tid];
#pragma unroll
        for (int off = 4; off; off >>= 1) s += __shfl_down_sync(0xffu, s, off);
        if (tid == 0) red[0] = s;
    }
    __syncthreads();
    const float rstd = rsqrtf(red[0] * (1.f / ND) + EPS);

    float4 o4;
    const int d0 = tid * 4;
    o4.x = (v[0] - mu) * rstd * g[d0]     + bt[d0];
    o4.y = (v[1] - mu) * rstd * g[d0 + 1] + bt[d0 + 1];
    o4.z = (v[2] - mu) * rstd * g[d0 + 2] + bt[d0 + 2];
    o4.w = (v[3] - mu) * rstd * g[d0 + 3] + bt[d0 + 3];
    *reinterpret_cast<float4*>(out + (size_t)t * ND + d0) = o4;
}

// ---------------- routing ----------------
__global__ void route_init() {
    if (threadIdx.x < NE) g_cnt[threadIdx.x] = 0;
}

__global__ __launch_bounds__(256) void gate_kernel(
    const float* __restrict__ X, const float* __restrict__ gw,
    const float* __restrict__ gb)
{
    const int warp = threadIdx.x >> 5;
    const int lane = threadIdx.x & 31;
    const int t = blockIdx.x * 8 + warp;
    const float* xp = X + (size_t)t * ND;
    float acc[NE];
#pragma unroll
    for (int e = 0; e < NE; ++e) acc[e] = 0.f;
    for (int d = lane; d < ND; d += 32) {
        const float xv = xp[d];
#pragma unroll
        for (int e = 0; e < NE; ++e) acc[e] = fmaf(xv, gw[e * ND + d], acc[e]);
    }
#pragma unroll
    for (int e = 0; e < NE; ++e)
#pragma unroll
        for (int off = 16; off; off >>= 1)
            acc[e] += __shfl_down_sync(0xffffffffu, acc[e], off);
    if (lane == 0) {
        int best = 0; float bv = acc[0] + gb[0];
#pragma unroll
        for (int e = 1; e < NE; ++e) {
            float v = acc[e] + gb[e];
            if (v > bv) { bv = v; best = e; }
        }
        g_idx[t] = best;
        atomicAdd(&g_cnt[best], 1);
    }
}

__global__ void route_scan() {
    g_off[0] = 0;
    for (int e = 0; e < NE; ++e) {
        g_off[e + 1] = g_off[e] + g_cnt[e];
        g_pos[e] = g_off[e];
    }
}

__global__ __launch_bounds__(256) void route_scatter() {
    const int t = blockIdx.x * 256 + threadIdx.x;
    if (t < NT) {
        const int e = g_idx[t];
        const int p = atomicAdd(&g_pos[e], 1);
        g_order[p] = t;
    }
}

// ---------------- launcher ----------------
extern "C" void kernel_launch(void* const* d_in, const int* in_sizes, int n_in,
                              void* d_out, int out_size)
{
    const float* x         = (const float*)d_in[0];
    const float* in_proj_w = (const float*)d_in[1];
    const float* in_proj_b = (const float*)d_in[2];
    const float* out_w     = (const float*)d_in[3];
    const float* out_b     = (const float*)d_in[4];
    const float* gate_w    = (const float*)d_in[5];
    const float* gate_b    = (const float*)d_in[6];
    const float* W1        = (const float*)d_in[7];
    const float* b1        = (const float*)d_in[8];
    const float* W2        = (const float*)d_in[9];
    const float* b2        = (const float*)d_in[10];
    const float* ln1_g     = (const float*)d_in[11];
    const float* ln1_b     = (const float*)d_in[12];
    const float* ln2_g     = (const float*)d_in[13];
    const float* ln2_b     = (const float*)d_in[14];
    float* out = (float*)d_out;

    float*  qkv;   cudaGetSymbolAddress((void**)&qkv,   g_qkv);
    float*  attno; cudaGetSymbolAddress((void**)&attno, g_attno);
    float*  tmp;   cudaGetSymbolAddress((void**)&tmp,   g_tmp);
    float*  x1;    cudaGetSymbolAddress((void**)&x1,    g_x1);
    __half* hbuf;  cudaGetSymbolAddress((void**)&hbuf,  g_h);

    cudaFuncSetAttribute(gemm_mma<0>, cudaFuncAttributeMaxDynamicSharedMemorySize, GEMM_SMEM_BYTES);
    cudaFuncSetAttribute(gemm_mma<1>, cudaFuncAttributeMaxDynamicSharedMemorySize, GEMM_SMEM_BYTES);
    cudaFuncSetAttribute(gemm_mma<2>, cudaFuncAttributeMaxDynamicSharedMemorySize, GEMM_SMEM_BYTES);
    const int fa_smem = FA_SMEM_FLOATS * 4;   // 88064 B
    cudaFuncSetAttribute(flash_attn_tc, cudaFuncAttributeMaxDynamicSharedMemorySize, fa_smem);

    // 1) QKV projection
    gemm_mma<0><<<dim3(NT / 128, 3 * ND / 128, 1), 256, GEMM_SMEM_BYTES>>>(
        x, ND, in_proj_w, ND, in_proj_b, qkv, 3 * ND, ND, 3 * ND);
    // 2) attention (tensor cores)
    flash_attn_tc<<<dim3(NS / 128, NB * NH), 256, fa_smem>>>(qkv, attno);
    // 3) output projection
    gemm_mma<0><<<dim3(NT / 128, ND / 128, 1), 256, GEMM_SMEM_BYTES>>>(
        attno, ND, out_w, ND, out_b, tmp, ND, ND, ND);
    // 4) residual + LN1
    add_ln<<<NT, 256>>>(tmp, x, ln1_g, ln1_b, x1);
    // 5) routing
    route_init<<<1, 32>>>();
    gate_kernel<<<NT / 8, 256>>>(x1, gate_w, gate_b);
    route_scan<<<1, 1>>>();
    route_scatter<<<NT / 256, 256>>>();
    // 6) MoE expert FFN (fp16 hidden)
    gemm_mma<1><<<dim3(NT / 128, NF / 128, NE), 256, GEMM_SMEM_BYTES>>>(
        x1, ND, W1, NF, b1, hbuf, NF, ND, NF);
    gemm_mma<2><<<dim3(NT / 128, ND / 128, NE), 256, GEMM_SMEM_BYTES>>>(
        hbuf, NF, W2, ND, b2, tmp, ND, NF, ND);
    // 7) residual + LN2 -> output
    add_ln<<<NT, 256>>>(tmp, x1, ln2_g, ln2_b, out);

    (void)in_sizes; (void)n_in; (void)out_size;
}

// round 8
// speedup vs baseline: 5.2188x; 1.2622x over previous
#include <cuda_runtime.h>
#include <cuda_fp16.h>
#include <math.h>
#include <float.h>
#include <stdint.h>

// ---------------- problem constants ----------------
constexpr int NB  = 4;
constexpr int NS  = 1024;
constexpr int ND  = 1024;
constexpr int NH  = 16;
constexpr int NHD = 64;
constexpr int NE  = 8;
constexpr int NF  = 4096;
constexpr int NT  = NB * NS;            // 4096 tokens
constexpr float EPS = 1e-5f;

// ---------------- scratch (device globals; no runtime alloc) ----------------
__device__ __half g_x16[(size_t)NT * ND];
__device__ __half g_inwh[(size_t)3 * ND * ND];
__device__ __half g_outwh[(size_t)ND * ND];
__device__ __half g_w1t[(size_t)NE * NF * ND];      // [E][F][D] fp16 (transposed)
__device__ __half g_w2t[(size_t)NE * ND * NF];      // [E][D][F] fp16 (transposed)
__device__ __half g_qkvh[(size_t)NT * 3 * ND];
__device__ __half g_attnoh[(size_t)NT * ND];
__device__ __half g_x1h[(size_t)NT * ND];
__device__ __half g_h[(size_t)(NT + 128) * NF];     // fp16 hidden
__device__ float  g_tmp[(size_t)NT * ND];
__device__ float  g_x1[(size_t)NT * ND];
__device__ int    g_idx[NT];
__device__ int    g_order[NT];
__device__ int    g_cnt[NE];
__device__ int    g_off[NE + 1];
__device__ int    g_pos[NE];

// ---------------- helpers ----------------
__device__ __forceinline__ uint32_t f2h2(float lo, float hi) {
    __half2 h = __floats2half2_rn(lo, hi);
    return *reinterpret_cast<uint32_t*>(&h);
}
__device__ __forceinline__ uint32_t smem_u32(const void* p) {
    uint32_t a;
    asm("{ .reg .u64 t; cvta.to.shared.u64 t, %1; cvt.u32.u64 %0, t; }" : "=r"(a) : "l"(p));
    return a;
}
__device__ __forceinline__ void mma_f16(float c[4], const uint32_t a[4],
                                        uint32_t b0, uint32_t b1) {
    asm volatile(
        "mma.sync.aligned.m16n8k16.row.col.f32.f16.f16.f32 "
        "{%0,%1,%2,%3}, {%4,%5,%6,%7}, {%8,%9}, {%0,%1,%2,%3};"
        : "+f"(c[0]), "+f"(c[1]), "+f"(c[2]), "+f"(c[3])
        : "r"(a[0]), "r"(a[1]), "r"(a[2]), "r"(a[3]), "r"(b0), "r"(b1));
}
__device__ __forceinline__ void cpa16(uint32_t saddr, const void* gptr, bool valid) {
    const int sz = valid ? 16 : 0;
    asm volatile("cp.async.cg.shared.global [%0], [%1], 16, %2;"
                 :: "r"(saddr), "l"(gptr), "r"(sz));
}
#define CP_COMMIT()  asm volatile("cp.async.commit_group;")
#define CP_WAIT1()   asm volatile("cp.async.wait_group 1;")

// fast 2^y for y <= 0, FMA pipe only. |rel err| ~3e-6.
__device__ __forceinline__ float exp2p(float y) {
    y = fmaxf(y, -80.f);
    const int ni = __float2int_rn(y);
    const float f = y - (float)ni;
    float p = 0.0013333558146428443f;
    p = fmaf(p, f, 0.009618129107628477f);
    p = fmaf(p, f, 0.05550410866482158f);
    p = fmaf(p, f, 0.2402265069591007f);
    p = fmaf(p, f, 0.6931471805599453f);
    p = fmaf(p, f, 1.0f);
    return __uint_as_float(__float_as_uint(p) + ((uint32_t)ni << 23));
}

// ---------------- conversion kernels ----------------
__global__ __launch_bounds__(256) void cvt_f32_f16(
    const float* __restrict__ src, __half* __restrict__ dst, int n4)
{
    const int i = blockIdx.x * 256 + threadIdx.x;
    if (i < n4) {
        float4 v = reinterpret_cast<const float4*>(src)[i];
        uint2 u;
        u.x = f2h2(v.x, v.y);
        u.y = f2h2(v.z, v.w);
        reinterpret_cast<uint2*>(dst)[i] = u;
    }
}

// transpose + convert: src [Kd][Nd] fp32 -> dst [Nd][Kd] fp16, per expert (blockIdx.z)
__global__ __launch_bounds__(256) void transpose_cvt(
    const float* __restrict__ src, __half* __restrict__ dst, int Kd, int Nd)
{
    __shared__ float t[32][33];
    const size_t eofs = (size_t)blockIdx.z * Kd * Nd;
    const int n0 = blockIdx.x * 32;
    const int k0 = blockIdx.y * 32;
    const int tx = threadIdx.x & 31;
    const int ty = threadIdx.x >> 5;   // 0..7
#pragma unroll
    for (int i = 0; i < 4; ++i)
        t[ty + i * 8][tx] = src[eofs + (size_t)(k0 + ty + i * 8) * Nd + n0 + tx];
    __syncthreads();
#pragma unroll
    for (int i = 0; i < 4; ++i)
        dst[eofs + (size_t)(n0 + ty + i * 8) * Kd + k0 + tx] = __float2half_rn(t[tx][ty + i * 8]);
}

// ================= fp16 GEMM, cp.async 3-stage pipeline =================
// C[M,N] = A[M,K] * B^T + bias ; A fp16 [M,K], B fp16 [N,K] (k-contig).
// MODE 0: plain rows, C fp16. (QKV)
// MODE 1: plain rows, C fp32. (out-proj)
// MODE 2: A gathered via g_order, ReLU, C fp16 rows p. (MoE FFN1)
// MODE 3: A direct rows (g_h), C fp32 scatter via tok. (MoE FFN2)
constexpr int G_ASTG = 2560;                 // [128][20] words per stage
constexpr int G_BOFF = 3 * G_ASTG;           // 7680
constexpr int GEMM_SMEM_BYTES = (G_BOFF + 3 * G_ASTG) * 4;   // 61440 B

template<int MODE>
__global__ void __launch_bounds__(256, 2) gemm_f16(
    const __half* __restrict__ A, int lda,
    const __half* __restrict__ B, int ldb,
    const float* __restrict__ bias,
    void* __restrict__ Cv, int ldc,
    int K, int Nglob)
{
    extern __shared__ uint32_t smw[];
    __shared__ int tok[128];

    const int tid = threadIdx.x;
    const int wid = tid >> 5;
    const int ln  = tid & 31;
    const int wm  = wid >> 1;
    const int wn  = wid & 1;
    const int m0 = blockIdx.x * 128;
    const int n0 = blockIdx.y * 128;

    int seg0 = 0, seg1 = 1 << 30;
    const __half* Bp = B;
    const float* biasp = bias;
    if (MODE >= 2) {
        const int e = blockIdx.z;
        seg0 = g_off[e]; seg1 = g_off[e + 1];
        if (seg0 + m0 >= seg1) return;
        Bp    = B + (size_t)e * K * Nglob;
        biasp = bias + (size_t)e * Nglob;
        if (tid < 128) {
            const int p = seg0 + m0 + tid;
            tok[tid] = (p < seg1) ? g_order[p] : -1;
        }
        __syncthreads();
    }

    const uint32_t sbase = smem_u32(smw);

    float acc[2][8][4];
#pragma unroll
    for (int mt = 0; mt < 2; ++mt)
#pragma unroll
        for (int nt = 0; nt < 8; ++nt)
#pragma unroll
            for (int r = 0; r < 4; ++r) acc[mt][nt][r] = 0.f;

    const int nK = K >> 5;

    auto issue = [&](int kt) {
        const int k0 = kt << 5;
        const int s = kt % 3;
        const uint32_t sA = sbase + (s * G_ASTG) * 4;
        const uint32_t sB = sbase + (G_BOFF + s * G_ASTG) * 4;
#pragma unroll
        for (int it = 0; it < 2; ++it) {
            const int idx = tid + it * 256;   // 0..511
            const int row = idx >> 2;         // 0..127
            const int c   = idx & 3;          // 16B chunk
            // A
            const __half* ga;
            bool vA = true;
            if (MODE == 2) {
                const int tk = tok[row];
                vA = (tk >= 0);
                ga = A + (size_t)(vA ? tk : 0) * lda + k0 + c * 8;
            } else if (MODE == 3) {
                ga = A + (size_t)(seg0 + m0 + row) * lda + k0 + c * 8;
            } else {
                ga = A + (size_t)(m0 + row) * lda + k0 + c * 8;
            }
            cpa16(sA + (row * 20 + c * 4) * 4, ga, vA);
            // B
            const __half* gb = Bp + (size_t)(n0 + row) * ldb + k0 + c * 8;
            cpa16(sB + (row * 20 + c * 4) * 4, gb, true);
        }
    };
    auto compute = [&](int kt) {
        const int s = kt % 3;
        const uint32_t* sA = smw + s * G_ASTG;
        const uint32_t* sB = smw + G_BOFF + s * G_ASTG;
        const int lr = ln >> 2;
        const int lc = ln & 3;
#pragma unroll
        for (int ks = 0; ks < 2; ++ks) {
            const int kk2 = ks * 8;
            uint32_t af[2][4];
#pragma unroll
            for (int mt = 0; mt < 2; ++mt) {
                const int r = wm * 32 + mt * 16 + lr;
                af[mt][0] = sA[r * 20 + kk2 + lc];
                af[mt][1] = sA[(r + 8) * 20 + kk2 + lc];
                af[mt][2] = sA[r * 20 + kk2 + 4 + lc];
                af[mt][3] = sA[(r + 8) * 20 + kk2 + 4 + lc];
            }
#pragma unroll
            for (int nt = 0; nt < 8; ++nt) {
                const int n = wn * 64 + nt * 8 + lr;
                const uint32_t b0 = sB[n * 20 + kk2 + lc];
                const uint32_t b1 = sB[n * 20 + kk2 + 4 + lc];
                mma_f16(acc[0][nt], af[0], b0, b1);
                mma_f16(acc[1][nt], af[1], b0, b1);
            }
        }
    };

    // ---- pipelined mainloop (3 stages) ----
    issue(0); CP_COMMIT();
    issue(1); CP_COMMIT();
    for (int kt = 0; kt < nK; ++kt) {
        CP_WAIT1();
        __syncthreads();
        if (kt + 2 < nK) issue(kt + 2);
        CP_COMMIT();                       // always commit (keeps group-count invariant)
        compute(kt);
    }

    // ---- epilogue ----
    const int lr = ln >> 2;
    const int lc = ln & 3;
#pragma unroll
    for (int mt = 0; mt < 2; ++mt) {
        const int lrow0 = wm * 32 + mt * 16 + lr;
#pragma unroll
        for (int half = 0; half < 2; ++half) {
            const int lrow = lrow0 + half * 8;
            bool valid = true;
            size_t rowidx = 0;
            if (MODE == 0 || MODE == 1) {
                rowidx = (size_t)(m0 + lrow);
            } else if (MODE == 2) {
                const int p = seg0 + m0 + lrow;
                valid = (p < seg1);
                rowidx = (size_t)p;
            } else {
                const int tk = tok[lrow];
                valid = (tk >= 0);
                rowidx = (size_t)(valid ? tk : 0);
            }
            if (!valid) continue;
#pragma unroll
            for (int nt = 0; nt < 8; ++nt) {
                const int cc = n0 + wn * 64 + nt * 8 + lc * 2;
                float vx = acc[mt][nt][half * 2 + 0] + biasp[cc];
                float vy = acc[mt][nt][half * 2 + 1] + biasp[cc + 1];
                if (MODE == 0) {
                    uint32_t* dst = (uint32_t*)Cv + rowidx * (ldc >> 1) + (cc >> 1);
                    *dst = f2h2(vx, vy);
                } else if (MODE == 2) {
                    vx = fmaxf(vx, 0.f); vy = fmaxf(vy, 0.f);
                    uint32_t* dst = (uint32_t*)Cv + rowidx * (ldc >> 1) + (cc >> 1);
                    *dst = f2h2(vx, vy);
                } else {
                    float2 v; v.x = vx; v.y = vy;
                    *reinterpret_cast<float2*>((float*)Cv + rowidx * ldc + cc) = v;
                }
            }
        }
    }
}

// ================= fp16 tensor-core flash attention =================
// grid (NS/128, NB*NH), 256 thr. qkv fp16 in, attno fp16 out.
// P stays in registers (fp16 C-frag == A-frag layout).
__global__ void __launch_bounds__(256, 2) flash_attn_f16(
    const __half* __restrict__ qkvh, __half* __restrict__ Oh)
{
    __shared__ uint32_t sQ[128 * 36];
    __shared__ uint32_t sK[64 * 36];
    __shared__ uint32_t sVt[32 * 72];

    const int tid = threadIdx.x;
    const int wid = tid >> 5;
    const int ln  = tid & 31;
    const int lr  = ln >> 2;
    const int lc  = ln & 3;
    const int b   = blockIdx.y >> 4;
    const int h   = blockIdx.y & 15;
    const int q0  = blockIdx.x * 128;
    const int wq  = wid * 16;
    const float qscale = 0.18033688011112042f;   // log2(e) / sqrt(64)

    const uint32_t* qkw = reinterpret_cast<const uint32_t*>(qkvh);   // 1536 words/row

    // ---- stage Q (pure fp16 copy) ----
#pragma unroll
    for (int it = 0; it < 4; ++it) {
        const int idx = tid + it * 256;
        const int row = idx >> 3;
        const int c   = idx & 7;
        const uint32_t* src = qkw + (size_t)(b * NS + q0 + row) * 1536 + h * 32 + c * 4;
        *reinterpret_cast<uint4*>(&sQ[row * 36 + c * 4]) = *reinterpret_cast<const uint4*>(src);
    }

    float mr0 = -1e30f, mr1 = -1e30f;
    float l0 = 0.f, l1 = 0.f;
    float o[8][4];
#pragma unroll
    for (int jd = 0; jd < 8; ++jd)
#pragma unroll
        for (int r = 0; r < 4; ++r) o[jd][r] = 0.f;

    for (int kb = 0; kb < 16; ++kb) {
        // ---- stage K ----
#pragma unroll
        for (int it = 0; it < 2; ++it) {
            const int idx = tid + it * 256;
            const int row = idx >> 3;
            const int c   = idx & 7;
            const uint32_t* src = qkw + (size_t)(b * NS + kb * 64 + row) * 1536 + 512 + h * 32 + c * 4;
            *reinterpret_cast<uint4*>(&sK[row * 36 + c * 4]) = *reinterpret_cast<const uint4*>(src);
        }
        // ---- stage V transposed: sVt[k2][d] word = (V[2k2][d], V[2k2+1][d]) ----
        {
            const int k2 = tid >> 3;
            const int dc = tid & 7;
            const uint32_t* base = qkw + (size_t)(b * NS + kb * 64 + 2 * k2) * 1536 + 1024 + h * 32 + dc * 4;
            uint4 lo = *reinterpret_cast<const uint4*>(base);
            uint4 hi = *reinterpret_cast<const uint4*>(base + 1536);
            uint4 w0, w1;
            w0.x = __byte_perm(lo.x, hi.x, 0x5410); w0.y = __byte_perm(lo.x, hi.x, 0x7632);
            w0.z = __byte_perm(lo.y, hi.y, 0x5410); w0.w = __byte_perm(lo.y, hi.y, 0x7632);
            w1.x = __byte_perm(lo.z, hi.z, 0x5410); w1.y = __byte_perm(lo.z, hi.z, 0x7632);
            w1.z = __byte_perm(lo.w, hi.w, 0x5410); w1.w = __byte_perm(lo.w, hi.w, 0x7632);
            *reinterpret_cast<uint4*>(&sVt[k2 * 72 + dc * 8]) = w0;
            *reinterpret_cast<uint4*>(&sVt[k2 * 72 + dc * 8 + 4]) = w1;
        }
        __syncthreads();

        // ---- S = Q @ K^T (fp16 mma, fp32 acc) ----
        float s[8][4];
#pragma unroll
        for (int jn = 0; jn < 8; ++jn)
#pragma unroll
            for (int r = 0; r < 4; ++r) s[jn][r] = 0.f;
#pragma unroll
        for (int kk = 0; kk < 4; ++kk) {          // 4 x k16 over d=64
            uint32_t a[4];
            a[0] = sQ[(wq + lr) * 36 + kk * 8 + lc];
            a[1] = sQ[(wq + lr + 8) * 36 + kk * 8 + lc];
            a[2] = sQ[(wq + lr) * 36 + kk * 8 + 4 + lc];
            a[3] = sQ[(wq + lr + 8) * 36 + kk * 8 + 4 + lc];
#pragma unroll
            for (int jn = 0; jn < 8; ++jn) {
                const uint32_t b0 = sK[(jn * 8 + lr) * 36 + kk * 8 + lc];
                const uint32_t b1 = sK[(jn * 8 + lr) * 36 + kk * 8 + 4 + lc];
                mma_f16(s[jn], a, b0, b1);
            }
        }
        // scale into log2 domain
#pragma unroll
        for (int jn = 0; jn < 8; ++jn)
#pragma unroll
            for (int r = 0; r < 4; ++r) s[jn][r] *= qscale;

        // ---- online softmax (FMA pipe) ----
        float mx0 = s[0][0], mx1 = s[0][2];
#pragma unroll
        for (int jn = 0; jn < 8; ++jn) {
            mx0 = fmaxf(mx0, fmaxf(s[jn][0], s[jn][1]));
            mx1 = fmaxf(mx1, fmaxf(s[jn][2], s[jn][3]));
        }
        mx0 = fmaxf(mx0, __shfl_xor_sync(0xffffffffu, mx0, 1));
        mx0 = fmaxf(mx0, __shfl_xor_sync(0xffffffffu, mx0, 2));
        mx1 = fmaxf(mx1, __shfl_xor_sync(0xffffffffu, mx1, 1));
        mx1 = fmaxf(mx1, __shfl_xor_sync(0xffffffffu, mx1, 2));
        const float mn0 = fmaxf(mr0, mx0);
        const float mn1 = fmaxf(mr1, mx1);
        const float c0 = exp2p(mr0 - mn0);
        const float c1 = exp2p(mr1 - mn1);
        mr0 = mn0; mr1 = mn1;
        l0 *= c0; l1 *= c1;
#pragma unroll
        for (int jn = 0; jn < 8; ++jn) {
            s[jn][0] = exp2p(s[jn][0] - mr0);
            s[jn][1] = exp2p(s[jn][1] - mr0);
            s[jn][2] = exp2p(s[jn][2] - mr1);
            s[jn][3] = exp2p(s[jn][3] - mr1);
            l0 += s[jn][0] + s[jn][1];
            l1 += s[jn][2] + s[jn][3];
        }
#pragma unroll
        for (int jd = 0; jd < 8; ++jd) {
            o[jd][0] *= c0; o[jd][1] *= c0;
            o[jd][2] *= c1; o[jd][3] *= c1;
        }

        // ---- O += P @ V : P direct from registers (C-frag -> A-frag identity) ----
#pragma unroll
        for (int q = 0; q < 4; ++q) {             // 4 x k16 over 64 keys
            uint32_t a[4];
            a[0] = f2h2(s[2 * q][0], s[2 * q][1]);
            a[1] = f2h2(s[2 * q][2], s[2 * q][3]);
            a[2] = f2h2(s[2 * q + 1][0], s[2 * q + 1][1]);
            a[3] = f2h2(s[2 * q + 1][2], s[2 * q + 1][3]);
#pragma unroll
            for (int jd = 0; jd < 8; ++jd) {
                const uint32_t b0 = sVt[(q * 8 + lc) * 72 + jd * 8 + lr];
                const uint32_t b1 = sVt[(q * 8 + 4 + lc) * 72 + jd * 8 + lr];
                mma_f16(o[jd], a, b0, b1);
            }
        }
        __syncthreads();   // done reading sK/sVt before next staging
    }

    // ---- finalize ----
    l0 += __shfl_xor_sync(0xffffffffu, l0, 1);
    l0 += __shfl_xor_sync(0xffffffffu, l0, 2);
    l1 += __shfl_xor_sync(0xffffffffu, l1, 1);
    l1 += __shfl_xor_sync(0xffffffffu, l1, 2);
    const float i0 = 1.f / l0;
    const float i1 = 1.f / l1;
    uint32_t* ow = reinterpret_cast<uint32_t*>(Oh);   // 512 words/row
    const size_t r0 = (size_t)(b * NS + q0 + wq + lr);
    const size_t r1 = r0 + 8;
#pragma unroll
    for (int jd = 0; jd < 8; ++jd) {
        ow[r0 * 512 + h * 32 + jd * 4 + lc] = f2h2(o[jd][0] * i0, o[jd][1] * i0);
        ow[r1 * 512 + h * 32 + jd * 4 + lc] = f2h2(o[jd][2] * i1, o[jd][3] * i1);
    }
}

// ---------------- residual add + LayerNorm (optional fp16 copy out) ----------------
__global__ __launch_bounds__(256) void add_ln(
    const float* __restrict__ A, const float* __restrict__ R,
    const float* __restrict__ g, const float* __restrict__ bt,
    float* __restrict__ out, __half* __restrict__ out16)
{
    const int t = blockIdx.x;
    const int tid = threadIdx.x;
    __shared__ float red[8];

    const float4 a4 = *reinterpret_cast<const float4*>(A + (size_t)t * ND + tid * 4);
    const float4 r4 = *reinterpret_cast<const float4*>(R + (size_t)t * ND + tid * 4);
    float v[4] = {a4.x + r4.x, a4.y + r4.y, a4.z + r4.z, a4.w + r4.w};

    float sum = v[0] + v[1] + v[2] + v[3];
#pragma unroll
    for (int off = 16; off; off >>= 1) sum += __shfl_down_sync(0xffffffffu, sum, off);
    if ((tid & 31) == 0) red[tid >> 5] = sum;
    __syncthreads();
    if (tid < 8) {
        float s = red[tid];
#pragma unroll
        for (int off = 4; off; off >>= 1) s += __shfl_down_sync(0xffu, s, off);
        if (tid == 0) red[0] = s;
    }
    __syncthreads();
    const float mu = red[0] * (1.f / ND);
    __syncthreads();

    float vs = 0.f;
#pragma unroll
    for (int i = 0; i < 4; ++i) { float d = v[i] - mu; vs += d * d; }
#pragma unroll
    for (int off = 16; off; off >>= 1) vs += __shfl_down_sync(0xffffffffu, vs, off);
    if ((tid & 31) == 0) red[tid >> 5] = vs;
    __syncthreads();
    if (tid < 8) {
        float s = red[tid];
#pragma unroll
        for (int off = 4; off; off >>= 1) s += __shfl_down_sync(0xffu, s, off);
        if (tid == 0) red[0] = s;
    }
    __syncthreads();
    const float rstd = rsqrtf(red[0] * (1.f / ND) + EPS);

    float4 o4;
    const int d0 = tid * 4;
    o4.x = (v[0] - mu) * rstd * g[d0]     + bt[d0];
    o4.y = (v[1] - mu) * rstd * g[d0 + 1] + bt[d0 + 1];
    o4.z = (v[2] - mu) * rstd * g[d0 + 2] + bt[d0 + 2];
    o4.w = (v[3] - mu) * rstd * g[d0 + 3] + bt[d0 + 3];
    *reinterpret_cast<float4*>(out + (size_t)t * ND + d0) = o4;
    if (out16) {
        uint2 u;
        u.x = f2h2(o4.x, o4.y);
        u.y = f2h2(o4.z, o4.w);
        *reinterpret_cast<uint2*>(out16 + (size_t)t * ND + d0) = u;
    }
}

// ---------------- routing ----------------
__global__ void route_init() {
    if (threadIdx.x < NE) g_cnt[threadIdx.x] = 0;
}

__global__ __launch_bounds__(256) void gate_kernel(
    const float* __restrict__ X, const float* __restrict__ gw,
    const float* __restrict__ gb)
{
    const int warp = threadIdx.x >> 5;
    const int lane = threadIdx.x & 31;
    const int t = blockIdx.x * 8 + warp;
    const float* xp = X + (size_t)t * ND;
    float acc[NE];
#pragma unroll
    for (int e = 0; e < NE; ++e) acc[e] = 0.f;
    for (int d = lane; d < ND; d += 32) {
        const float xv = xp[d];
#pragma unroll
        for (int e = 0; e < NE; ++e) acc[e] = fmaf(xv, gw[e * ND + d], acc[e]);
    }
#pragma unroll
    for (int e = 0; e < NE; ++e)
#pragma unroll
        for (int off = 16; off; off >>= 1)
            acc[e] += __shfl_down_sync(0xffffffffu, acc[e], off);
    if (lane == 0) {
        int best = 0; float bv = acc[0] + gb[0];
#pragma unroll
        for (int e = 1; e < NE; ++e) {
            float v = acc[e] + gb[e];
            if (v > bv) { bv = v; best = e; }
        }
        g_idx[t] = best;
        atomicAdd(&g_cnt[best], 1);
    }
}

__global__ void route_scan() {
    g_off[0] = 0;
    for (int e = 0; e < NE; ++e) {
        g_off[e + 1] = g_off[e] + g_cnt[e];
        g_pos[e] = g_off[e];
    }
}

__global__ __launch_bounds__(256) void route_scatter() {
    const int t = blockIdx.x * 256 + threadIdx.x;
    if (t < NT) {
        const int e = g_idx[t];
        const int p = atomicAdd(&g_pos[e], 1);
        g_order[p] = t;
    }
}

// ---------------- launcher ----------------
extern "C" void kernel_launch(void* const* d_in, const int* in_sizes, int n_in,
                              void* d_out, int out_size)
{
    const float* x         = (const float*)d_in[0];
    const float* in_proj_w = (const float*)d_in[1];
    const float* in_proj_b = (const float*)d_in[2];
    const float* out_w     = (const float*)d_in[3];
    const float* out_b     = (const float*)d_in[4];
    const float* gate_w    = (const float*)d_in[5];
    const float* gate_b    = (const float*)d_in[6];
    const float* W1        = (const float*)d_in[7];
    const float* b1        = (const float*)d_in[8];
    const float* W2        = (const float*)d_in[9];
    const float* b2        = (const float*)d_in[10];
    const float* ln1_g     = (const float*)d_in[11];
    const float* ln1_b     = (const float*)d_in[12];
    const float* ln2_g     = (const float*)d_in[13];
    const float* ln2_b     = (const float*)d_in[14];
    float* out = (float*)d_out;

    __half *x16, *inwh, *outwh, *w1t, *w2t, *qkvh, *attnoh, *x1h, *hbuf;
    float  *tmp, *x1;
    cudaGetSymbolAddress((void**)&x16,    g_x16);
    cudaGetSymbolAddress((void**)&inwh,   g_inwh);
    cudaGetSymbolAddress((void**)&outwh,  g_outwh);
    cudaGetSymbolAddress((void**)&w1t,    g_w1t);
    cudaGetSymbolAddress((void**)&w2t,    g_w2t);
    cudaGetSymbolAddress((void**)&qkvh,   g_qkvh);
    cudaGetSymbolAddress((void**)&attnoh, g_attnoh);
    cudaGetSymbolAddress((void**)&x1h,    g_x1h);
    cudaGetSymbolAddress((void**)&hbuf,   g_h);
    cudaGetSymbolAddress((void**)&tmp,    g_tmp);
    cudaGetSymbolAddress((void**)&x1,     g_x1);

    cudaFuncSetAttribute(gemm_f16<0>, cudaFuncAttributeMaxDynamicSharedMemorySize, GEMM_SMEM_BYTES);
    cudaFuncSetAttribute(gemm_f16<1>, cudaFuncAttributeMaxDynamicSharedMemorySize, GEMM_SMEM_BYTES);
    cudaFuncSetAttribute(gemm_f16<2>, cudaFuncAttributeMaxDynamicSharedMemorySize, GEMM_SMEM_BYTES);
    cudaFuncSetAttribute(gemm_f16<3>, cudaFuncAttributeMaxDynamicSharedMemorySize, GEMM_SMEM_BYTES);

    // 0) one-time conversions / transposes
    cvt_f32_f16<<<NT * ND / 1024, 256>>>(x, x16, NT * ND / 4);
    cvt_f32_f16<<<3 * ND * ND / 1024, 256>>>(in_proj_w, inwh, 3 * ND * ND / 4);
    cvt_f32_f16<<<ND * ND / 1024, 256>>>(out_w, outwh, ND * ND / 4);
    transpose_cvt<<<dim3(NF / 32, ND / 32, NE), 256>>>(W1, w1t, ND, NF);   // [D][F]->[F][D]
    transpose_cvt<<<dim3(ND / 32, NF / 32, NE), 256>>>(W2, w2t, NF, ND);   // [F][D]->[D][F]

    // 1) QKV projection (fp16 out)
    gemm_f16<0><<<dim3(NT / 128, 3 * ND / 128, 1), 256, GEMM_SMEM_BYTES>>>(
        x16, ND, inwh, ND, in_proj_b, qkvh, 3 * ND, ND, 3 * ND);
    // 2) attention (fp16)
    flash_attn_f16<<<dim3(NS / 128, NB * NH), 256>>>(qkvh, attnoh);
    // 3) output projection (fp32 out)
    gemm_f16<1><<<dim3(NT / 128, ND / 128, 1), 256, GEMM_SMEM_BYTES>>>(
        attnoh, ND, outwh, ND, out_b, tmp, ND, ND, ND);
    // 4) residual + LN1 (fp32 + fp16 copies)
    add_ln<<<NT, 256>>>(tmp, x, ln1_g, ln1_b, x1, x1h);
    // 5) routing
    route_init<<<1, 32>>>();
    gate_kernel<<<NT / 8, 256>>>(x1, gate_w, gate_b);
    route_scan<<<1, 1>>>();
    route_scatter<<<NT / 256, 256>>>();
    // 6) MoE expert FFN
    gemm_f16<2><<<dim3(NT / 128, NF / 128, NE), 256, GEMM_SMEM_BYTES>>>(
        x1h, ND, w1t, ND, b1, hbuf, NF, ND, NF);
    gemm_f16<3><<<dim3(NT / 128, ND / 128, NE), 256, GEMM_SMEM_BYTES>>>(
        hbuf, NF, w2t, NF, b2, tmp, ND, NF, ND);
    // 7) residual + LN2 -> output
    add_ln<<<NT, 256>>>(tmp, x1, ln2_g, ln2_b, out, nullptr);

    (void)in_sizes; (void)n_in; (void)out_size;
}

// round 9
// speedup vs baseline: 5.9112x; 1.1327x over previous
#include <cuda_runtime.h>
#include <cuda_fp16.h>
#include <math.h>
#include <float.h>
#include <stdint.h>

// ---------------- problem constants ----------------
constexpr int NB  = 4;
constexpr int NS  = 1024;
constexpr int ND  = 1024;
constexpr int NH  = 16;
constexpr int NHD = 64;
constexpr int NE  = 8;
constexpr int NF  = 4096;
constexpr int NT  = NB * NS;            // 4096 tokens
constexpr float EPS = 1e-5f;

// ---------------- scratch (device globals; no runtime alloc) ----------------
__device__ __half g_x16[(size_t)NT * ND];
__device__ __half g_inwh[(size_t)3 * ND * ND];
__device__ __half g_outwh[(size_t)ND * ND];
__device__ __half g_w1t[(size_t)NE * NF * ND];      // [E][F][D] fp16 (transposed)
__device__ __half g_w2t[(size_t)NE * ND * NF];      // [E][D][F] fp16 (transposed)
__device__ __half g_qkvh[(size_t)NT * 3 * ND];
__device__ __half g_attnoh[(size_t)NT * ND];
__device__ __half g_x1h[(size_t)NT * ND];
__device__ __half g_h[(size_t)(NT + 128) * NF];     // fp16 hidden
__device__ float  g_tmp[(size_t)NT * ND];
__device__ float  g_x1[(size_t)NT * ND];
__device__ int    g_idx[NT];
__device__ int    g_order[NT];
__device__ int    g_cnt[NE];
__device__ int    g_off[NE + 1];
__device__ int    g_pos[NE];

// ---------------- helpers ----------------
__device__ __forceinline__ uint32_t f2h2(float lo, float hi) {
    __half2 h = __floats2half2_rn(lo, hi);
    return *reinterpret_cast<uint32_t*>(&h);
}
__device__ __forceinline__ uint32_t smem_u32(const void* p) {
    uint32_t a;
    asm("{ .reg .u64 t; cvta.to.shared.u64 t, %1; cvt.u32.u64 %0, t; }" : "=r"(a) : "l"(p));
    return a;
}
__device__ __forceinline__ void mma_f16(float c[4], const uint32_t a[4],
                                        uint32_t b0, uint32_t b1) {
    asm volatile(
        "mma.sync.aligned.m16n8k16.row.col.f32.f16.f16.f32 "
        "{%0,%1,%2,%3}, {%4,%5,%6,%7}, {%8,%9}, {%0,%1,%2,%3};"
        : "+f"(c[0]), "+f"(c[1]), "+f"(c[2]), "+f"(c[3])
        : "r"(a[0]), "r"(a[1]), "r"(a[2]), "r"(a[3]), "r"(b0), "r"(b1));
}
__device__ __forceinline__ void ldsm_x4(uint32_t d[4], uint32_t addr) {
    asm volatile("ldmatrix.sync.aligned.m8n8.x4.shared.b16 {%0,%1,%2,%3}, [%4];"
                 : "=r"(d[0]), "=r"(d[1]), "=r"(d[2]), "=r"(d[3]) : "r"(addr));
}
__device__ __forceinline__ void cpa16(uint32_t saddr, const void* gptr, bool valid) {
    const int sz = valid ? 16 : 0;
    asm volatile("cp.async.cg.shared.global [%0], [%1], 16, %2;"
                 :: "r"(saddr), "l"(gptr), "r"(sz));
}
#define CP_COMMIT()  asm volatile("cp.async.commit_group;")
#define CP_WAIT1()   asm volatile("cp.async.wait_group 1;")

// fast 2^y for y <= 0, FMA pipe only. |rel err| ~3e-6.
__device__ __forceinline__ float exp2p(float y) {
    y = fmaxf(y, -80.f);
    const int ni = __float2int_rn(y);
    const float f = y - (float)ni;
    float p = 0.0013333558146428443f;
    p = fmaf(p, f, 0.009618129107628477f);
    p = fmaf(p, f, 0.05550410866482158f);
    p = fmaf(p, f, 0.2402265069591007f);
    p = fmaf(p, f, 0.6931471805599453f);
    p = fmaf(p, f, 1.0f);
    return __uint_as_float(__float_as_uint(p) + ((uint32_t)ni << 23));
}

// ---------------- conversion kernels ----------------
__global__ __launch_bounds__(256) void cvt_f32_f16(
    const float* __restrict__ src, __half* __restrict__ dst, int n4)
{
    const int i = blockIdx.x * 256 + threadIdx.x;
    if (i < n4) {
        float4 v = reinterpret_cast<const float4*>(src)[i];
        uint2 u;
        u.x = f2h2(v.x, v.y);
        u.y = f2h2(v.z, v.w);
        reinterpret_cast<uint2*>(dst)[i] = u;
    }
}

// transpose + convert: src [Kd][Nd] fp32 -> dst [Nd][Kd] fp16, per expert (blockIdx.z)
// 64(k) x 32(n) tile; half2 stores.
__global__ __launch_bounds__(256) void transpose_cvt(
    const float* __restrict__ src, __half* __restrict__ dst, int Kd, int Nd)
{
    __shared__ float t[64][33];
    const size_t eofs = (size_t)blockIdx.z * (size_t)Kd * Nd;
    const int n0 = blockIdx.x * 32;
    const int k0 = blockIdx.y * 64;
    const int tx = threadIdx.x & 31;
    const int ty = threadIdx.x >> 5;   // 0..7
#pragma unroll
    for (int i = 0; i < 8; ++i)
        t[ty + i * 8][tx] = src[eofs + (size_t)(k0 + ty + i * 8) * Nd + n0 + tx];
    __syncthreads();
    const int nl = threadIdx.x >> 3;   // 0..31
    const int kc = threadIdx.x & 7;    // 0..7
    __half* drow = dst + eofs + (size_t)(n0 + nl) * Kd + k0;
#pragma unroll
    for (int j = 0; j < 4; ++j) {
        const int k2 = kc + j * 8;     // half2 index 0..31
        __half2 h = __floats2half2_rn(t[2 * k2][nl], t[2 * k2 + 1][nl]);
        *reinterpret_cast<__half2*>(drow + 2 * k2) = h;
    }
}

// ================= fp16 GEMM, cp.async 3-stage pipeline + ldmatrix =================
// C[M,N] = A[M,K] * B^T + bias ; A fp16 [M,K], B fp16 [N,K] (k-contig).
// MODE 0: plain rows, C fp16. (QKV)
// MODE 1: plain rows, C fp32. (out-proj)
// MODE 2: A gathered via g_order, ReLU, C fp16 rows p. (MoE FFN1)
// MODE 3: A direct rows (g_h), C fp32 scatter via tok. (MoE FFN2)
constexpr int G_ASTG = 2560;                 // [128][20] words per stage
constexpr int G_BOFF = 3 * G_ASTG;           // 7680
constexpr int GEMM_SMEM_BYTES = (G_BOFF + 3 * G_ASTG) * 4;   // 61440 B

template<int MODE>
__global__ void __launch_bounds__(256, 2) gemm_f16(
    const __half* __restrict__ A, int lda,
    const __half* __restrict__ B, int ldb,
    const float* __restrict__ bias,
    void* __restrict__ Cv, int ldc,
    int K, int Nglob)
{
    extern __shared__ uint32_t smw[];
    __shared__ int tok[128];

    const int tid = threadIdx.x;
    const int wid = tid >> 5;
    const int ln  = tid & 31;
    const int wm  = wid >> 1;
    const int wn  = wid & 1;
    const int m0 = blockIdx.x * 128;
    const int n0 = blockIdx.y * 128;

    int seg0 = 0, seg1 = 1 << 30;
    const __half* Bp = B;
    const float* biasp = bias;
    if (MODE >= 2) {
        const int e = blockIdx.z;
        seg0 = g_off[e]; seg1 = g_off[e + 1];
        if (seg0 + m0 >= seg1) return;
        Bp    = B + (size_t)e * K * Nglob;
        biasp = bias + (size_t)e * Nglob;
        if (tid < 128) {
            const int p = seg0 + m0 + tid;
            tok[tid] = (p < seg1) ? g_order[p] : -1;
        }
        __syncthreads();
    }

    const uint32_t sbase = smem_u32(smw);

    // ldmatrix lane-address offsets (bytes), invariant over kt
    // A: lanes 0-15 -> rows (wm*32 + mt*16 + (ln&15)), lanes 16-31 -> same rows, +16B (k-half)
    const uint32_t aoff0 = ((uint32_t)(wm * 32 + (ln & 15)) * 20u + (uint32_t)(ln >> 4) * 4u) * 4u;
    // B quad: lanes {0-7,8-15,16-23,24-31} -> rows n..n+7 (kh0), n..n+7 (kh1), n+8..15 (kh0), n+8..15 (kh1)
    const uint32_t brow = (uint32_t)(wn * 64) + (uint32_t)(((ln >> 4) << 3) | (ln & 7));
    const uint32_t boff0 = (brow * 20u + (uint32_t)((ln >> 3) & 1) * 4u) * 4u;

    float acc[2][8][4];
#pragma unroll
    for (int mt = 0; mt < 2; ++mt)
#pragma unroll
        for (int nt = 0; nt < 8; ++nt)
#pragma unroll
            for (int r = 0; r < 4; ++r) acc[mt][nt][r] = 0.f;

    const int nK = K >> 5;

    auto issue = [&](int kt) {
        const int k0 = kt << 5;
        const int s = kt % 3;
        const uint32_t sA = sbase + (s * G_ASTG) * 4;
        const uint32_t sB = sbase + (G_BOFF + s * G_ASTG) * 4;
#pragma unroll
        for (int it = 0; it < 2; ++it) {
            const int idx = tid + it * 256;   // 0..511
            const int row = idx >> 2;         // 0..127
            const int c   = idx & 3;          // 16B chunk
            const __half* ga;
            bool vA = true;
            if (MODE == 2) {
                const int tk = tok[row];
                vA = (tk >= 0);
                ga = A + (size_t)(vA ? tk : 0) * lda + k0 + c * 8;
            } else if (MODE == 3) {
                ga = A + (size_t)(seg0 + m0 + row) * lda + k0 + c * 8;
            } else {
                ga = A + (size_t)(m0 + row) * lda + k0 + c * 8;
            }
            cpa16(sA + (row * 20 + c * 4) * 4, ga, vA);
            const __half* gb = Bp + (size_t)(n0 + row) * ldb + k0 + c * 8;
            cpa16(sB + (row * 20 + c * 4) * 4, gb, true);
        }
    };
    auto compute = [&](int kt) {
        const int s = kt % 3;
        const uint32_t aab = sbase + (s * G_ASTG) * 4 + aoff0;
        const uint32_t bab = sbase + ((G_BOFF + s * G_ASTG)) * 4 + boff0;
#pragma unroll
        for (int ks = 0; ks < 2; ++ks) {
            const uint32_t kofs = (uint32_t)ks * 32u;
            uint32_t af[2][4];
            ldsm_x4(af[0], aab + kofs);
            ldsm_x4(af[1], aab + 1280u + kofs);     // mt=1: +16 rows * 80B
#pragma unroll
            for (int q = 0; q < 4; ++q) {
                uint32_t bf[4];
                ldsm_x4(bf, bab + (uint32_t)q * 1280u + kofs);
                mma_f16(acc[0][2 * q],     af[0], bf[0], bf[1]);
                mma_f16(acc[1][2 * q],     af[1], bf[0], bf[1]);
                mma_f16(acc[0][2 * q + 1], af[0], bf[2], bf[3]);
                mma_f16(acc[1][2 * q + 1], af[1], bf[2], bf[3]);
            }
        }
    };

    // ---- pipelined mainloop (3 stages) ----
    issue(0); CP_COMMIT();
    issue(1); CP_COMMIT();
    for (int kt = 0; kt < nK; ++kt) {
        CP_WAIT1();
        __syncthreads();
        if (kt + 2 < nK) issue(kt + 2);
        CP_COMMIT();                       // always commit (keeps group-count invariant)
        compute(kt);
    }

    // ---- epilogue ----
    const int lr = ln >> 2;
    const int lc = ln & 3;
#pragma unroll
    for (int mt = 0; mt < 2; ++mt) {
        const int lrow0 = wm * 32 + mt * 16 + lr;
#pragma unroll
        for (int half = 0; half < 2; ++half) {
            const int lrow = lrow0 + half * 8;
            bool valid = true;
            size_t rowidx = 0;
            if (MODE == 0 || MODE == 1) {
                rowidx = (size_t)(m0 + lrow);
            } else if (MODE == 2) {
                const int p = seg0 + m0 + lrow;
                valid = (p < seg1);
                rowidx = (size_t)p;
            } else {
                const int tk = tok[lrow];
                valid = (tk >= 0);
                rowidx = (size_t)(valid ? tk : 0);
            }
            if (!valid) continue;
#pragma unroll
            for (int nt = 0; nt < 8; ++nt) {
                const int cc = n0 + wn * 64 + nt * 8 + lc * 2;
                float vx = acc[mt][nt][half * 2 + 0] + biasp[cc];
                float vy = acc[mt][nt][half * 2 + 1] + biasp[cc + 1];
                if (MODE == 0) {
                    uint32_t* dst = (uint32_t*)Cv + rowidx * (ldc >> 1) + (cc >> 1);
                    *dst = f2h2(vx, vy);
                } else if (MODE == 2) {
                    vx = fmaxf(vx, 0.f); vy = fmaxf(vy, 0.f);
                    uint32_t* dst = (uint32_t*)Cv + rowidx * (ldc >> 1) + (cc >> 1);
                    *dst = f2h2(vx, vy);
                } else {
                    float2 v; v.x = vx; v.y = vy;
                    *reinterpret_cast<float2*>((float*)Cv + rowidx * ldc + cc) = v;
                }
            }
        }
    }
}

// ================= fp16 tensor-core flash attention =================
// grid (NS/128, NB*NH), 256 thr. qkv fp16 in, attno fp16 out.
// P stays in registers (fp16 C-frag == A-frag layout).
__global__ void __launch_bounds__(256, 2) flash_attn_f16(
    const __half* __restrict__ qkvh, __half* __restrict__ Oh)
{
    __shared__ uint32_t sQ[128 * 36];
    __shared__ uint32_t sK[64 * 36];
    __shared__ uint32_t sVt[32 * 72];

    const int tid = threadIdx.x;
    const int wid = tid >> 5;
    const int ln  = tid & 31;
    const int lr  = ln >> 2;
    const int lc  = ln & 3;
    const int b   = blockIdx.y >> 4;
    const int h   = blockIdx.y & 15;
    const int q0  = blockIdx.x * 128;
    const int wq  = wid * 16;
    const float qscale = 0.18033688011112042f;   // log2(e) / sqrt(64)

    const uint32_t* qkw = reinterpret_cast<const uint32_t*>(qkvh);   // 1536 words/row

    // ---- stage Q (pure fp16 copy) ----
#pragma unroll
    for (int it = 0; it < 4; ++it) {
        const int idx = tid + it * 256;
        const int row = idx >> 3;
        const int c   = idx & 7;
        const uint32_t* src = qkw + (size_t)(b * NS + q0 + row) * 1536 + h * 32 + c * 4;
        *reinterpret_cast<uint4*>(&sQ[row * 36 + c * 4]) = *reinterpret_cast<const uint4*>(src);
    }

    float mr0 = -1e30f, mr1 = -1e30f;
    float l0 = 0.f, l1 = 0.f;
    float o[8][4];
#pragma unroll
    for (int jd = 0; jd < 8; ++jd)
#pragma unroll
        for (int r = 0; r < 4; ++r) o[jd][r] = 0.f;

    for (int kb = 0; kb < 16; ++kb) {
        // ---- stage K ----
#pragma unroll
        for (int it = 0; it < 2; ++it) {
            const int idx = tid + it * 256;
            const int row = idx >> 3;
            const int c   = idx & 7;
            const uint32_t* src = qkw + (size_t)(b * NS + kb * 64 + row) * 1536 + 512 + h * 32 + c * 4;
            *reinterpret_cast<uint4*>(&sK[row * 36 + c * 4]) = *reinterpret_cast<const uint4*>(src);
        }
        // ---- stage V transposed: sVt[k2][d] word = (V[2k2][d], V[2k2+1][d]) ----
        {
            const int k2 = tid >> 3;
            const int dc = tid & 7;
            const uint32_t* base = qkw + (size_t)(b * NS + kb * 64 + 2 * k2) * 1536 + 1024 + h * 32 + dc * 4;
            uint4 lo = *reinterpret_cast<const uint4*>(base);
            uint4 hi = *reinterpret_cast<const uint4*>(base + 1536);
            uint4 w0, w1;
            w0.x = __byte_perm(lo.x, hi.x, 0x5410); w0.y = __byte_perm(lo.x, hi.x, 0x7632);
            w0.z = __byte_perm(lo.y, hi.y, 0x5410); w0.w = __byte_perm(lo.y, hi.y, 0x7632);
            w1.x = __byte_perm(lo.z, hi.z, 0x5410); w1.y = __byte_perm(lo.z, hi.z, 0x7632);
            w1.z = __byte_perm(lo.w, hi.w, 0x5410); w1.w = __byte_perm(lo.w, hi.w, 0x7632);
            *reinterpret_cast<uint4*>(&sVt[k2 * 72 + dc * 8]) = w0;
            *reinterpret_cast<uint4*>(&sVt[k2 * 72 + dc * 8 + 4]) = w1;
        }
        __syncthreads();

        // ---- S = Q @ K^T (fp16 mma, fp32 acc) ----
        float s[8][4];
#pragma unroll
        for (int jn = 0; jn < 8; ++jn)
#pragma unroll
            for (int r = 0; r < 4; ++r) s[jn][r] = 0.f;
#pragma unroll
        for (int kk = 0; kk < 4; ++kk) {          // 4 x k16 over d=64
            uint32_t a[4];
            a[0] = sQ[(wq + lr) * 36 + kk * 8 + lc];
            a[1] = sQ[(wq + lr + 8) * 36 + kk * 8 + lc];
            a[2] = sQ[(wq + lr) * 36 + kk * 8 + 4 + lc];
            a[3] = sQ[(wq + lr + 8) * 36 + kk * 8 + 4 + lc];
#pragma unroll
            for (int jn = 0; jn < 8; ++jn) {
                const uint32_t b0 = sK[(jn * 8 + lr) * 36 + kk * 8 + lc];
                const uint32_t b1 = sK[(jn * 8 + lr) * 36 + kk * 8 + 4 + lc];
                mma_f16(s[jn], a, b0, b1);
            }
        }
        // scale into log2 domain
#pragma unroll
        for (int jn = 0; jn < 8; ++jn)
#pragma unroll
            for (int r = 0; r < 4; ++r) s[jn][r] *= qscale;

        // ---- online softmax (FMA pipe) ----
        float mx0 = s[0][0], mx1 = s[0][2];
#pragma unroll
        for (int jn = 0; jn < 8; ++jn) {
            mx0 = fmaxf(mx0, fmaxf(s[jn][0], s[jn][1]));
            mx1 = fmaxf(mx1, fmaxf(s[jn][2], s[jn][3]));
        }
        mx0 = fmaxf(mx0, __shfl_xor_sync(0xffffffffu, mx0, 1));
        mx0 = fmaxf(mx0, __shfl_xor_sync(0xffffffffu, mx0, 2));
        mx1 = fmaxf(mx1, __shfl_xor_sync(0xffffffffu, mx1, 1));
        mx1 = fmaxf(mx1, __shfl_xor_sync(0xffffffffu, mx1, 2));
        const float mn0 = fmaxf(mr0, mx0);
        const float mn1 = fmaxf(mr1, mx1);
        const float c0 = exp2p(mr0 - mn0);
        const float c1 = exp2p(mr1 - mn1);
        mr0 = mn0; mr1 = mn1;
        l0 *= c0; l1 *= c1;
#pragma unroll
        for (int jn = 0; jn < 8; ++jn) {
            s[jn][0] = exp2p(s[jn][0] - mr0);
            s[jn][1] = exp2p(s[jn][1] - mr0);
            s[jn][2] = exp2p(s[jn][2] - mr1);
            s[jn][3] = exp2p(s[jn][3] - mr1);
            l0 += s[jn][0] + s[jn][1];
            l1 += s[jn][2] + s[jn][3];
        }
#pragma unroll
        for (int jd = 0; jd < 8; ++jd) {
            o[jd][0] *= c0; o[jd][1] *= c0;
            o[jd][2] *= c1; o[jd][3] *= c1;
        }

        // ---- O += P @ V : P direct from registers (C-frag -> A-frag identity) ----
#pragma unroll
        for (int q = 0; q < 4; ++q) {             // 4 x k16 over 64 keys
            uint32_t a[4];
            a[0] = f2h2(s[2 * q][0], s[2 * q][1]);
            a[1] = f2h2(s[2 * q][2], s[2 * q][3]);
            a[2] = f2h2(s[2 * q + 1][0], s[2 * q + 1][1]);
            a[3] = f2h2(s[2 * q + 1][2], s[2 * q + 1][3]);
#pragma unroll
            for (int jd = 0; jd < 8; ++jd) {
                const uint32_t b0 = sVt[(q * 8 + lc) * 72 + jd * 8 + lr];
                const uint32_t b1 = sVt[(q * 8 + 4 + lc) * 72 + jd * 8 + lr];
                mma_f16(o[jd], a, b0, b1);
            }
        }
        __syncthreads();   // done reading sK/sVt before next staging
    }

    // ---- finalize ----
    l0 += __shfl_xor_sync(0xffffffffu, l0, 1);
    l0 += __shfl_xor_sync(0xffffffffu, l0, 2);
    l1 += __shfl_xor_sync(0xffffffffu, l1, 1);
    l1 += __shfl_xor_sync(0xffffffffu, l1, 2);
    const float i0 = 1.f / l0;
    const float i1 = 1.f / l1;
    uint32_t* ow = reinterpret_cast<uint32_t*>(Oh);   // 512 words/row
    const size_t r0 = (size_t)(b * NS + q0 + wq + lr);
    const size_t r1 = r0 + 8;
#pragma unroll
    for (int jd = 0; jd < 8; ++jd) {
        ow[r0 * 512 + h * 32 + jd * 4 + lc] = f2h2(o[jd][0] * i0, o[jd][1] * i0);
        ow[r1 * 512 + h * 32 + jd * 4 + lc] = f2h2(o[jd][2] * i1, o[jd][3] * i1);
    }
}

// ---------------- residual add + LayerNorm (optional fp16 copy out) ----------------
__global__ __launch_bounds__(256) void add_ln(
    const float* __restrict__ A, const float* __restrict__ R,
    const float* __restrict__ g, const float* __restrict__ bt,
    float* __restrict__ out, __half* __restrict__ out16)
{
    const int t = blockIdx.x;
    const int tid = threadIdx.x;
    __shared__ float red[8];

    const float4 a4 = *reinterpret_cast<const float4*>(A + (size_t)t * ND + tid * 4);
    const float4 r4 = *reinterpret_cast<const float4*>(R + (size_t)t * ND + tid * 4);
    float v[4] = {a4.x + r4.x, a4.y + r4.y, a4.z + r4.z, a4.w + r4.w};

    float sum = v[0] + v[1] + v[2] + v[3];
#pragma unroll
    for (int off = 16; off; off >>= 1) sum += __shfl_down_sync(0xffffffffu, sum, off);
    if ((tid & 31) == 0) red[tid >> 5] = sum;
    __syncthreads();
    if (tid < 8) {
        float s = red[tid];
#pragma unroll
        for (int off = 4; off; off >>= 1) s += __shfl_down_sync(0xffu, s, off);
        if (tid == 0) red[0] = s;
    }
    __syncthreads();
    const float mu = red[0] * (1.f / ND);
    __syncthreads();

    float vs = 0.f;
#pragma unroll
    for (int i = 0; i < 4; ++i) { float d = v[i] - mu; vs += d * d; }
#pragma unroll
    for (int off = 16; off; off >>= 1) vs += __shfl_down_sync(0xffffffffu, vs, off);
    if ((tid & 31) == 0) red[tid >> 5] = vs;
    __syncthreads();
    if (tid < 8) {
        float s = red[tid];
#pragma unroll
        for (int off = 4; off; off >>= 1) s += __shfl_down_sync(0xffu, s, off);
        if (tid == 0) red[0] = s;
    }
    __syncthreads();
    const float rstd = rsqrtf(red[0] * (1.f / ND) + EPS);

    float4 o4;
    const int d0 = tid * 4;
    o4.x = (v[0] - mu) * rstd * g[d0]     + bt[d0];
    o4.y = (v[1] - mu) * rstd * g[d0 + 1] + bt[d0 + 1];
    o4.z = (v[2] - mu) * rstd * g[d0 + 2] + bt[d0 + 2];
    o4.w = (v[3] - mu) * rstd * g[d0 + 3] + bt[d0 + 3];
    *reinterpret_cast<float4*>(out + (size_t)t * ND + d0) = o4;
    if (out16) {
        uint2 u;
        u.x = f2h2(o4.x, o4.y);
        u.y = f2h2(o4.z, o4.w);
        *reinterpret_cast<uint2*>(out16 + (size_t)t * ND + d0) = u;
    }
}

// ---------------- routing ----------------
__global__ void route_init() {
    if (threadIdx.x < NE) g_cnt[threadIdx.x] = 0;
}

__global__ __launch_bounds__(256) void gate_kernel(
    const float* __restrict__ X, const float* __restrict__ gw,
    const float* __restrict__ gb)
{
    const int warp = threadIdx.x >> 5;
    const int lane = threadIdx.x & 31;
    const int t = blockIdx.x * 8 + warp;
    const float* xp = X + (size_t)t * ND;
    float acc[NE];
#pragma unroll
    for (int e = 0; e < NE; ++e) acc[e] = 0.f;
    for (int d = lane; d < ND; d += 32) {
        const float xv = xp[d];
#pragma unroll
        for (int e = 0; e < NE; ++e) acc[e] = fmaf(xv, gw[e * ND + d], acc[e]);
    }
#pragma unroll
    for (int e = 0; e < NE; ++e)
#pragma unroll
        for (int off = 16; off; off >>= 1)
            acc[e] += __shfl_down_sync(0xffffffffu, acc[e], off);
    if (lane == 0) {
        int best = 0; float bv = acc[0] + gb[0];
#pragma unroll
        for (int e = 1; e < NE; ++e) {
            float v = acc[e] + gb[e];
            if (v > bv) { bv = v; best = e; }
        }
        g_idx[t] = best;
        atomicAdd(&g_cnt[best], 1);
    }
}

__global__ void route_scan() {
    g_off[0] = 0;
    for (int e = 0; e < NE; ++e) {
        g_off[e + 1] = g_off[e] + g_cnt[e];
        g_pos[e] = g_off[e];
    }
}

__global__ __launch_bounds__(256) void route_scatter() {
    const int t = blockIdx.x * 256 + threadIdx.x;
    if (t < NT) {
        const int e = g_idx[t];
        const int p = atomicAdd(&g_pos[e], 1);
        g_order[p] = t;
    }
}

// ---------------- launcher ----------------
extern "C" void kernel_launch(void* const* d_in, const int* in_sizes, int n_in,
                              void* d_out, int out_size)
{
    const float* x         = (const float*)d_in[0];
    const float* in_proj_w = (const float*)d_in[1];
    const float* in_proj_b = (const float*)d_in[2];
    const float* out_w     = (const float*)d_in[3];
    const float* out_b     = (const float*)d_in[4];
    const float* gate_w    = (const float*)d_in[5];
    const float* gate_b    = (const float*)d_in[6];
    const float* W1        = (const float*)d_in[7];
    const float* b1        = (const float*)d_in[8];
    const float* W2        = (const float*)d_in[9];
    const float* b2        = (const float*)d_in[10];
    const float* ln1_g     = (const float*)d_in[11];
    const float* ln1_b     = (const float*)d_in[12];
    const float* ln2_g     = (const float*)d_in[13];
    const float* ln2_b     = (const float*)d_in[14];
    float* out = (float*)d_out;

    __half *x16, *inwh, *outwh, *w1t, *w2t, *qkvh, *attnoh, *x1h, *hbuf;
    float  *tmp, *x1;
    cudaGetSymbolAddress((void**)&x16,    g_x16);
    cudaGetSymbolAddress((void**)&inwh,   g_inwh);
    cudaGetSymbolAddress((void**)&outwh,  g_outwh);
    cudaGetSymbolAddress((void**)&w1t,    g_w1t);
    cudaGetSymbolAddress((void**)&w2t,    g_w2t);
    cudaGetSymbolAddress((void**)&qkvh,   g_qkvh);
    cudaGetSymbolAddress((void**)&attnoh, g_attnoh);
    cudaGetSymbolAddress((void**)&x1h,    g_x1h);
    cudaGetSymbolAddress((void**)&hbuf,   g_h);
    cudaGetSymbolAddress((void**)&tmp,    g_tmp);
    cudaGetSymbolAddress((void**)&x1,     g_x1);

    cudaFuncSetAttribute(gemm_f16<0>, cudaFuncAttributeMaxDynamicSharedMemorySize, GEMM_SMEM_BYTES);
    cudaFuncSetAttribute(gemm_f16<1>, cudaFuncAttributeMaxDynamicSharedMemorySize, GEMM_SMEM_BYTES);
    cudaFuncSetAttribute(gemm_f16<2>, cudaFuncAttributeMaxDynamicSharedMemorySize, GEMM_SMEM_BYTES);
    cudaFuncSetAttribute(gemm_f16<3>, cudaFuncAttributeMaxDynamicSharedMemorySize, GEMM_SMEM_BYTES);

    // 0) one-time conversions / transposes
    cvt_f32_f16<<<NT * ND / 1024, 256>>>(x, x16, NT * ND / 4);
    cvt_f32_f16<<<3 * ND * ND / 1024, 256>>>(in_proj_w, inwh, 3 * ND * ND / 4);
    cvt_f32_f16<<<ND * ND / 1024, 256>>>(out_w, outwh, ND * ND / 4);
    transpose_cvt<<<dim3(NF / 32, ND / 64, NE), 256>>>(W1, w1t, ND, NF);   // [D][F]->[F][D]
    transpose_cvt<<<dim3(ND / 32, NF / 64, NE), 256>>>(W2, w2t, NF, ND);   // [F][D]->[D][F]

    // 1) QKV projection (fp16 out)
    gemm_f16<0><<<dim3(NT / 128, 3 * ND / 128, 1), 256, GEMM_SMEM_BYTES>>>(
        x16, ND, inwh, ND, in_proj_b, qkvh, 3 * ND, ND, 3 * ND);
    // 2) attention (fp16)
    flash_attn_f16<<<dim3(NS / 128, NB * NH), 256>>>(qkvh, attnoh);
    // 3) output projection (fp32 out)
    gemm_f16<1><<<dim3(NT / 128, ND / 128, 1), 256, GEMM_SMEM_BYTES>>>(
        attnoh, ND, outwh, ND, out_b, tmp, ND, ND, ND);
    // 4) residual + LN1 (fp32 + fp16 copies)
    add_ln<<<NT, 256>>>(tmp, x, ln1_g, ln1_b, x1, x1h);
    // 5) routing
    route_init<<<1, 32>>>();
    gate_kernel<<<NT / 8, 256>>>(x1, gate_w, gate_b);
    route_scan<<<1, 1>>>();
    route_scatter<<<NT / 256, 256>>>();
    // 6) MoE expert FFN
    gemm_f16<2><<<dim3(NT / 128, NF / 128, NE), 256, GEMM_SMEM_BYTES>>>(
        x1h, ND, w1t, ND, b1, hbuf, NF, ND, NF);
    gemm_f16<3><<<dim3(NT / 128, ND / 128, NE), 256, GEMM_SMEM_BYTES>>>(
        hbuf, NF, w2t, NF, b2, tmp, ND, NF, ND);
    // 7) residual + LN2 -> output
    add_ln<<<NT, 256>>>(tmp, x1, ln2_g, ln2_b, out, nullptr);

    (void)in_sizes; (void)n_in; (void)out_size;
}

// round 10
// speedup vs baseline: 6.3460x; 1.0735x over previous
#include <cuda_runtime.h>
#include <cuda_fp16.h>
#include <math.h>
#include <float.h>
#include <stdint.h>

// ---------------- problem constants ----------------
constexpr int NB  = 4;
constexpr int NS  = 1024;
constexpr int ND  = 1024;
constexpr int NH  = 16;
constexpr int NHD = 64;
constexpr int NE  = 8;
constexpr int NF  = 4096;
constexpr int NT  = NB * NS;            // 4096 tokens
constexpr float EPS = 1e-5f;

// ---------------- scratch (device globals; no runtime alloc) ----------------
__device__ __half g_x16[(size_t)NT * ND];
__device__ __half g_inwh[(size_t)3 * ND * ND];
__device__ __half g_outwh[(size_t)ND * ND];
__device__ __half g_w1t[(size_t)NE * NF * ND];      // [E][F][D] fp16 (transposed)
__device__ __half g_w2t[(size_t)NE * ND * NF];      // [E][D][F] fp16 (transposed)
__device__ __half g_qkvh[(size_t)NT * 3 * ND];
__device__ __half g_attnoh[(size_t)NT * ND];
__device__ __half g_x1h[(size_t)NT * ND];
__device__ __half g_h[(size_t)(NT + 128) * NF];     // fp16 hidden
__device__ float  g_tmp[(size_t)NT * ND];
__device__ float  g_x1[(size_t)NT * ND];
__device__ int    g_idx[NT];
__device__ int    g_order[NT];
__device__ int    g_cnt[NE];
__device__ int    g_off[NE + 1];
__device__ int    g_pos[NE];

// ---------------- helpers ----------------
__device__ __forceinline__ uint32_t f2h2(float lo, float hi) {
    __half2 h = __floats2half2_rn(lo, hi);
    return *reinterpret_cast<uint32_t*>(&h);
}
__device__ __forceinline__ uint32_t smem_u32(const void* p) {
    uint32_t a;
    asm("{ .reg .u64 t; cvta.to.shared.u64 t, %1; cvt.u32.u64 %0, t; }" : "=r"(a) : "l"(p));
    return a;
}
__device__ __forceinline__ void mma_f16(float c[4], const uint32_t a[4],
                                        uint32_t b0, uint32_t b1) {
    asm volatile(
        "mma.sync.aligned.m16n8k16.row.col.f32.f16.f16.f32 "
        "{%0,%1,%2,%3}, {%4,%5,%6,%7}, {%8,%9}, {%0,%1,%2,%3};"
        : "+f"(c[0]), "+f"(c[1]), "+f"(c[2]), "+f"(c[3])
        : "r"(a[0]), "r"(a[1]), "r"(a[2]), "r"(a[3]), "r"(b0), "r"(b1));
}
__device__ __forceinline__ void ldsm_x4(uint32_t d[4], uint32_t addr) {
    asm volatile("ldmatrix.sync.aligned.m8n8.x4.shared.b16 {%0,%1,%2,%3}, [%4];"
                 : "=r"(d[0]), "=r"(d[1]), "=r"(d[2]), "=r"(d[3]) : "r"(addr));
}
__device__ __forceinline__ void cpa16(uint32_t saddr, const void* gptr, bool valid) {
    const int sz = valid ? 16 : 0;
    asm volatile("cp.async.cg.shared.global [%0], [%1], 16, %2;"
                 :: "r"(saddr), "l"(gptr), "r"(sz));
}
#define CP_COMMIT()  asm volatile("cp.async.commit_group;")
#define CP_WAIT2()   asm volatile("cp.async.wait_group 2;")

// fast 2^y for y <= 0, FMA pipe only. |rel err| ~3e-6.
__device__ __forceinline__ float exp2p(float y) {
    y = fmaxf(y, -80.f);
    const int ni = __float2int_rn(y);
    const float f = y - (float)ni;
    float p = 0.0013333558146428443f;
    p = fmaf(p, f, 0.009618129107628477f);
    p = fmaf(p, f, 0.05550410866482158f);
    p = fmaf(p, f, 0.2402265069591007f);
    p = fmaf(p, f, 0.6931471805599453f);
    p = fmaf(p, f, 1.0f);
    return __uint_as_float(__float_as_uint(p) + ((uint32_t)ni << 23));
}

// ---------------- conversion kernels ----------------
__global__ __launch_bounds__(256) void cvt_f32_f16(
    const float* __restrict__ src, __half* __restrict__ dst, int n4)
{
    const int i = blockIdx.x * 256 + threadIdx.x;
    if (i < n4) {
        float4 v = reinterpret_cast<const float4*>(src)[i];
        uint2 u;
        u.x = f2h2(v.x, v.y);
        u.y = f2h2(v.z, v.w);
        reinterpret_cast<uint2*>(dst)[i] = u;
    }
}

// transpose + convert: src [Kd][Nd] fp32 -> dst [Nd][Kd] fp16, per expert (blockIdx.z)
__global__ __launch_bounds__(256) void transpose_cvt(
    const float* __restrict__ src, __half* __restrict__ dst, int Kd, int Nd)
{
    __shared__ float t[64][33];
    const size_t eofs = (size_t)blockIdx.z * (size_t)Kd * Nd;
    const int n0 = blockIdx.x * 32;
    const int k0 = blockIdx.y * 64;
    const int tx = threadIdx.x & 31;
    const int ty = threadIdx.x >> 5;   // 0..7
#pragma unroll
    for (int i = 0; i < 8; ++i)
        t[ty + i * 8][tx] = src[eofs + (size_t)(k0 + ty + i * 8) * Nd + n0 + tx];
    __syncthreads();
    const int nl = threadIdx.x >> 3;   // 0..31
    const int kc = threadIdx.x & 7;    // 0..7
    __half* drow = dst + eofs + (size_t)(n0 + nl) * Kd + k0;
#pragma unroll
    for (int j = 0; j < 4; ++j) {
        const int k2 = kc + j * 8;     // half2 index 0..31
        __half2 h = __floats2half2_rn(t[2 * k2][nl], t[2 * k2 + 1][nl]);
        *reinterpret_cast<__half2*>(drow + 2 * k2) = h;
    }
}

// ================= fp16 GEMM: 4 warps x (64x64), cp.async 4-stage, ldmatrix ========
// C[M,N] = A[M,K] * B^T + bias ; A fp16 [M,K], B fp16 [N,K] (k-contig).
// MODE 0: plain rows, C fp16. (QKV)
// MODE 1: plain rows, C fp32. (out-proj)
// MODE 2: A gathered via g_order, ReLU, C fp16 rows p. (MoE FFN1)
// MODE 3: A direct rows (g_h), C fp32 scatter via tok. (MoE FFN2)
constexpr int G_ASTG = 2560;                 // [128][20] words per stage
constexpr int G_BOFF = 4 * G_ASTG;           // 10240
constexpr int GEMM_SMEM_BYTES = 8 * G_ASTG * 4;   // 81920 B

template<int MODE>
__global__ void __launch_bounds__(128, 2) gemm_f16(
    const __half* __restrict__ A, int lda,
    const __half* __restrict__ B, int ldb,
    const float* __restrict__ bias,
    void* __restrict__ Cv, int ldc,
    int K, int Nglob)
{
    extern __shared__ uint32_t smw[];
    __shared__ int tok[128];

    const int tid = threadIdx.x;
    const int wid = tid >> 5;           // 0..3
    const int ln  = tid & 31;
    const int wm  = wid >> 1;           // 0..1 -> 64-row slice
    const int wn  = wid & 1;            // 0..1 -> 64-col slice
    const int m0 = blockIdx.x * 128;
    const int n0 = blockIdx.y * 128;

    int seg0 = 0, seg1 = 1 << 30;
    const __half* Bp = B;
    const float* biasp = bias;
    if (MODE >= 2) {
        const int e = blockIdx.z;
        seg0 = g_off[e]; seg1 = g_off[e + 1];
        if (seg0 + m0 >= seg1) return;
        Bp    = B + (size_t)e * K * Nglob;
        biasp = bias + (size_t)e * Nglob;
        {
            const int p = seg0 + m0 + tid;
            tok[tid] = (p < seg1) ? g_order[p] : -1;
        }
        __syncthreads();
    }

    const uint32_t sbase = smem_u32(smw);

    // ldmatrix lane-address offsets (bytes), invariant over kt
    const uint32_t aoff0 = ((uint32_t)(wm * 64 + (ln & 15)) * 20u + (uint32_t)(ln >> 4) * 4u) * 4u;
    const uint32_t brow = (uint32_t)(wn * 64) + (uint32_t)(((ln >> 4) << 3) | (ln & 7));
    const uint32_t boff0 = (brow * 20u + (uint32_t)((ln >> 3) & 1) * 4u) * 4u;

    float acc[4][8][4];
#pragma unroll
    for (int mt = 0; mt < 4; ++mt)
#pragma unroll
        for (int nt = 0; nt < 8; ++nt)
#pragma unroll
            for (int r = 0; r < 4; ++r) acc[mt][nt][r] = 0.f;

    const int nK = K >> 5;

    auto issue = [&](int kt) {
        const int k0 = kt << 5;
        const int s = kt & 3;
        const uint32_t sA = sbase + (s * G_ASTG) * 4;
        const uint32_t sB = sbase + (G_BOFF + s * G_ASTG) * 4;
#pragma unroll
        for (int it = 0; it < 4; ++it) {
            const int idx = tid + it * 128;   // 0..511
            const int row = idx >> 2;         // 0..127
            const int c   = idx & 3;          // 16B chunk
            const __half* ga;
            bool vA = true;
            if (MODE == 2) {
                const int tk = tok[row];
                vA = (tk >= 0);
                ga = A + (size_t)(vA ? tk : 0) * lda + k0 + c * 8;
            } else if (MODE == 3) {
                ga = A + (size_t)(seg0 + m0 + row) * lda + k0 + c * 8;
            } else {
                ga = A + (size_t)(m0 + row) * lda + k0 + c * 8;
            }
            cpa16(sA + (row * 20 + c * 4) * 4, ga, vA);
            const __half* gb = Bp + (size_t)(n0 + row) * ldb + k0 + c * 8;
            cpa16(sB + (row * 20 + c * 4) * 4, gb, true);
        }
    };
    auto compute = [&](int kt) {
        const int s = kt & 3;
        const uint32_t aab = sbase + (s * G_ASTG) * 4 + aoff0;
        const uint32_t bab = sbase + ((G_BOFF + s * G_ASTG)) * 4 + boff0;
#pragma unroll
        for (int ks = 0; ks < 2; ++ks) {
            const uint32_t kofs = (uint32_t)ks * 32u;
            uint32_t af[4][4];
#pragma unroll
            for (int mt = 0; mt < 4; ++mt)
                ldsm_x4(af[mt], aab + (uint32_t)mt * 1280u + kofs);
#pragma unroll
            for (int q = 0; q < 4; ++q) {
                uint32_t bf[4];
                ldsm_x4(bf, bab + (uint32_t)q * 1280u + kofs);
#pragma unroll
                for (int mt = 0; mt < 4; ++mt) {
                    mma_f16(acc[mt][2 * q],     af[mt], bf[0], bf[1]);
                    mma_f16(acc[mt][2 * q + 1], af[mt], bf[2], bf[3]);
                }
            }
        }
    };

    // ---- pipelined mainloop (4 stages, 3 in flight) ----
    issue(0); CP_COMMIT();
    issue(1); CP_COMMIT();
    issue(2); CP_COMMIT();
    for (int kt = 0; kt < nK; ++kt) {
        CP_WAIT2();
        __syncthreads();
        if (kt + 3 < nK) issue(kt + 3);
        CP_COMMIT();                       // always commit (keeps group-count invariant)
        compute(kt);
    }

    // ---- epilogue ----
    const int lr = ln >> 2;
    const int lc = ln & 3;
#pragma unroll
    for (int mt = 0; mt < 4; ++mt) {
#pragma unroll
        for (int half = 0; half < 2; ++half) {
            const int lrow = wm * 64 + mt * 16 + half * 8 + lr;
            bool valid = true;
            size_t rowidx = 0;
            if (MODE == 0 || MODE == 1) {
                rowidx = (size_t)(m0 + lrow);
            } else if (MODE == 2) {
                const int p = seg0 + m0 + lrow;
                valid = (p < seg1);
                rowidx = (size_t)p;
            } else {
                const int tk = tok[lrow];
                valid = (tk >= 0);
                rowidx = (size_t)(valid ? tk : 0);
            }
            if (!valid) continue;
#pragma unroll
            for (int nt = 0; nt < 8; ++nt) {
                const int cc = n0 + wn * 64 + nt * 8 + lc * 2;
                float vx = acc[mt][nt][half * 2 + 0] + biasp[cc];
                float vy = acc[mt][nt][half * 2 + 1] + biasp[cc + 1];
                if (MODE == 0) {
                    uint32_t* dst = (uint32_t*)Cv + rowidx * (ldc >> 1) + (cc >> 1);
                    *dst = f2h2(vx, vy);
                } else if (MODE == 2) {
                    vx = fmaxf(vx, 0.f); vy = fmaxf(vy, 0.f);
                    uint32_t* dst = (uint32_t*)Cv + rowidx * (ldc >> 1) + (cc >> 1);
                    *dst = f2h2(vx, vy);
                } else {
                    float2 v; v.x = vx; v.y = vy;
                    *reinterpret_cast<float2*>((float*)Cv + rowidx * ldc + cc) = v;
                }
            }
        }
    }
}

// ================= fp16 tensor-core flash attention =================
// grid (NS/128, NB*NH), 256 thr. qkv fp16 in, attno fp16 out.
// P stays in registers (fp16 C-frag == A-frag layout).
__global__ void __launch_bounds__(256, 2) flash_attn_f16(
    const __half* __restrict__ qkvh, __half* __restrict__ Oh)
{
    __shared__ uint32_t sQ[128 * 36];
    __shared__ uint32_t sK[64 * 36];
    __shared__ uint32_t sVt[32 * 72];

    const int tid = threadIdx.x;
    const int wid = tid >> 5;
    const int ln  = tid & 31;
    const int lr  = ln >> 2;
    const int lc  = ln & 3;
    const int b   = blockIdx.y >> 4;
    const int h   = blockIdx.y & 15;
    const int q0  = blockIdx.x * 128;
    const int wq  = wid * 16;
    const float qscale = 0.18033688011112042f;   // log2(e) / sqrt(64)

    const uint32_t* qkw = reinterpret_cast<const uint32_t*>(qkvh);   // 1536 words/row

    // ---- stage Q (pure fp16 copy) ----
#pragma unroll
    for (int it = 0; it < 4; ++it) {
        const int idx = tid + it * 256;
        const int row = idx >> 3;
        const int c   = idx & 7;
        const uint32_t* src = qkw + (size_t)(b * NS + q0 + row) * 1536 + h * 32 + c * 4;
        *reinterpret_cast<uint4*>(&sQ[row * 36 + c * 4]) = *reinterpret_cast<const uint4*>(src);
    }

    float mr0 = -1e30f, mr1 = -1e30f;
    float l0 = 0.f, l1 = 0.f;
    float o[8][4];
#pragma unroll
    for (int jd = 0; jd < 8; ++jd)
#pragma unroll
        for (int r = 0; r < 4; ++r) o[jd][r] = 0.f;

    for (int kb = 0; kb < 16; ++kb) {
        // ---- stage K ----
#pragma unroll
        for (int it = 0; it < 2; ++it) {
            const int idx = tid + it * 256;
            const int row = idx >> 3;
            const int c   = idx & 7;
            const uint32_t* src = qkw + (size_t)(b * NS + kb * 64 + row) * 1536 + 512 + h * 32 + c * 4;
            *reinterpret_cast<uint4*>(&sK[row * 36 + c * 4]) = *reinterpret_cast<const uint4*>(src);
        }
        // ---- stage V transposed: sVt[k2][d] word = (V[2k2][d], V[2k2+1][d]) ----
        {
            const int k2 = tid >> 3;
            const int dc = tid & 7;
            const uint32_t* base = qkw + (size_t)(b * NS + kb * 64 + 2 * k2) * 1536 + 1024 + h * 32 + dc * 4;
            uint4 lo = *reinterpret_cast<const uint4*>(base);
            uint4 hi = *reinterpret_cast<const uint4*>(base + 1536);
            uint4 w0, w1;
            w0.x = __byte_perm(lo.x, hi.x, 0x5410); w0.y = __byte_perm(lo.x, hi.x, 0x7632);
            w0.z = __byte_perm(lo.y, hi.y, 0x5410); w0.w = __byte_perm(lo.y, hi.y, 0x7632);
            w1.x = __byte_perm(lo.z, hi.z, 0x5410); w1.y = __byte_perm(lo.z, hi.z, 0x7632);
            w1.z = __byte_perm(lo.w, hi.w, 0x5410); w1.w = __byte_perm(lo.w, hi.w, 0x7632);
            *reinterpret_cast<uint4*>(&sVt[k2 * 72 + dc * 8]) = w0;
            *reinterpret_cast<uint4*>(&sVt[k2 * 72 + dc * 8 + 4]) = w1;
        }
        __syncthreads();

        // ---- S = Q @ K^T (fp16 mma, fp32 acc) ----
        float s[8][4];
#pragma unroll
        for (int jn = 0; jn < 8; ++jn)
#pragma unroll
            for (int r = 0; r < 4; ++r) s[jn][r] = 0.f;
#pragma unroll
        for (int kk = 0; kk < 4; ++kk) {          // 4 x k16 over d=64
            uint32_t a[4];
            a[0] = sQ[(wq + lr) * 36 + kk * 8 + lc];
            a[1] = sQ[(wq + lr + 8) * 36 + kk * 8 + lc];
            a[2] = sQ[(wq + lr) * 36 + kk * 8 + 4 + lc];
            a[3] = sQ[(wq + lr + 8) * 36 + kk * 8 + 4 + lc];
#pragma unroll
            for (int jn = 0; jn < 8; ++jn) {
                const uint32_t b0 = sK[(jn * 8 + lr) * 36 + kk * 8 + lc];
                const uint32_t b1 = sK[(jn * 8 + lr) * 36 + kk * 8 + 4 + lc];
                mma_f16(s[jn], a, b0, b1);
            }
        }
        // scale into log2 domain
#pragma unroll
        for (int jn = 0; jn < 8; ++jn)
#pragma unroll
            for (int r = 0; r < 4; ++r) s[jn][r] *= qscale;

        // ---- online softmax (FMA pipe) ----
        float mx0 = s[0][0], mx1 = s[0][2];
#pragma unroll
        for (int jn = 0; jn < 8; ++jn) {
            mx0 = fmaxf(mx0, fmaxf(s[jn][0], s[jn][1]));
            mx1 = fmaxf(mx1, fmaxf(s[jn][2], s[jn][3]));
        }
        mx0 = fmaxf(mx0, __shfl_xor_sync(0xffffffffu, mx0, 1));
        mx0 = fmaxf(mx0, __shfl_xor_sync(0xffffffffu, mx0, 2));
        mx1 = fmaxf(mx1, __shfl_xor_sync(0xffffffffu, mx1, 1));
        mx1 = fmaxf(mx1, __shfl_xor_sync(0xffffffffu, mx1, 2));
        const float mn0 = fmaxf(mr0, mx0);
        const float mn1 = fmaxf(mr1, mx1);
        const float c0 = exp2p(mr0 - mn0);
        const float c1 = exp2p(mr1 - mn1);
        mr0 = mn0; mr1 = mn1;
        l0 *= c0; l1 *= c1;
#pragma unroll
        for (int jn = 0; jn < 8; ++jn) {
            s[jn][0] = exp2p(s[jn][0] - mr0);
            s[jn][1] = exp2p(s[jn][1] - mr0);
            s[jn][2] = exp2p(s[jn][2] - mr1);
            s[jn][3] = exp2p(s[jn][3] - mr1);
            l0 += s[jn][0] + s[jn][1];
            l1 += s[jn][2] + s[jn][3];
        }
#pragma unroll
        for (int jd = 0; jd < 8; ++jd) {
            o[jd][0] *= c0; o[jd][1] *= c0;
            o[jd][2] *= c1; o[jd][3] *= c1;
        }

        // ---- O += P @ V : P direct from registers (C-frag -> A-frag identity) ----
#pragma unroll
        for (int q = 0; q < 4; ++q) {             // 4 x k16 over 64 keys
            uint32_t a[4];
            a[0] = f2h2(s[2 * q][0], s[2 * q][1]);
            a[1] = f2h2(s[2 * q][2], s[2 * q][3]);
            a[2] = f2h2(s[2 * q + 1][0], s[2 * q + 1][1]);
            a[3] = f2h2(s[2 * q + 1][2], s[2 * q + 1][3]);
#pragma unroll
            for (int jd = 0; jd < 8; ++jd) {
                const uint32_t b0 = sVt[(q * 8 + lc) * 72 + jd * 8 + lr];
                const uint32_t b1 = sVt[(q * 8 + 4 + lc) * 72 + jd * 8 + lr];
                mma_f16(o[jd], a, b0, b1);
            }
        }
        __syncthreads();   // done reading sK/sVt before next staging
    }

    // ---- finalize ----
    l0 += __shfl_xor_sync(0xffffffffu, l0, 1);
    l0 += __shfl_xor_sync(0xffffffffu, l0, 2);
    l1 += __shfl_xor_sync(0xffffffffu, l1, 1);
    l1 += __shfl_xor_sync(0xffffffffu, l1, 2);
    const float i0 = 1.f / l0;
    const float i1 = 1.f / l1;
    uint32_t* ow = reinterpret_cast<uint32_t*>(Oh);   // 512 words/row
    const size_t r0 = (size_t)(b * NS + q0 + wq + lr);
    const size_t r1 = r0 + 8;
#pragma unroll
    for (int jd = 0; jd < 8; ++jd) {
        ow[r0 * 512 + h * 32 + jd * 4 + lc] = f2h2(o[jd][0] * i0, o[jd][1] * i0);
        ow[r1 * 512 + h * 32 + jd * 4 + lc] = f2h2(o[jd][2] * i1, o[jd][3] * i1);
    }
}

// ---------------- residual add + LayerNorm (optional fp16 copy out) ----------------
__global__ __launch_bounds__(256) void add_ln(
    const float* __restrict__ A, const float* __restrict__ R,
    const float* __restrict__ g, const float* __restrict__ bt,
    float* __restrict__ out, __half* __restrict__ out16)
{
    const int t = blockIdx.x;
    const int tid = threadIdx.x;
    __shared__ float red[8];

    const float4 a4 = *reinterpret_cast<const float4*>(A + (size_t)t * ND + tid * 4);
    const float4 r4 = *reinterpret_cast<const float4*>(R + (size_t)t * ND + tid * 4);
    float v[4] = {a4.x + r4.x, a4.y + r4.y, a4.z + r4.z, a4.w + r4.w};

    float sum = v[0] + v[1] + v[2] + v[3];
#pragma unroll
    for (int off = 16; off; off >>= 1) sum += __shfl_down_sync(0xffffffffu, sum, off);
    if ((tid & 31) == 0) red[tid >> 5] = sum;
    __syncthreads();
    if (tid < 8) {
        float s = red[tid];
#pragma unroll
        for (int off = 4; off; off >>= 1) s += __shfl_down_sync(0xffu, s, off);
        if (tid == 0) red[0] = s;
    }
    __syncthreads();
    const float mu = red[0] * (1.f / ND);
    __syncthreads();

    float vs = 0.f;
#pragma unroll
    for (int i = 0; i < 4; ++i) { float d = v[i] - mu; vs += d * d; }
#pragma unroll
    for (int off = 16; off; off >>= 1) vs += __shfl_down_sync(0xffffffffu, vs, off);
    if ((tid & 31) == 0) red[tid >> 5] = vs;
    __syncthreads();
    if (tid < 8) {
        float s = red[tid];
#pragma unroll
        for (int off = 4; off; off >>= 1) s += __shfl_down_sync(0xffu, s, off);
        if (tid == 0) red[0] = s;
    }
    __syncthreads();
    const float rstd = rsqrtf(red[0] * (1.f / ND) + EPS);

    float4 o4;
    const int d0 = tid * 4;
    o4.x = (v[0] - mu) * rstd * g[d0]     + bt[d0];
    o4.y = (v[1] - mu) * rstd * g[d0 + 1] + bt[d0 + 1];
    o4.z = (v[2] - mu) * rstd * g[d0 + 2] + bt[d0 + 2];
    o4.w = (v[3] - mu) * rstd * g[d0 + 3] + bt[d0 + 3];
    *reinterpret_cast<float4*>(out + (size_t)t * ND + d0) = o4;
    if (out16) {
        uint2 u;
        u.x = f2h2(o4.x, o4.y);
        u.y = f2h2(o4.z, o4.w);
        *reinterpret_cast<uint2*>(out16 + (size_t)t * ND + d0) = u;
    }
}

// ---------------- routing ----------------
__global__ void route_init() {
    if (threadIdx.x < NE) g_cnt[threadIdx.x] = 0;
}

__global__ __launch_bounds__(256) void gate_kernel(
    const float* __restrict__ X, const float* __restrict__ gw,
    const float* __restrict__ gb)
{
    const int warp = threadIdx.x >> 5;
    const int lane = threadIdx.x & 31;
    const int t = blockIdx.x * 8 + warp;
    const float* xp = X + (size_t)t * ND;
    float acc[NE];
#pragma unroll
    for (int e = 0; e < NE; ++e) acc[e] = 0.f;
    for (int d = lane; d < ND; d += 32) {
        const float xv = xp[d];
#pragma unroll
        for (int e = 0; e < NE; ++e) acc[e] = fmaf(xv, gw[e * ND + d], acc[e]);
    }
#pragma unroll
    for (int e = 0; e < NE; ++e)
#pragma unroll
        for (int off = 16; off; off >>= 1)
            acc[e] += __shfl_down_sync(0xffffffffu, acc[e], off);
    if (lane == 0) {
        int best = 0; float bv = acc[0] + gb[0];
#pragma unroll
        for (int e = 1; e < NE; ++e) {
            float v = acc[e] + gb[e];
            if (v > bv) { bv = v; best = e; }
        }
        g_idx[t] = best;
        atomicAdd(&g_cnt[best], 1);
    }
}

__global__ void route_scan() {
    g_off[0] = 0;
    for (int e = 0; e < NE; ++e) {
        g_off[e + 1] = g_off[e] + g_cnt[e];
        g_pos[e] = g_off[e];
    }
}

__global__ __launch_bounds__(256) void route_scatter() {
    const int t = blockIdx.x * 256 + threadIdx.x;
    if (t < NT) {
        const int e = g_idx[t];
        const int p = atomicAdd(&g_pos[e], 1);
        g_order[p] = t;
    }
}

// ---------------- launcher ----------------
extern "C" void kernel_launch(void* const* d_in, const int* in_sizes, int n_in,
                              void* d_out, int out_size)
{
    const float* x         = (const float*)d_in[0];
    const float* in_proj_w = (const float*)d_in[1];
    const float* in_proj_b = (const float*)d_in[2];
    const float* out_w     = (const float*)d_in[3];
    const float* out_b     = (const float*)d_in[4];
    const float* gate_w    = (const float*)d_in[5];
    const float* gate_b    = (const float*)d_in[6];
    const float* W1        = (const float*)d_in[7];
    const float* b1        = (const float*)d_in[8];
    const float* W2        = (const float*)d_in[9];
    const float* b2        = (const float*)d_in[10];
    const float* ln1_g     = (const float*)d_in[11];
    const float* ln1_b     = (const float*)d_in[12];
    const float* ln2_g     = (const float*)d_in[13];
    const float* ln2_b     = (const float*)d_in[14];
    float* out = (float*)d_out;

    __half *x16, *inwh, *outwh, *w1t, *w2t, *qkvh, *attnoh, *x1h, *hbuf;
    float  *tmp, *x1;
    cudaGetSymbolAddress((void**)&x16,    g_x16);
    cudaGetSymbolAddress((void**)&inwh,   g_inwh);
    cudaGetSymbolAddress((void**)&outwh,  g_outwh);
    cudaGetSymbolAddress((void**)&w1t,    g_w1t);
    cudaGetSymbolAddress((void**)&w2t,    g_w2t);
    cudaGetSymbolAddress((void**)&qkvh,   g_qkvh);
    cudaGetSymbolAddress((void**)&attnoh, g_attnoh);
    cudaGetSymbolAddress((void**)&x1h,    g_x1h);
    cudaGetSymbolAddress((void**)&hbuf,   g_h);
    cudaGetSymbolAddress((void**)&tmp,    g_tmp);
    cudaGetSymbolAddress((void**)&x1,     g_x1);

    cudaFuncSetAttribute(gemm_f16<0>, cudaFuncAttributeMaxDynamicSharedMemorySize, GEMM_SMEM_BYTES);
    cudaFuncSetAttribute(gemm_f16<1>, cudaFuncAttributeMaxDynamicSharedMemorySize, GEMM_SMEM_BYTES);
    cudaFuncSetAttribute(gemm_f16<2>, cudaFuncAttributeMaxDynamicSharedMemorySize, GEMM_SMEM_BYTES);
    cudaFuncSetAttribute(gemm_f16<3>, cudaFuncAttributeMaxDynamicSharedMemorySize, GEMM_SMEM_BYTES);

    // 0) one-time conversions / transposes
    cvt_f32_f16<<<NT * ND / 1024, 256>>>(x, x16, NT * ND / 4);
    cvt_f32_f16<<<3 * ND * ND / 1024, 256>>>(in_proj_w, inwh, 3 * ND * ND / 4);
    cvt_f32_f16<<<ND * ND / 1024, 256>>>(out_w, outwh, ND * ND / 4);
    transpose_cvt<<<dim3(NF / 32, ND / 64, NE), 256>>>(W1, w1t, ND, NF);   // [D][F]->[F][D]
    transpose_cvt<<<dim3(ND / 32, NF / 64, NE), 256>>>(W2, w2t, NF, ND);   // [F][D]->[D][F]

    // 1) QKV projection (fp16 out)
    gemm_f16<0><<<dim3(NT / 128, 3 * ND / 128, 1), 128, GEMM_SMEM_BYTES>>>(
        x16, ND, inwh, ND, in_proj_b, qkvh, 3 * ND, ND, 3 * ND);
    // 2) attention (fp16)
    flash_attn_f16<<<dim3(NS / 128, NB * NH), 256>>>(qkvh, attnoh);
    // 3) output projection (fp32 out)
    gemm_f16<1><<<dim3(NT / 128, ND / 128, 1), 128, GEMM_SMEM_BYTES>>>(
        attnoh, ND, outwh, ND, out_b, tmp, ND, ND, ND);
    // 4) residual + LN1 (fp32 + fp16 copies)
    add_ln<<<NT, 256>>>(tmp, x, ln1_g, ln1_b, x1, x1h);
    // 5) routing
    route_init<<<1, 32>>>();
    gate_kernel<<<NT / 8, 256>>>(x1, gate_w, gate_b);
    route_scan<<<1, 1>>>();
    route_scatter<<<NT / 256, 256>>>();
    // 6) MoE expert FFN
    gemm_f16<2><<<dim3(NT / 128, NF / 128, NE), 128, GEMM_SMEM_BYTES>>>(
        x1h, ND, w1t, ND, b1, hbuf, NF, ND, NF);
    gemm_f16<3><<<dim3(NT / 128, ND / 128, NE), 128, GEMM_SMEM_BYTES>>>(
        hbuf, NF, w2t, NF, b2, tmp, ND, NF, ND);
    // 7) residual + LN2 -> output
    add_ln<<<NT, 256>>>(tmp, x1, ln2_g, ln2_b, out, nullptr);

    (void)in_sizes; (void)n_in; (void)out_size;
}

// round 11
// speedup vs baseline: 6.5568x; 1.0332x over previous
#include <cuda_runtime.h>
#include <cuda_fp16.h>
#include <math.h>
#include <float.h>
#include <stdint.h>

// ---------------- problem constants ----------------
constexpr int NB  = 4;
constexpr int NS  = 1024;
constexpr int ND  = 1024;
constexpr int NH  = 16;
constexpr int NHD = 64;
constexpr int NE  = 8;
constexpr int NF  = 4096;
constexpr int NT  = NB * NS;            // 4096 tokens
constexpr float EPS = 1e-5f;

// ---------------- scratch (device globals; no runtime alloc) ----------------
__device__ __half g_x16[(size_t)NT * ND];
__device__ __half g_inwh[(size_t)3 * ND * ND];
__device__ __half g_outwh[(size_t)ND * ND];
__device__ __half g_w1t[(size_t)NE * NF * ND];      // [E][F][D] fp16 (transposed)
__device__ __half g_w2t[(size_t)NE * ND * NF];      // [E][D][F] fp16 (transposed)
__device__ __half g_qkvh[(size_t)NT * 3 * ND];
__device__ __half g_attnoh[(size_t)NT * ND];
__device__ __half g_x1h[(size_t)NT * ND];
__device__ __half g_h[(size_t)(NT + 128) * NF];     // fp16 hidden
__device__ float  g_tmp[(size_t)NT * ND];
__device__ float  g_x1[(size_t)NT * ND];
__device__ int    g_idx[NT];
__device__ int    g_order[NT];
__device__ int    g_cnt[NE];
__device__ int    g_off[NE + 1];
__device__ int    g_pos[NE];

// ---------------- helpers ----------------
__device__ __forceinline__ uint32_t f2h2(float lo, float hi) {
    __half2 h = __floats2half2_rn(lo, hi);
    return *reinterpret_cast<uint32_t*>(&h);
}
__device__ __forceinline__ uint32_t smem_u32(const void* p) {
    uint32_t a;
    asm("{ .reg .u64 t; cvta.to.shared.u64 t, %1; cvt.u32.u64 %0, t; }" : "=r"(a) : "l"(p));
    return a;
}
__device__ __forceinline__ void mma_f16(float c[4], const uint32_t a[4],
                                        uint32_t b0, uint32_t b1) {
    asm volatile(
        "mma.sync.aligned.m16n8k16.row.col.f32.f16.f16.f32 "
        "{%0,%1,%2,%3}, {%4,%5,%6,%7}, {%8,%9}, {%0,%1,%2,%3};"
        : "+f"(c[0]), "+f"(c[1]), "+f"(c[2]), "+f"(c[3])
        : "r"(a[0]), "r"(a[1]), "r"(a[2]), "r"(a[3]), "r"(b0), "r"(b1));
}
__device__ __forceinline__ void ldsm_x4(uint32_t d[4], uint32_t addr) {
    asm volatile("ldmatrix.sync.aligned.m8n8.x4.shared.b16 {%0,%1,%2,%3}, [%4];"
                 : "=r"(d[0]), "=r"(d[1]), "=r"(d[2]), "=r"(d[3]) : "r"(addr));
}
__device__ __forceinline__ void cpa16(uint32_t saddr, const void* gptr, bool valid) {
    const int sz = valid ? 16 : 0;
    asm volatile("cp.async.cg.shared.global [%0], [%1], 16, %2;"
                 :: "r"(saddr), "l"(gptr), "r"(sz));
}
#define CP_COMMIT()  asm volatile("cp.async.commit_group;")
#define CP_WAIT2()   asm volatile("cp.async.wait_group 2;")

// fast 2^y for y <= 0, FMA pipe only. |rel err| ~3e-6.
__device__ __forceinline__ float exp2p(float y) {
    y = fmaxf(y, -80.f);
    const int ni = __float2int_rn(y);
    const float f = y - (float)ni;
    float p = 0.0013333558146428443f;
    p = fmaf(p, f, 0.009618129107628477f);
    p = fmaf(p, f, 0.05550410866482158f);
    p = fmaf(p, f, 0.2402265069591007f);
    p = fmaf(p, f, 0.6931471805599453f);
    p = fmaf(p, f, 1.0f);
    return __uint_as_float(__float_as_uint(p) + ((uint32_t)ni << 23));
}

// ---------------- conversion kernels ----------------
__global__ __launch_bounds__(256) void cvt_f32_f16(
    const float* __restrict__ src, __half* __restrict__ dst, int n4)
{
    const int i = blockIdx.x * 256 + threadIdx.x;
    if (i < n4) {
        float4 v = reinterpret_cast<const float4*>(src)[i];
        uint2 u;
        u.x = f2h2(v.x, v.y);
        u.y = f2h2(v.z, v.w);
        reinterpret_cast<uint2*>(dst)[i] = u;
    }
}

// transpose + convert: src [Kd][Nd] fp32 -> dst [Nd][Kd] fp16, per expert (blockIdx.z)
__global__ __launch_bounds__(256) void transpose_cvt(
    const float* __restrict__ src, __half* __restrict__ dst, int Kd, int Nd)
{
    __shared__ float t[64][33];
    const size_t eofs = (size_t)blockIdx.z * (size_t)Kd * Nd;
    const int n0 = blockIdx.x * 32;
    const int k0 = blockIdx.y * 64;
    const int tx = threadIdx.x & 31;
    const int ty = threadIdx.x >> 5;   // 0..7
#pragma unroll
    for (int i = 0; i < 8; ++i)
        t[ty + i * 8][tx] = src[eofs + (size_t)(k0 + ty + i * 8) * Nd + n0 + tx];
    __syncthreads();
    const int nl = threadIdx.x >> 3;   // 0..31
    const int kc = threadIdx.x & 7;    // 0..7
    __half* drow = dst + eofs + (size_t)(n0 + nl) * Kd + k0;
#pragma unroll
    for (int j = 0; j < 4; ++j) {
        const int k2 = kc + j * 8;     // half2 index 0..31
        __half2 h = __floats2half2_rn(t[2 * k2][nl], t[2 * k2 + 1][nl]);
        *reinterpret_cast<__half2*>(drow + 2 * k2) = h;
    }
}

// ================= fp16 GEMM: 4 warps x (64x64), cp.async 4-stage, ldmatrix ========
// C[M,N] = A[M,K] * B^T + bias ; A fp16 [M,K], B fp16 [N,K] (k-contig).
// MODE 0: plain rows, C fp16. (QKV)
// MODE 1: plain rows, C fp32. (out-proj)
// MODE 2: A gathered via g_order, ReLU, C fp16 rows p. (MoE FFN1)
// MODE 3: A direct rows (g_h), C fp32 scatter via tok. (MoE FFN2)
constexpr int G_ASTG = 2560;                 // [128][20] words per stage
constexpr int G_BOFF = 4 * G_ASTG;           // 10240
constexpr int GEMM_SMEM_BYTES = 8 * G_ASTG * 4;   // 81920 B

template<int MODE>
__global__ void __launch_bounds__(128, 2) gemm_f16(
    const __half* __restrict__ A, int lda,
    const __half* __restrict__ B, int ldb,
    const float* __restrict__ bias,
    void* __restrict__ Cv, int ldc,
    int K, int Nglob)
{
    extern __shared__ uint32_t smw[];
    __shared__ int tok[128];

    const int tid = threadIdx.x;
    const int wid = tid >> 5;           // 0..3
    const int ln  = tid & 31;
    const int wm  = wid >> 1;           // 0..1 -> 64-row slice
    const int wn  = wid & 1;            // 0..1 -> 64-col slice
    const int m0 = blockIdx.x * 128;
    const int n0 = blockIdx.y * 128;

    int seg0 = 0, seg1 = 1 << 30;
    const __half* Bp = B;
    const float* biasp = bias;
    if (MODE >= 2) {
        const int e = blockIdx.z;
        seg0 = g_off[e]; seg1 = g_off[e + 1];
        if (seg0 + m0 >= seg1) return;
        Bp    = B + (size_t)e * K * Nglob;
        biasp = bias + (size_t)e * Nglob;
        {
            const int p = seg0 + m0 + tid;
            tok[tid] = (p < seg1) ? g_order[p] : -1;
        }
        __syncthreads();
    }

    const uint32_t sbase = smem_u32(smw);

    // ldmatrix lane-address offsets (bytes), invariant over kt
    const uint32_t aoff0 = ((uint32_t)(wm * 64 + (ln & 15)) * 20u + (uint32_t)(ln >> 4) * 4u) * 4u;
    const uint32_t brow = (uint32_t)(wn * 64) + (uint32_t)(((ln >> 4) << 3) | (ln & 7));
    const uint32_t boff0 = (brow * 20u + (uint32_t)((ln >> 3) & 1) * 4u) * 4u;

    float acc[4][8][4];
#pragma unroll
    for (int mt = 0; mt < 4; ++mt)
#pragma unroll
        for (int nt = 0; nt < 8; ++nt)
#pragma unroll
            for (int r = 0; r < 4; ++r) acc[mt][nt][r] = 0.f;

    const int nK = K >> 5;

    auto issue = [&](int kt) {
        const int k0 = kt << 5;
        const int s = kt & 3;
        const uint32_t sA = sbase + (s * G_ASTG) * 4;
        const uint32_t sB = sbase + (G_BOFF + s * G_ASTG) * 4;
#pragma unroll
        for (int it = 0; it < 4; ++it) {
            const int idx = tid + it * 128;   // 0..511
            const int row = idx >> 2;         // 0..127
            const int c   = idx & 3;          // 16B chunk
            const __half* ga;
            bool vA = true;
            if (MODE == 2) {
                const int tk = tok[row];
                vA = (tk >= 0);
                ga = A + (size_t)(vA ? tk : 0) * lda + k0 + c * 8;
            } else if (MODE == 3) {
                ga = A + (size_t)(seg0 + m0 + row) * lda + k0 + c * 8;
            } else {
                ga = A + (size_t)(m0 + row) * lda + k0 + c * 8;
            }
            cpa16(sA + (row * 20 + c * 4) * 4, ga, vA);
            const __half* gb = Bp + (size_t)(n0 + row) * ldb + k0 + c * 8;
            cpa16(sB + (row * 20 + c * 4) * 4, gb, true);
        }
    };
    auto compute = [&](int kt) {
        const int s = kt & 3;
        const uint32_t aab = sbase + (s * G_ASTG) * 4 + aoff0;
        const uint32_t bab = sbase + ((G_BOFF + s * G_ASTG)) * 4 + boff0;
#pragma unroll
        for (int ks = 0; ks < 2; ++ks) {
            const uint32_t kofs = (uint32_t)ks * 32u;
            uint32_t af[4][4];
#pragma unroll
            for (int mt = 0; mt < 4; ++mt)
                ldsm_x4(af[mt], aab + (uint32_t)mt * 1280u + kofs);
#pragma unroll
            for (int q = 0; q < 4; ++q) {
                uint32_t bf[4];
                ldsm_x4(bf, bab + (uint32_t)q * 1280u + kofs);
#pragma unroll
                for (int mt = 0; mt < 4; ++mt) {
                    mma_f16(acc[mt][2 * q],     af[mt], bf[0], bf[1]);
                    mma_f16(acc[mt][2 * q + 1], af[mt], bf[2], bf[3]);
                }
            }
        }
    };

    // ---- pipelined mainloop (4 stages, 3 in flight) ----
    issue(0); CP_COMMIT();
    issue(1); CP_COMMIT();
    issue(2); CP_COMMIT();
    for (int kt = 0; kt < nK; ++kt) {
        CP_WAIT2();
        __syncthreads();
        if (kt + 3 < nK) issue(kt + 3);
        CP_COMMIT();                       // always commit (keeps group-count invariant)
        compute(kt);
    }

    // ---- epilogue ----
    const int lr = ln >> 2;
    const int lc = ln & 3;
#pragma unroll
    for (int mt = 0; mt < 4; ++mt) {
#pragma unroll
        for (int half = 0; half < 2; ++half) {
            const int lrow = wm * 64 + mt * 16 + half * 8 + lr;
            bool valid = true;
            size_t rowidx = 0;
            if (MODE == 0 || MODE == 1) {
                rowidx = (size_t)(m0 + lrow);
            } else if (MODE == 2) {
                const int p = seg0 + m0 + lrow;
                valid = (p < seg1);
                rowidx = (size_t)p;
            } else {
                const int tk = tok[lrow];
                valid = (tk >= 0);
                rowidx = (size_t)(valid ? tk : 0);
            }
            if (!valid) continue;
#pragma unroll
            for (int nt = 0; nt < 8; ++nt) {
                const int cc = n0 + wn * 64 + nt * 8 + lc * 2;
                float vx = acc[mt][nt][half * 2 + 0] + biasp[cc];
                float vy = acc[mt][nt][half * 2 + 1] + biasp[cc + 1];
                if (MODE == 0) {
                    uint32_t* dst = (uint32_t*)Cv + rowidx * (ldc >> 1) + (cc >> 1);
                    *dst = f2h2(vx, vy);
                } else if (MODE == 2) {
                    vx = fmaxf(vx, 0.f); vy = fmaxf(vy, 0.f);
                    uint32_t* dst = (uint32_t*)Cv + rowidx * (ldc >> 1) + (cc >> 1);
                    *dst = f2h2(vx, vy);
                } else {
                    float2 v; v.x = vx; v.y = vy;
                    *reinterpret_cast<float2*>((float*)Cv + rowidx * ldc + cc) = v;
                }
            }
        }
    }
}

// ================= fp16 tensor-core flash attention =================
__global__ void __launch_bounds__(256, 2) flash_attn_f16(
    const __half* __restrict__ qkvh, __half* __restrict__ Oh)
{
    __shared__ uint32_t sQ[128 * 36];
    __shared__ uint32_t sK[64 * 36];
    __shared__ uint32_t sVt[32 * 72];

    const int tid = threadIdx.x;
    const int wid = tid >> 5;
    const int ln  = tid & 31;
    const int lr  = ln >> 2;
    const int lc  = ln & 3;
    const int b   = blockIdx.y >> 4;
    const int h   = blockIdx.y & 15;
    const int q0  = blockIdx.x * 128;
    const int wq  = wid * 16;
    const float qscale = 0.18033688011112042f;   // log2(e) / sqrt(64)

    const uint32_t* qkw = reinterpret_cast<const uint32_t*>(qkvh);   // 1536 words/row

#pragma unroll
    for (int it = 0; it < 4; ++it) {
        const int idx = tid + it * 256;
        const int row = idx >> 3;
        const int c   = idx & 7;
        const uint32_t* src = qkw + (size_t)(b * NS + q0 + row) * 1536 + h * 32 + c * 4;
        *reinterpret_cast<uint4*>(&sQ[row * 36 + c * 4]) = *reinterpret_cast<const uint4*>(src);
    }

    float mr0 = -1e30f, mr1 = -1e30f;
    float l0 = 0.f, l1 = 0.f;
    float o[8][4];
#pragma unroll
    for (int jd = 0; jd < 8; ++jd)
#pragma unroll
        for (int r = 0; r < 4; ++r) o[jd][r] = 0.f;

    for (int kb = 0; kb < 16; ++kb) {
#pragma unroll
        for (int it = 0; it < 2; ++it) {
            const int idx = tid + it * 256;
            const int row = idx >> 3;
            const int c   = idx & 7;
            const uint32_t* src = qkw + (size_t)(b * NS + kb * 64 + row) * 1536 + 512 + h * 32 + c * 4;
            *reinterpret_cast<uint4*>(&sK[row * 36 + c * 4]) = *reinterpret_cast<const uint4*>(src);
        }
        {
            const int k2 = tid >> 3;
            const int dc = tid & 7;
            const uint32_t* base = qkw + (size_t)(b * NS + kb * 64 + 2 * k2) * 1536 + 1024 + h * 32 + dc * 4;
            uint4 lo = *reinterpret_cast<const uint4*>(base);
            uint4 hi = *reinterpret_cast<const uint4*>(base + 1536);
            uint4 w0, w1;
            w0.x = __byte_perm(lo.x, hi.x, 0x5410); w0.y = __byte_perm(lo.x, hi.x, 0x7632);
            w0.z = __byte_perm(lo.y, hi.y, 0x5410); w0.w = __byte_perm(lo.y, hi.y, 0x7632);
            w1.x = __byte_perm(lo.z, hi.z, 0x5410); w1.y = __byte_perm(lo.z, hi.z, 0x7632);
            w1.z = __byte_perm(lo.w, hi.w, 0x5410); w1.w = __byte_perm(lo.w, hi.w, 0x7632);
            *reinterpret_cast<uint4*>(&sVt[k2 * 72 + dc * 8]) = w0;
            *reinterpret_cast<uint4*>(&sVt[k2 * 72 + dc * 8 + 4]) = w1;
        }
        __syncthreads();

        float s[8][4];
#pragma unroll
        for (int jn = 0; jn < 8; ++jn)
#pragma unroll
            for (int r = 0; r < 4; ++r) s[jn][r] = 0.f;
#pragma unroll
        for (int kk = 0; kk < 4; ++kk) {
            uint32_t a[4];
            a[0] = sQ[(wq + lr) * 36 + kk * 8 + lc];
            a[1] = sQ[(wq + lr + 8) * 36 + kk * 8 + lc];
            a[2] = sQ[(wq + lr) * 36 + kk * 8 + 4 + lc];
            a[3] = sQ[(wq + lr + 8) * 36 + kk * 8 + 4 + lc];
#pragma unroll
            for (int jn = 0; jn < 8; ++jn) {
                const uint32_t b0 = sK[(jn * 8 + lr) * 36 + kk * 8 + lc];
                const uint32_t b1 = sK[(jn * 8 + lr) * 36 + kk * 8 + 4 + lc];
                mma_f16(s[jn], a, b0, b1);
            }
        }
#pragma unroll
        for (int jn = 0; jn < 8; ++jn)
#pragma unroll
            for (int r = 0; r < 4; ++r) s[jn][r] *= qscale;

        float mx0 = s[0][0], mx1 = s[0][2];
#pragma unroll
        for (int jn = 0; jn < 8; ++jn) {
            mx0 = fmaxf(mx0, fmaxf(s[jn][0], s[jn][1]));
            mx1 = fmaxf(mx1, fmaxf(s[jn][2], s[jn][3]));
        }
        mx0 = fmaxf(mx0, __shfl_xor_sync(0xffffffffu, mx0, 1));
        mx0 = fmaxf(mx0, __shfl_xor_sync(0xffffffffu, mx0, 2));
        mx1 = fmaxf(mx1, __shfl_xor_sync(0xffffffffu, mx1, 1));
        mx1 = fmaxf(mx1, __shfl_xor_sync(0xffffffffu, mx1, 2));
        const float mn0 = fmaxf(mr0, mx0);
        const float mn1 = fmaxf(mr1, mx1);
        const float c0 = exp2p(mr0 - mn0);
        const float c1 = exp2p(mr1 - mn1);
        mr0 = mn0; mr1 = mn1;
        l0 *= c0; l1 *= c1;
#pragma unroll
        for (int jn = 0; jn < 8; ++jn) {
            s[jn][0] = exp2p(s[jn][0] - mr0);
            s[jn][1] = exp2p(s[jn][1] - mr0);
            s[jn][2] = exp2p(s[jn][2] - mr1);
            s[jn][3] = exp2p(s[jn][3] - mr1);
            l0 += s[jn][0] + s[jn][1];
            l1 += s[jn][2] + s[jn][3];
        }
#pragma unroll
        for (int jd = 0; jd < 8; ++jd) {
            o[jd][0] *= c0; o[jd][1] *= c0;
            o[jd][2] *= c1; o[jd][3] *= c1;
        }

#pragma unroll
        for (int q = 0; q < 4; ++q) {
            uint32_t a[4];
            a[0] = f2h2(s[2 * q][0], s[2 * q][1]);
            a[1] = f2h2(s[2 * q][2], s[2 * q][3]);
            a[2] = f2h2(s[2 * q + 1][0], s[2 * q + 1][1]);
            a[3] = f2h2(s[2 * q + 1][2], s[2 * q + 1][3]);
#pragma unroll
            for (int jd = 0; jd < 8; ++jd) {
                const uint32_t b0 = sVt[(q * 8 + lc) * 72 + jd * 8 + lr];
                const uint32_t b1 = sVt[(q * 8 + 4 + lc) * 72 + jd * 8 + lr];
                mma_f16(o[jd], a, b0, b1);
            }
        }
        __syncthreads();
    }

    l0 += __shfl_xor_sync(0xffffffffu, l0, 1);
    l0 += __shfl_xor_sync(0xffffffffu, l0, 2);
    l1 += __shfl_xor_sync(0xffffffffu, l1, 1);
    l1 += __shfl_xor_sync(0xffffffffu, l1, 2);
    const float i0 = 1.f / l0;
    const float i1 = 1.f / l1;
    uint32_t* ow = reinterpret_cast<uint32_t*>(Oh);   // 512 words/row
    const size_t r0 = (size_t)(b * NS + q0 + wq + lr);
    const size_t r1 = r0 + 8;
#pragma unroll
    for (int jd = 0; jd < 8; ++jd) {
        ow[r0 * 512 + h * 32 + jd * 4 + lc] = f2h2(o[jd][0] * i0, o[jd][1] * i0);
        ow[r1 * 512 + h * 32 + jd * 4 + lc] = f2h2(o[jd][2] * i1, o[jd][3] * i1);
    }
}

// ---------------- residual add + LayerNorm (+ optional fused router gate) ----------
template<bool GATE>
__global__ __launch_bounds__(256) void add_ln_g(
    const float* __restrict__ A, const float* __restrict__ R,
    const float* __restrict__ g, const float* __restrict__ bt,
    float* __restrict__ out, __half* __restrict__ out16,
    const float* __restrict__ gw, const float* __restrict__ gb)
{
    const int t = blockIdx.x;
    const int tid = threadIdx.x;
    __shared__ float red[8];
    __shared__ float gl[8][8];

    const float4 a4 = *reinterpret_cast<const float4*>(A + (size_t)t * ND + tid * 4);
    const float4 r4 = *reinterpret_cast<const float4*>(R + (size_t)t * ND + tid * 4);
    float v[4] = {a4.x + r4.x, a4.y + r4.y, a4.z + r4.z, a4.w + r4.w};

    float sum = v[0] + v[1] + v[2] + v[3];
#pragma unroll
    for (int off = 16; off; off >>= 1) sum += __shfl_down_sync(0xffffffffu, sum, off);
    if ((tid & 31) == 0) red[tid >> 5] = sum;
    __syncthreads();
    if (tid < 8) {
        float s = red[tid];
#pragma unroll
        for (int off = 4; off; off >>= 1) s += __shfl_down_sync(0xffu, s, off);
        if (tid == 0) red[0] = s;
    }
    __syncthreads();
    const float mu = red[0] * (1.f / ND);
    __syncthreads();

    float vs = 0.f;
#pragma unroll
    for (int i = 0; i < 4; ++i) { float d = v[i] - mu; vs += d * d; }
#pragma unroll
    for (int off = 16; off; off >>= 1) vs += __shfl_down_sync(0xffffffffu, vs, off);
    if ((tid & 31) == 0) red[tid >> 5] = vs;
    __syncthreads();
    if (tid < 8) {
        float s = red[tid];
#pragma unroll
        for (int off = 4; off; off >>= 1) s += __shfl_down_sync(0xffu, s, off);
        if (tid == 0) red[0] = s;
    }
    __syncthreads();
    const float rstd = rsqrtf(red[0] * (1.f / ND) + EPS);

    float4 o4;
    const int d0 = tid * 4;
    o4.x = (v[0] - mu) * rstd * g[d0]     + bt[d0];
    o4.y = (v[1] - mu) * rstd * g[d0 + 1] + bt[d0 + 1];
    o4.z = (v[2] - mu) * rstd * g[d0 + 2] + bt[d0 + 2];
    o4.w = (v[3] - mu) * rstd * g[d0 + 3] + bt[d0 + 3];
    *reinterpret_cast<float4*>(out + (size_t)t * ND + d0) = o4;
    if (out16) {
        uint2 u;
        u.x = f2h2(o4.x, o4.y);
        u.y = f2h2(o4.z, o4.w);
        *reinterpret_cast<uint2*>(out16 + (size_t)t * ND + d0) = u;
    }

    if (GATE) {
        float ga[NE];
#pragma unroll
        for (int e = 0; e < NE; ++e) {
            const float4 w4 = *reinterpret_cast<const float4*>(gw + (size_t)e * ND + d0);
            ga[e] = o4.x * w4.x + o4.y * w4.y + o4.z * w4.z + o4.w * w4.w;
        }
#pragma unroll
        for (int e = 0; e < NE; ++e)
#pragma unroll
            for (int off = 16; off; off >>= 1)
                ga[e] += __shfl_down_sync(0xffffffffu, ga[e], off);
        if ((tid & 31) == 0) {
#pragma unroll
            for (int e = 0; e < NE; ++e) gl[tid >> 5][e] = ga[e];
        }
        __syncthreads();
        if (tid < NE) {
            float s = gb[tid];
#pragma unroll
            for (int w = 0; w < 8; ++w) s += gl[w][tid];
            gl[0][tid] = s;
        }
        __syncthreads();
        if (tid == 0) {
            int best = 0; float bv = gl[0][0];
#pragma unroll
            for (int e = 1; e < NE; ++e) {
                const float vv = gl[0][e];
                if (vv > bv) { bv = vv; best = e; }
            }
            g_idx[t] = best;
            atomicAdd(&g_cnt[best], 1);
        }
    }
}

// ---------------- routing ----------------
__global__ void route_init() {
    if (threadIdx.x < NE) g_cnt[threadIdx.x] = 0;
}

__global__ void route_scan() {
    g_off[0] = 0;
    for (int e = 0; e < NE; ++e) {
        g_off[e + 1] = g_off[e] + g_cnt[e];
        g_pos[e] = g_off[e];
    }
}

__global__ __launch_bounds__(256) void route_scatter() {
    const int t = blockIdx.x * 256 + threadIdx.x;
    if (t < NT) {
        const int e = g_idx[t];
        const int p = atomicAdd(&g_pos[e], 1);
        g_order[p] = t;
    }
}

// ---------------- launcher ----------------
extern "C" void kernel_launch(void* const* d_in, const int* in_sizes, int n_in,
                              void* d_out, int out_size)
{
    const float* x         = (const float*)d_in[0];
    const float* in_proj_w = (const float*)d_in[1];
    const float* in_proj_b = (const float*)d_in[2];
    const float* out_w     = (const float*)d_in[3];
    const float* out_b     = (const float*)d_in[4];
    const float* gate_w    = (const float*)d_in[5];
    const float* gate_b    = (const float*)d_in[6];
    const float* W1        = (const float*)d_in[7];
    const float* b1        = (const float*)d_in[8];
    const float* W2        = (const float*)d_in[9];
    const float* b2        = (const float*)d_in[10];
    const float* ln1_g     = (const float*)d_in[11];
    const float* ln1_b     = (const float*)d_in[12];
    const float* ln2_g     = (const float*)d_in[13];
    const float* ln2_b     = (const float*)d_in[14];
    float* out = (float*)d_out;

    __half *x16, *inwh, *outwh, *w1t, *w2t, *qkvh, *attnoh, *x1h, *hbuf;
    float  *tmp, *x1;
    cudaGetSymbolAddress((void**)&x16,    g_x16);
    cudaGetSymbolAddress((void**)&inwh,   g_inwh);
    cudaGetSymbolAddress((void**)&outwh,  g_outwh);
    cudaGetSymbolAddress((void**)&w1t,    g_w1t);
    cudaGetSymbolAddress((void**)&w2t,    g_w2t);
    cudaGetSymbolAddress((void**)&qkvh,   g_qkvh);
    cudaGetSymbolAddress((void**)&attnoh, g_attnoh);
    cudaGetSymbolAddress((void**)&x1h,    g_x1h);
    cudaGetSymbolAddress((void**)&hbuf,   g_h);
    cudaGetSymbolAddress((void**)&tmp,    g_tmp);
    cudaGetSymbolAddress((void**)&x1,     g_x1);

    cudaFuncSetAttribute(gemm_f16<0>, cudaFuncAttributeMaxDynamicSharedMemorySize, GEMM_SMEM_BYTES);
    cudaFuncSetAttribute(gemm_f16<1>, cudaFuncAttributeMaxDynamicSharedMemorySize, GEMM_SMEM_BYTES);
    cudaFuncSetAttribute(gemm_f16<2>, cudaFuncAttributeMaxDynamicSharedMemorySize, GEMM_SMEM_BYTES);
    cudaFuncSetAttribute(gemm_f16<3>, cudaFuncAttributeMaxDynamicSharedMemorySize, GEMM_SMEM_BYTES);

    // ---- side stream for the independent W1/W2 transposes (overlap with QKV/attn) ----
    cudaStream_t s2 = 0;
    cudaEvent_t evFork = 0, evJoin = 0;
    bool use2 =
        (cudaStreamCreateWithFlags(&s2, cudaStreamNonBlocking) == cudaSuccess) &&
        (cudaEventCreateWithFlags(&evFork, cudaEventDisableTiming) == cudaSuccess) &&
        (cudaEventCreateWithFlags(&evJoin, cudaEventDisableTiming) == cudaSuccess);

    route_init<<<1, 32>>>();   // zero expert counters (needed by fused gate in LN1)

    if (use2) {
        cudaEventRecord(evFork, 0);
        cudaStreamWaitEvent(s2, evFork, 0);
        transpose_cvt<<<dim3(NF / 32, ND / 64, NE), 256, 0, s2>>>(W1, w1t, ND, NF);
        transpose_cvt<<<dim3(ND / 32, NF / 64, NE), 256, 0, s2>>>(W2, w2t, NF, ND);
        cudaEventRecord(evJoin, s2);
    } else {
        transpose_cvt<<<dim3(NF / 32, ND / 64, NE), 256>>>(W1, w1t, ND, NF);
        transpose_cvt<<<dim3(ND / 32, NF / 64, NE), 256>>>(W2, w2t, NF, ND);
    }

    // 0) conversions on the main stream
    cvt_f32_f16<<<NT * ND / 1024, 256>>>(x, x16, NT * ND / 4);
    cvt_f32_f16<<<3 * ND * ND / 1024, 256>>>(in_proj_w, inwh, 3 * ND * ND / 4);
    cvt_f32_f16<<<ND * ND / 1024, 256>>>(out_w, outwh, ND * ND / 4);

    // 1) QKV projection (fp16 out)
    gemm_f16<0><<<dim3(NT / 128, 3 * ND / 128, 1), 128, GEMM_SMEM_BYTES>>>(
        x16, ND, inwh, ND, in_proj_b, qkvh, 3 * ND, ND, 3 * ND);
    // 2) attention (fp16)
    flash_attn_f16<<<dim3(NS / 128, NB * NH), 256>>>(qkvh, attnoh);
    // 3) output projection (fp32 out)
    gemm_f16<1><<<dim3(NT / 128, ND / 128, 1), 128, GEMM_SMEM_BYTES>>>(
        attnoh, ND, outwh, ND, out_b, tmp, ND, ND, ND);
    // 4) residual + LN1 + fused router gate
    add_ln_g<true><<<NT, 256>>>(tmp, x, ln1_g, ln1_b, x1, x1h, gate_w, gate_b);
    // 5) routing finalize
    route_scan<<<1, 1>>>();
    route_scatter<<<NT / 256, 256>>>();
    // join the transpose branch before the MoE GEMMs consume w1t/w2t
    if (use2) cudaStreamWaitEvent(0, evJoin, 0);
    // 6) MoE expert FFN
    gemm_f16<2><<<dim3(NT / 128, NF / 128, NE), 128, GEMM_SMEM_BYTES>>>(
        x1h, ND, w1t, ND, b1, hbuf, NF, ND, NF);
    gemm_f16<3><<<dim3(NT / 128, ND / 128, NE), 128, GEMM_SMEM_BYTES>>>(
        hbuf, NF, w2t, NF, b2, tmp, ND, NF, ND);
    // 7) residual + LN2 -> output
    add_ln_g<false><<<NT, 256>>>(tmp, x1, ln2_g, ln2_b, out, nullptr, nullptr, nullptr);

    (void)in_sizes; (void)n_in; (void)out_size;
}